// round 7
// baseline (speedup 1.0000x reference)
#include <cuda_runtime.h>
#include <cuda_fp16.h>
#include <cstdint>

#define D_MODEL 1024
#define NHEAD   16
#define DHEAD   64
#define BSZ     256
#define NTOK    16384
#define NBLK    64
#define NELEM   ((size_t)NTOK * D_MODEL)
#define WSTRIDE (1024 * 1024)
#define PART_STRIDE (128 * 1024)

// ---------------- fp32 scratch (small path) ----------------
__device__ __align__(16) float g_Q2  [NBLK * D_MODEL];
__device__ __align__(16) float g_K2  [NBLK * D_MODEL];
__device__ __align__(16) float g_V2  [NBLK * D_MODEL];
__device__ __align__(16) float g_SOUT[NBLK * D_MODEL];
__device__ __align__(16) float g_PART[12 * PART_STRIDE];   // split-K partials

// ---------------- fp16 split scratch ----------------
__device__ __align__(16) __half g_XH[NELEM];
__device__ __align__(16) __half g_XL[NELEM];
__device__ __align__(16) __half g_QH[NELEM];
__device__ __align__(16) __half g_QL[NELEM];
__device__ __align__(16) __half g_KH[NELEM];
__device__ __align__(16) __half g_KL[NELEM];
__device__ __align__(16) __half g_VH[NELEM];
__device__ __align__(16) __half g_VL[NELEM];
__device__ __align__(16) __half g_VTH[NELEM];   // [blk][dim][tok]
__device__ __align__(16) __half g_VTL[NELEM];
__device__ __align__(16) __half g_CH[NELEM];
__device__ __align__(16) __half g_CL[NELEM];
__device__ __align__(16) __half g_WH[9][WSTRIDE];  // transposed [N][K] hi
__device__ __align__(16) __half g_WL[9][WSTRIDE];  // transposed [N][K] lo
// per-stage small activations (distinct buffers -> replay-deterministic)
__device__ __align__(16) __half g_S1H[128 * 1024];  // meanpool out
__device__ __align__(16) __half g_S1L[128 * 1024];
__device__ __align__(16) __half g_S2H[128 * 1024];  // summarizer out
__device__ __align__(16) __half g_S2L[128 * 1024];
__device__ __align__(16) __half g_S3H[128 * 1024];  // summ attention ctx
__device__ __align__(16) __half g_S3L[128 * 1024];

// =================== helpers ===================
__device__ __forceinline__ uint32_t smem_u32(const void* p) {
    uint32_t a;
    asm("{ .reg .u64 t; cvta.to.shared.u64 t, %1; cvt.u32.u64 %0, t; }" : "=r"(a) : "l"(p));
    return a;
}
#define SWZ128(off) ((off) ^ (((off) >> 3) & 0x70))
#define SWZ512(off) ((off) ^ (((off) >> 5) & 0x70))

__device__ __forceinline__ void cp16(uint32_t dst, const void* src) {
    asm volatile("cp.async.cg.shared.global [%0], [%1], 16;" :: "r"(dst), "l"(src));
}
__device__ __forceinline__ void cp_commit() {
    asm volatile("cp.async.commit_group;" ::: "memory");
}
__device__ __forceinline__ void ldsm_x4(uint32_t addr, uint32_t r[4]) {
    asm volatile("ldmatrix.sync.aligned.m8n8.x4.shared.b16 {%0,%1,%2,%3}, [%4];"
        : "=r"(r[0]), "=r"(r[1]), "=r"(r[2]), "=r"(r[3]) : "r"(addr));
}
__device__ __forceinline__ void mma_f16(float c[4], const uint32_t a[4],
                                        uint32_t b0, uint32_t b1) {
    asm volatile(
        "mma.sync.aligned.m16n8k16.row.col.f32.f16.f16.f32 "
        "{%0,%1,%2,%3}, {%4,%5,%6,%7}, {%8,%9}, {%0,%1,%2,%3};"
        : "+f"(c[0]), "+f"(c[1]), "+f"(c[2]), "+f"(c[3])
        : "r"(a[0]), "r"(a[1]), "r"(a[2]), "r"(a[3]), "r"(b0), "r"(b1));
}
__device__ __forceinline__ uint32_t pack_f16x2(float lo, float hi) {
    uint32_t r;
    asm("cvt.rn.f16x2.f32 %0, %1, %2;" : "=r"(r) : "f"(hi), "f"(lo));
    return r;
}

// =================== prep kernels ===================
__global__ void prep_act_kernel(const float4* __restrict__ A,
                                __half* __restrict__ H,
                                __half* __restrict__ L,
                                int nquads)
{
    const int i = blockIdx.x * blockDim.x + threadIdx.x;
    if (i >= nquads) return;
    const float4 v = A[i];
    const __half h0 = __float2half_rn(v.x);
    const __half h1 = __float2half_rn(v.y);
    const __half h2 = __float2half_rn(v.z);
    const __half h3 = __float2half_rn(v.w);
    *(__half2*)(H + (size_t)i * 4)     = __halves2half2(h0, h1);
    *(__half2*)(H + (size_t)i * 4 + 2) = __halves2half2(h2, h3);
    *(__half2*)(L + (size_t)i * 4)     = __halves2half2(
        __float2half_rn(v.x - __half2float(h0)), __float2half_rn(v.y - __half2float(h1)));
    *(__half2*)(L + (size_t)i * 4 + 2) = __halves2half2(
        __float2half_rn(v.z - __half2float(h2)), __float2half_rn(v.w - __half2float(h3)));
}

struct WP9 {
    const float* w[9];
    __half* h[9];
    __half* l[9];
};
__global__ void prep_w_kernel(WP9 wp)
{
    __shared__ float t[32][33];
    const int z  = blockIdx.z;
    const float* W = wp.w[z];
    __half* H = wp.h[z];
    __half* L = wp.l[z];
    const int bx = blockIdx.x;
    const int by = blockIdx.y;
    const int tx = threadIdx.x;
    const int ty = threadIdx.y;
    #pragma unroll
    for (int r = 0; r < 32; r += 8)
        t[ty + r][tx] = W[(size_t)(by * 32 + ty + r) * 1024 + bx * 32 + tx];
    __syncthreads();
    #pragma unroll
    for (int r = 0; r < 32; r += 8) {
        const float v = t[tx][ty + r];
        const __half h = __float2half_rn(v);
        const size_t o = (size_t)(bx * 32 + ty + r) * 1024 + by * 32 + tx;
        H[o] = h;
        if (z >= 4) L[o] = __float2half_rn(v - __half2float(h));  // lo only used by 3-term path
    }
}

// =================== fragment index helpers ===================
#define FRAG_IDX()                                                            \
    const int arow_in = (lane & 7) + ((lane >> 3) & 1) * 8;                   \
    const int acolx   = (lane >> 4) * 16;                                     \
    const int brow_in = (lane & 7) + ((lane >> 4) & 1) * 8;                   \
    const int bcolx   = ((lane >> 3) & 1) * 16;

#define BUF3_BYTES 65536
#define GEMM3_SMEM (2 * BUF3_BYTES)

#define ISSUE3(ic, buf) do {                                                  \
    const uint32_t sbase = sb + (buf) * BUF3_BYTES;                           \
    const size_t coff = (size_t)(ic) * 128 + cb;                              \
    _Pragma("unroll")                                                         \
    for (int i = 0; i < 4; i++) {                                             \
        const size_t go = (size_t)(rcp + i * 32) * 2048 + coff;               \
        cp16(sbase + dsw[i],          gAh + go);                              \
        cp16(sbase + 16384 + dsw[i],  gAl + go);                              \
        cp16(sbase + 32768 + dsw[i],  gBh + go);                              \
        cp16(sbase + 49152 + dsw[i],  gBl + go);                              \
    }                                                                         \
    cp_commit();                                                              \
} while (0)

// =================== split-K 3-term small GEMM -> fp32 partials ===================
// grid (8, nz, 4): bn, zi (weight = zbase+zi), ks (K-split slot). M fixed 128.
__global__ __launch_bounds__(256, 1) void gemm_smallk_kernel(
    const __half* __restrict__ Ah, const __half* __restrict__ Al,
    const __half* __restrict__ WHb, const __half* __restrict__ WLb,
    int zbase, float* __restrict__ P)
{
    extern __shared__ char smem[];
    const uint32_t sb = smem_u32(smem);
    const int tid  = threadIdx.x;
    const int lane = tid & 31;
    const int wid  = tid >> 5;
    const int wm   = wid & 3;
    const int wn   = wid >> 2;
    const int bn = blockIdx.x;
    const int zi = blockIdx.y;
    const int ks = blockIdx.z;
    const int rcp = tid >> 3;
    const int cb  = (tid & 7) << 4;
    uint32_t dsw[4];
    #pragma unroll
    for (int i = 0; i < 4; i++) dsw[i] = SWZ128((uint32_t)((rcp + i * 32) * 128 + cb));
    FRAG_IDX();

    const char* gAh = (const char*)Ah;
    const char* gAl = (const char*)Al;
    const char* gBh = (const char*)(WHb + (size_t)(zbase + zi) * WSTRIDE + (size_t)bn * 128 * 1024);
    const char* gBl = (const char*)(WLb + (size_t)(zbase + zi) * WSTRIDE + (size_t)bn * 128 * 1024);

    float c[2][8][4];
    #pragma unroll
    for (int mt = 0; mt < 2; mt++)
        #pragma unroll
        for (int nb = 0; nb < 8; nb++)
            #pragma unroll
            for (int j = 0; j < 4; j++) c[mt][nb][j] = 0.f;

    const int ic0 = ks * 4;
    ISSUE3(ic0, 0);
    #pragma unroll 1
    for (int it = 0; it < 4; it++) {
        const int cur = it & 1;
        if (it < 3) ISSUE3(ic0 + it + 1, cur ^ 1);
        if (it < 3) asm volatile("cp.async.wait_group 1;" ::: "memory");
        else        asm volatile("cp.async.wait_group 0;" ::: "memory");
        __syncthreads();
        const uint32_t base = sb + cur * BUF3_BYTES;
        #pragma unroll
        for (int kk = 0; kk < 4; kk++) {
            const uint32_t kb = kk * 32;
            uint32_t ah[2][4], al_[2][4];
            #pragma unroll
            for (int mt = 0; mt < 2; mt++) {
                const uint32_t off =
                    SWZ128((uint32_t)((wm * 32 + mt * 16 + arow_in) * 128 + kb + acolx));
                ldsm_x4(base + off,          ah[mt]);
                ldsm_x4(base + 16384 + off,  al_[mt]);
            }
            uint32_t bh[4][4], bl[4][4];
            #pragma unroll
            for (int p = 0; p < 4; p++) {
                const uint32_t off =
                    SWZ128((uint32_t)((wn * 64 + p * 16 + brow_in) * 128 + kb + bcolx));
                ldsm_x4(base + 32768 + off, bh[p]);
                ldsm_x4(base + 49152 + off, bl[p]);
            }
            #pragma unroll
            for (int mt = 0; mt < 2; mt++) {
                #pragma unroll
                for (int p = 0; p < 4; p++) {
                    mma_f16(c[mt][2 * p],     ah[mt],  bh[p][0], bh[p][1]);
                    mma_f16(c[mt][2 * p],     ah[mt],  bl[p][0], bl[p][1]);
                    mma_f16(c[mt][2 * p],     al_[mt], bh[p][0], bh[p][1]);
                    mma_f16(c[mt][2 * p + 1], ah[mt],  bh[p][2], bh[p][3]);
                    mma_f16(c[mt][2 * p + 1], ah[mt],  bl[p][2], bl[p][3]);
                    mma_f16(c[mt][2 * p + 1], al_[mt], bh[p][2], bh[p][3]);
                }
            }
        }
        __syncthreads();
    }

    float* Pp = P + (size_t)(zi * 4 + ks) * PART_STRIDE;
    const int row_base = wm * 32 + (lane >> 2);
    const int col_base = bn * 128 + wn * 64 + 2 * (lane & 3);
    #pragma unroll
    for (int mt = 0; mt < 2; mt++) {
        #pragma unroll
        for (int hh = 0; hh < 2; hh++) {
            const int row = row_base + mt * 16 + hh * 8;
            #pragma unroll
            for (int nb = 0; nb < 8; nb++) {
                const int col = col_base + nb * 8;
                float2 o;
                o.x = c[mt][nb][hh * 2 + 0];
                o.y = c[mt][nb][hh * 2 + 1];
                *(float2*)(Pp + (size_t)row * 1024 + col) = o;
            }
        }
    }
}

// ---- reduce 4 partials + bias -> fp32 (grid 256: rows 0..63 only) ----
__global__ void reduce_fp32_kernel(const float* __restrict__ P,
                                   const float* __restrict__ bias,
                                   float* __restrict__ C)
{
    const int idx = blockIdx.x * 256 + threadIdx.x;
    const float s = P[idx] + P[idx + PART_STRIDE] + P[idx + 2 * PART_STRIDE] + P[idx + 3 * PART_STRIDE];
    C[idx] = s + bias[idx & 1023];
}

// ---- reduce 4 partials + bias -> split fp16 (grid 512: all 128 rows) ----
__global__ void reduce_hl_kernel(const float* __restrict__ P,
                                 const float* __restrict__ bias,
                                 __half* __restrict__ H, __half* __restrict__ L)
{
    const int idx = blockIdx.x * 256 + threadIdx.x;
    const float v = P[idx] + P[idx + PART_STRIDE] + P[idx + 2 * PART_STRIDE] + P[idx + 3 * PART_STRIDE]
                  + bias[idx & 1023];
    const __half h = __float2half_rn(v);
    H[idx] = h;
    L[idx] = __float2half_rn(v - __half2float(h));
}

// =================== 2-term GEMM mainloop (big path): C ~= (Ah+Al) * Bh ===================
#define BUF2_BYTES 49152
#define GEMM2_SMEM (2 * BUF2_BYTES)

#define GEMM2_BODY()                                                          \
    extern __shared__ char smem[];                                            \
    const uint32_t sb = smem_u32(smem);                                       \
    const int tid  = threadIdx.x;                                             \
    const int lane = tid & 31;                                                \
    const int wid  = tid >> 5;                                                \
    const int wm   = wid & 3;                                                 \
    const int wn   = wid >> 2;                                                \
    const int bn = blockIdx.x;                                                \
    const int bm = blockIdx.y;                                                \
    const int rcp = tid >> 3;                                                 \
    const int cb  = (tid & 7) << 4;                                           \
    uint32_t dsw[4];                                                          \
    _Pragma("unroll")                                                         \
    for (int i = 0; i < 4; i++) dsw[i] = SWZ128((uint32_t)((rcp + i * 32) * 128 + cb)); \
    FRAG_IDX();                                                               \
    float c[2][8][4];                                                         \
    _Pragma("unroll")                                                         \
    for (int mt = 0; mt < 2; mt++)                                            \
        _Pragma("unroll")                                                     \
        for (int nb = 0; nb < 8; nb++)                                        \
            _Pragma("unroll")                                                 \
            for (int j = 0; j < 4; j++) c[mt][nb][j] = 0.f;                   \
    ISSUE2(0, 0);                                                             \
    _Pragma("unroll 1")                                                       \
    for (int ic = 0; ic < 16; ic++) {                                         \
        const int cur = ic & 1;                                               \
        if (ic < 15) ISSUE2(ic + 1, cur ^ 1);                                 \
        if (ic < 15) asm volatile("cp.async.wait_group 1;" ::: "memory");     \
        else         asm volatile("cp.async.wait_group 0;" ::: "memory");     \
        __syncthreads();                                                      \
        const uint32_t base = sb + cur * BUF2_BYTES;                          \
        _Pragma("unroll")                                                     \
        for (int kk = 0; kk < 4; kk++) {                                      \
            const uint32_t kb = kk * 32;                                      \
            uint32_t ah[2][4], al_[2][4];                                     \
            _Pragma("unroll")                                                 \
            for (int mt = 0; mt < 2; mt++) {                                  \
                const uint32_t off =                                          \
                    SWZ128((uint32_t)((wm * 32 + mt * 16 + arow_in) * 128 + kb + acolx)); \
                ldsm_x4(base + off,          ah[mt]);                         \
                ldsm_x4(base + 16384 + off,  al_[mt]);                        \
            }                                                                 \
            uint32_t bh[4][4];                                                \
            _Pragma("unroll")                                                 \
            for (int p = 0; p < 4; p++) {                                     \
                const uint32_t off =                                          \
                    SWZ128((uint32_t)((wn * 64 + p * 16 + brow_in) * 128 + kb + bcolx)); \
                ldsm_x4(base + 32768 + off, bh[p]);                           \
            }                                                                 \
            _Pragma("unroll")                                                 \
            for (int mt = 0; mt < 2; mt++) {                                  \
                _Pragma("unroll")                                             \
                for (int p = 0; p < 4; p++) {                                 \
                    mma_f16(c[mt][2 * p],     ah[mt],  bh[p][0], bh[p][1]);   \
                    mma_f16(c[mt][2 * p],     al_[mt], bh[p][0], bh[p][1]);   \
                    mma_f16(c[mt][2 * p + 1], ah[mt],  bh[p][2], bh[p][3]);   \
                    mma_f16(c[mt][2 * p + 1], al_[mt], bh[p][2], bh[p][3]);   \
                }                                                             \
            }                                                                 \
        }                                                                     \
        __syncthreads();                                                      \
    }

#define ISSUE2(ic, buf) do {                                                  \
    const uint32_t sbase = sb + (buf) * BUF2_BYTES;                           \
    const size_t coff = (size_t)(ic) * 128 + cb;                              \
    _Pragma("unroll")                                                         \
    for (int i = 0; i < 4; i++) {                                             \
        const size_t go = (size_t)(rcp + i * 32) * 2048 + coff;               \
        cp16(sbase + dsw[i],          gAh + go);                              \
        cp16(sbase + 16384 + dsw[i],  gAl + go);                              \
        cp16(sbase + 32768 + dsw[i],  gBh + go);                              \
    }                                                                         \
    cp_commit();                                                              \
} while (0)

// ---- o-proj: fp32 out, bias + summary add ----
__global__ __launch_bounds__(256, 2) void gemm2_kernel(
    const __half* __restrict__ Ah, const __half* __restrict__ Al,
    const __half* __restrict__ Bh,
    const float* __restrict__ bias, const float* __restrict__ addBlk,
    float* __restrict__ C)
{
    const char* gAh = (const char*)(Ah + (size_t)(blockIdx.y * 128) * 1024);
    const char* gAl = (const char*)(Al + (size_t)(blockIdx.y * 128) * 1024);
    const char* gBh = (const char*)(Bh + (size_t)(blockIdx.x * 128) * 1024);
    GEMM2_BODY();

    const int row_base = bm * 128 + wm * 32 + (lane >> 2);
    const int col_base = bn * 128 + wn * 64 + 2 * (lane & 3);
    #pragma unroll
    for (int mt = 0; mt < 2; mt++) {
        #pragma unroll
        for (int hh = 0; hh < 2; hh++) {
            const int row = row_base + mt * 16 + hh * 8;
            const int rb = row >> 8;
            #pragma unroll
            for (int nb = 0; nb < 8; nb++) {
                const int col = col_base + nb * 8;
                float2 o;
                o.x = c[mt][nb][hh * 2 + 0] + bias[col + 0] + addBlk[(size_t)rb * 1024 + col + 0];
                o.y = c[mt][nb][hh * 2 + 1] + bias[col + 1] + addBlk[(size_t)rb * 1024 + col + 1];
                *(float2*)(C + (size_t)row * 1024 + col) = o;
            }
        }
    }
}

// ---- fused QKV: split-fp16 out ----
__global__ __launch_bounds__(256, 2) void gemm2_qkv_kernel(
    const __half* __restrict__ Ah, const __half* __restrict__ Al,
    const __half* __restrict__ Bh,
    const float* __restrict__ bq, const float* __restrict__ bk, const float* __restrict__ bv,
    __half* __restrict__ QH, __half* __restrict__ QL,
    __half* __restrict__ KH, __half* __restrict__ KL,
    __half* __restrict__ VH, __half* __restrict__ VL)
{
    const char* gAh = (const char*)(Ah + (size_t)(blockIdx.y * 128) * 1024);
    const char* gAl = (const char*)(Al + (size_t)(blockIdx.y * 128) * 1024);
    const char* gBh = (const char*)(Bh + (size_t)(blockIdx.x * 128) * 1024);
    GEMM2_BODY();

    const int tensor = bn >> 3;
    const float* bias = (tensor == 0) ? bq : (tensor == 1) ? bk : bv;
    __half* OH = (tensor == 0) ? QH : (tensor == 1) ? KH : VH;
    __half* OL = (tensor == 0) ? QL : (tensor == 1) ? KL : VL;

    const int row_base = bm * 128 + wm * 32 + (lane >> 2);
    const int col_base = (bn & 7) * 128 + wn * 64 + 2 * (lane & 3);
    #pragma unroll
    for (int mt = 0; mt < 2; mt++) {
        #pragma unroll
        for (int hh = 0; hh < 2; hh++) {
            const int row = row_base + mt * 16 + hh * 8;
            #pragma unroll
            for (int nb = 0; nb < 8; nb++) {
                const int col = col_base + nb * 8;
                const float v0 = c[mt][nb][hh * 2 + 0] + bias[col + 0];
                const float v1 = c[mt][nb][hh * 2 + 1] + bias[col + 1];
                const __half h0 = __float2half_rn(v0);
                const __half h1 = __float2half_rn(v1);
                *(__half2*)(OH + (size_t)row * 1024 + col) = __halves2half2(h0, h1);
                *(__half2*)(OL + (size_t)row * 1024 + col) = __halves2half2(
                    __float2half_rn(v0 - __half2float(h0)),
                    __float2half_rn(v1 - __half2float(h1)));
            }
        }
    }
}

// =================== V transpose: [tok][dim] -> [blk][dim][tok] ===================
__global__ __launch_bounds__(256) void vtrans_kernel(
    const __half* __restrict__ VH, const __half* __restrict__ VL,
    __half* __restrict__ VTH, __half* __restrict__ VTL)
{
    __shared__ __half t[256][72];
    const int blk = blockIdx.x;
    const int dt  = blockIdx.y;
    const int tid = threadIdx.x;
    #pragma unroll 1
    for (int pass = 0; pass < 2; pass++) {
        const __half* src = pass ? VL : VH;
        __half* dst = pass ? VTL : VTH;
        #pragma unroll
        for (int it = 0; it < 8; it++) {
            const int task = it * 256 + tid;
            const int row = task >> 3;
            const int dc  = (task & 7) * 8;
            *(uint4*)&t[row][dc] =
                *(const uint4*)(src + ((size_t)(blk * 256 + row)) * 1024 + dt * 64 + dc);
        }
        __syncthreads();
        #pragma unroll
        for (int it = 0; it < 8; it++) {
            const int task = it * 256 + tid;
            const int d  = task >> 5;
            const int tc = (task & 31) * 8;
            __half tmp[8];
            #pragma unroll
            for (int j = 0; j < 8; j++) tmp[j] = t[tc + j][d];
            *(uint4*)(dst + ((size_t)(blk * 1024) + dt * 64 + d) * 256 + tc) = *(uint4*)tmp;
        }
        __syncthreads();
    }
}

// =================== HMMA local attention (3-term fp16) ===================
#define ATT_SMEM (6 * 32768)

__global__ __launch_bounds__(512, 1) void attn_mma_kernel(
    const __half* __restrict__ QH, const __half* __restrict__ QL,
    const __half* __restrict__ KH, const __half* __restrict__ KL,
    const __half* __restrict__ VTH, const __half* __restrict__ VTL,
    const float* __restrict__ bias,
    __half* __restrict__ CH, __half* __restrict__ CL)
{
    extern __shared__ char smem[];
    const uint32_t sb = smem_u32(smem);
    const int blk = blockIdx.x;
    const int h   = blockIdx.y;
    const int tid = threadIdx.x;
    const int lane = tid & 31;
    const int w    = tid >> 5;

    const uint32_t QHs = sb;
    const uint32_t QLs = sb + 32768;
    const uint32_t KHs = sb + 65536;
    const uint32_t KLs = sb + 98304;
    const uint32_t VHs = sb + 131072;
    const uint32_t VLs = sb + 163840;

    {
        const char* qh0 = (const char*)(QH + ((size_t)blk * 256) * 1024 + h * 64);
        const char* ql0 = (const char*)(QL + ((size_t)blk * 256) * 1024 + h * 64);
        const char* kh0 = (const char*)(KH + ((size_t)blk * 256) * 1024 + h * 64);
        const char* kl0 = (const char*)(KL + ((size_t)blk * 256) * 1024 + h * 64);
        #pragma unroll
        for (int i = 0; i < 4; i++) {
            const int cidx = tid + i * 512;
            const int row = cidx >> 3;
            const int cbo = (cidx & 7) << 4;
            const uint32_t d = SWZ128((uint32_t)(row * 128 + cbo));
            const size_t go = (size_t)row * 2048 + cbo;
            cp16(QHs + d, qh0 + go);
            cp16(QLs + d, ql0 + go);
            cp16(KHs + d, kh0 + go);
            cp16(KLs + d, kl0 + go);
        }
        const char* vh0 = (const char*)(VTH + ((size_t)blk * 1024 + h * 64) * 256);
        const char* vl0 = (const char*)(VTL + ((size_t)blk * 1024 + h * 64) * 256);
        #pragma unroll
        for (int i = 0; i < 4; i++) {
            const int cidx = tid + i * 512;
            const int row = cidx >> 5;
            const int cbo = (cidx & 31) << 4;
            const uint32_t d = SWZ512((uint32_t)(row * 512 + cbo));
            const size_t go = (size_t)row * 512 + cbo;
            cp16(VHs + d, vh0 + go);
            cp16(VLs + d, vl0 + go);
        }
        cp_commit();
        asm volatile("cp.async.wait_group 0;" ::: "memory");
        __syncthreads();
    }

    const int arow = (lane & 7) + ((lane >> 3) & 1) * 8;
    const int acol = (lane >> 4) * 16;
    const int brow = (lane & 7) + ((lane >> 4) & 1) * 8;
    const int bcol = ((lane >> 3) & 1) * 16;

    // ---- phase 1: S = Qh Kh^T + Qh Kl^T + Ql Kh^T ----
    float s[32][4];
    #pragma unroll
    for (int j = 0; j < 32; j++)
        #pragma unroll
        for (int q = 0; q < 4; q++) s[j][q] = 0.f;

    #pragma unroll
    for (int kk = 0; kk < 4; kk++) {
        const uint32_t kb = kk * 32;
        uint32_t qh[4], ql[4];
        const uint32_t aoff = SWZ128((uint32_t)((w * 16 + arow) * 128 + kb + acol));
        ldsm_x4(QHs + aoff, qh);
        ldsm_x4(QLs + aoff, ql);
        #pragma unroll
        for (int p = 0; p < 16; p++) {
            uint32_t bh[4], bl[4];
            const uint32_t boff = SWZ128((uint32_t)((p * 16 + brow) * 128 + kb + bcol));
            ldsm_x4(KHs + boff, bh);
            ldsm_x4(KLs + boff, bl);
            mma_f16(s[2 * p],     qh, bh[0], bh[1]);
            mma_f16(s[2 * p],     qh, bl[0], bl[1]);
            mma_f16(s[2 * p],     ql, bh[0], bh[1]);
            mma_f16(s[2 * p + 1], qh, bh[2], bh[3]);
            mma_f16(s[2 * p + 1], qh, bl[2], bl[3]);
            mma_f16(s[2 * p + 1], ql, bh[2], bh[3]);
        }
    }

    // ---- softmax ----
    const int r0 = w * 16 + (lane >> 2);
    const int cq = (lane & 3) * 2;
    const float* br0 = bias + ((size_t)h * 256 + r0) * 256;
    const float* br1 = br0 + 8 * 256;

    float m0 = -1e30f, m1 = -1e30f;
    #pragma unroll
    for (int j = 0; j < 32; j++) {
        const float2 b0 = *(const float2*)(br0 + j * 8 + cq);
        const float2 b1 = *(const float2*)(br1 + j * 8 + cq);
        s[j][0] = s[j][0] * 0.125f + b0.x;
        s[j][1] = s[j][1] * 0.125f + b0.y;
        s[j][2] = s[j][2] * 0.125f + b1.x;
        s[j][3] = s[j][3] * 0.125f + b1.y;
        m0 = fmaxf(m0, fmaxf(s[j][0], s[j][1]));
        m1 = fmaxf(m1, fmaxf(s[j][2], s[j][3]));
    }
    #pragma unroll
    for (int msk = 1; msk <= 2; msk <<= 1) {
        m0 = fmaxf(m0, __shfl_xor_sync(0xffffffffu, m0, msk));
        m1 = fmaxf(m1, __shfl_xor_sync(0xffffffffu, m1, msk));
    }
    float l0 = 0.f, l1 = 0.f;
    #pragma unroll
    for (int j = 0; j < 32; j++) {
        s[j][0] = __expf(s[j][0] - m0);
        s[j][1] = __expf(s[j][1] - m0);
        s[j][2] = __expf(s[j][2] - m1);
        s[j][3] = __expf(s[j][3] - m1);
        l0 += s[j][0] + s[j][1];
        l1 += s[j][2] + s[j][3];
    }
    #pragma unroll
    for (int msk = 1; msk <= 2; msk <<= 1) {
        l0 += __shfl_xor_sync(0xffffffffu, l0, msk);
        l1 += __shfl_xor_sync(0xffffffffu, l1, msk);
    }

    // ---- phase 2: O = Ph Vh + Ph Vl + Pl Vh ----
    float o[8][4];
    #pragma unroll
    for (int j = 0; j < 8; j++)
        #pragma unroll
        for (int q = 0; q < 4; q++) o[j][q] = 0.f;

    #pragma unroll
    for (int kt = 0; kt < 16; kt++) {
        uint32_t pah[4], pal[4];
        #pragma unroll
        for (int half_ = 0; half_ < 2; half_++) {
            const float* sv = s[2 * kt + half_];
            const float p0 = sv[0], p1 = sv[1], p2 = sv[2], p3 = sv[3];
            const __half h0 = __float2half_rn(p0);
            const __half h1 = __float2half_rn(p1);
            const __half h2 = __float2half_rn(p2);
            const __half h3 = __float2half_rn(p3);
            pah[2 * half_ + 0] = pack_f16x2(__half2float(h0), __half2float(h1));
            pah[2 * half_ + 1] = pack_f16x2(__half2float(h2), __half2float(h3));
            pal[2 * half_ + 0] = pack_f16x2(p0 - __half2float(h0), p1 - __half2float(h1));
            pal[2 * half_ + 1] = pack_f16x2(p2 - __half2float(h2), p3 - __half2float(h3));
        }
        #pragma unroll
        for (int nd = 0; nd < 4; nd++) {
            uint32_t bh[4], bl[4];
            const uint32_t boff = SWZ512((uint32_t)((nd * 16 + brow) * 512 + kt * 32 + bcol));
            ldsm_x4(VHs + boff, bh);
            ldsm_x4(VLs + boff, bl);
            mma_f16(o[2 * nd],     pah, bh[0], bh[1]);
            mma_f16(o[2 * nd],     pah, bl[0], bl[1]);
            mma_f16(o[2 * nd],     pal, bh[0], bh[1]);
            mma_f16(o[2 * nd + 1], pah, bh[2], bh[3]);
            mma_f16(o[2 * nd + 1], pah, bl[2], bl[3]);
            mma_f16(o[2 * nd + 1], pal, bh[2], bh[3]);
        }
    }

    // ---- epilogue ----
    const float inv0 = 1.f / l0;
    const float inv1 = 1.f / l1;
    const size_t row0 = (size_t)blk * 256 + r0;
    #pragma unroll
    for (int j = 0; j < 8; j++) {
        const int col = h * 64 + j * 8 + cq;
        {
            const float v0 = o[j][0] * inv0;
            const float v1 = o[j][1] * inv0;
            const __half h0 = __float2half_rn(v0);
            const __half h1 = __float2half_rn(v1);
            *(__half2*)(CH + row0 * 1024 + col) = __halves2half2(h0, h1);
            *(__half2*)(CL + row0 * 1024 + col) = __halves2half2(
                __float2half_rn(v0 - __half2float(h0)),
                __float2half_rn(v1 - __half2float(h1)));
        }
        {
            const float v0 = o[j][2] * inv1;
            const float v1 = o[j][3] * inv1;
            const __half h0 = __float2half_rn(v0);
            const __half h1 = __float2half_rn(v1);
            *(__half2*)(CH + (row0 + 8) * 1024 + col) = __halves2half2(h0, h1);
            *(__half2*)(CL + (row0 + 8) * 1024 + col) = __halves2half2(
                __float2half_rn(v0 - __half2float(h0)),
                __float2half_rn(v1 - __half2float(h1)));
        }
    }
}

// =================== mean pool -> split fp16 directly ===================
__global__ void meanpool_hl_kernel(const float* __restrict__ x,
                                   __half* __restrict__ H, __half* __restrict__ L)
{
    const int blk = blockIdx.x;                 // 0..63
    const int c   = blockIdx.y * 256 + threadIdx.x;
    const float* base = x + (size_t)blk * BSZ * D_MODEL + c;
    float s = 0.f;
    #pragma unroll 4
    for (int r = 0; r < BSZ; r++) s += base[(size_t)r * D_MODEL];
    const float v = s * (1.0f / BSZ);
    const __half h = __float2half_rn(v);
    H[blk * D_MODEL + c] = h;
    L[blk * D_MODEL + c] = __float2half_rn(v - __half2float(h));
}

// =================== summary attention (fp32 in, split fp16 out) ===================
__global__ void summ_attn_kernel(
    const float* __restrict__ Q2, const float* __restrict__ K2,
    const float* __restrict__ V2,
    __half* __restrict__ SCH, __half* __restrict__ SCL)
{
    const int b = blockIdx.x;
    const int h = blockIdx.y;
    const int l = threadIdx.x;

    const float* qr = Q2 + (size_t)(b * 16 + l) * D_MODEL + h * DHEAD;
    float q[DHEAD];
    #pragma unroll
    for (int d = 0; d < DHEAD; d += 4) {
        const float4 v = *(const float4*)(qr + d);
        q[d] = v.x; q[d + 1] = v.y; q[d + 2] = v.z; q[d + 3] = v.w;
    }

    float s[16];
    float m = -1e30f;
    for (int j = 0; j < 16; j++) {
        const float* kr = K2 + (size_t)(b * 16 + j) * D_MODEL + h * DHEAD;
        float a = 0.f;
        #pragma unroll
        for (int d = 0; d < DHEAD; d += 4) {
            const float4 v = *(const float4*)(kr + d);
            a += q[d] * v.x + q[d + 1] * v.y + q[d + 2] * v.z + q[d + 3] * v.w;
        }
        s[j] = a * 0.125f;
        m = fmaxf(m, s[j]);
    }
    float lsum = 0.f;
    for (int j = 0; j < 16; j++) { s[j] = __expf(s[j] - m); lsum += s[j]; }
    const float inv = 1.f / lsum;

    float o[DHEAD];
    #pragma unroll
    for (int d = 0; d < DHEAD; d++) o[d] = 0.f;
    for (int j = 0; j < 16; j++) {
        const float* vr = V2 + (size_t)(b * 16 + j) * D_MODEL + h * DHEAD;
        const float p = s[j] * inv;
        #pragma unroll
        for (int d = 0; d < DHEAD; d += 4) {
            const float4 v = *(const float4*)(vr + d);
            o[d] += p * v.x; o[d + 1] += p * v.y; o[d + 2] += p * v.z; o[d + 3] += p * v.w;
        }
    }
    const size_t ob = (size_t)(b * 16 + l) * D_MODEL + h * DHEAD;
    #pragma unroll
    for (int d = 0; d < DHEAD; d += 2) {
        const __half h0 = __float2half_rn(o[d]);
        const __half h1 = __float2half_rn(o[d + 1]);
        *(__half2*)(SCH + ob + d) = __halves2half2(h0, h1);
        *(__half2*)(SCL + ob + d) = __halves2half2(
            __float2half_rn(o[d] - __half2float(h0)),
            __float2half_rn(o[d + 1] - __half2float(h1)));
    }
}

// =================== launch ===================
extern "C" void kernel_launch(void* const* d_in, const int* in_sizes, int n_in,
                              void* d_out, int out_size)
{
    const float* x     = (const float*)d_in[0];
    const float* lq_w  = (const float*)d_in[1];
    const float* lq_b  = (const float*)d_in[2];
    const float* lk_w  = (const float*)d_in[3];
    const float* lk_b  = (const float*)d_in[4];
    const float* lv_w  = (const float*)d_in[5];
    const float* lv_b  = (const float*)d_in[6];
    const float* lo_w  = (const float*)d_in[7];
    const float* lo_b  = (const float*)d_in[8];
    const float* pbias = (const float*)d_in[9];
    const float* sq_w  = (const float*)d_in[10];
    const float* sq_b  = (const float*)d_in[11];
    const float* sk_w  = (const float*)d_in[12];
    const float* sk_b  = (const float*)d_in[13];
    const float* sv_w  = (const float*)d_in[14];
    const float* sv_b  = (const float*)d_in[15];
    const float* so_w  = (const float*)d_in[16];
    const float* so_b  = (const float*)d_in[17];
    const float* sum_w = (const float*)d_in[18];
    const float* sum_b = (const float*)d_in[19];
    float* out = (float*)d_out;

    float *Q2, *K2, *V2, *SOUT, *PART;
    cudaGetSymbolAddress((void**)&Q2,   g_Q2);
    cudaGetSymbolAddress((void**)&K2,   g_K2);
    cudaGetSymbolAddress((void**)&V2,   g_V2);
    cudaGetSymbolAddress((void**)&SOUT, g_SOUT);
    cudaGetSymbolAddress((void**)&PART, g_PART);

    __half *XH, *XL, *QH, *QL, *KH, *KL, *VH, *VL, *VTH, *VTL, *CH, *CL, *WH, *WL;
    __half *S1H, *S1L, *S2H, *S2L, *S3H, *S3L;
    cudaGetSymbolAddress((void**)&XH, g_XH);
    cudaGetSymbolAddress((void**)&XL, g_XL);
    cudaGetSymbolAddress((void**)&QH, g_QH);
    cudaGetSymbolAddress((void**)&QL, g_QL);
    cudaGetSymbolAddress((void**)&KH, g_KH);
    cudaGetSymbolAddress((void**)&KL, g_KL);
    cudaGetSymbolAddress((void**)&VH, g_VH);
    cudaGetSymbolAddress((void**)&VL, g_VL);
    cudaGetSymbolAddress((void**)&VTH, g_VTH);
    cudaGetSymbolAddress((void**)&VTL, g_VTL);
    cudaGetSymbolAddress((void**)&CH, g_CH);
    cudaGetSymbolAddress((void**)&CL, g_CL);
    cudaGetSymbolAddress((void**)&WH, g_WH);
    cudaGetSymbolAddress((void**)&WL, g_WL);
    cudaGetSymbolAddress((void**)&S1H, g_S1H);
    cudaGetSymbolAddress((void**)&S1L, g_S1L);
    cudaGetSymbolAddress((void**)&S2H, g_S2H);
    cudaGetSymbolAddress((void**)&S2L, g_S2L);
    cudaGetSymbolAddress((void**)&S3H, g_S3H);
    cudaGetSymbolAddress((void**)&S3L, g_S3L);

    // weight order: 0 lq, 1 lk, 2 lv (contiguous for fused QKV), 3 lo, 4 sum, 5 sq, 6 sk, 7 sv, 8 so
    WP9 wp;
    const float* ws[9] = {lq_w, lk_w, lv_w, lo_w, sum_w, sq_w, sk_w, sv_w, so_w};
    for (int i = 0; i < 9; i++) {
        wp.w[i] = ws[i];
        wp.h[i] = WH + (size_t)i * WSTRIDE;
        wp.l[i] = WL + (size_t)i * WSTRIDE;
    }

    cudaFuncSetAttribute(gemm_smallk_kernel,
                         cudaFuncAttributeMaxDynamicSharedMemorySize, GEMM3_SMEM);
    cudaFuncSetAttribute(gemm2_kernel,
                         cudaFuncAttributeMaxDynamicSharedMemorySize, GEMM2_SMEM);
    cudaFuncSetAttribute(gemm2_qkv_kernel,
                         cudaFuncAttributeMaxDynamicSharedMemorySize, GEMM2_SMEM);
    cudaFuncSetAttribute(attn_mma_kernel,
                         cudaFuncAttributeMaxDynamicSharedMemorySize, ATT_SMEM);

    // ---- prep ----
    prep_w_kernel<<<dim3(32, 32, 9), dim3(32, 8)>>>(wp);
    prep_act_kernel<<<16384, 256>>>((const float4*)x, XH, XL, 4194304);

    // ---- small summary path (split-K latency-optimized) ----
    meanpool_hl_kernel<<<dim3(NBLK, 4), 256>>>(x, S1H, S1L);
    gemm_smallk_kernel<<<dim3(8, 1, 4), 256, GEMM3_SMEM>>>(S1H, S1L, WH, WL, 4, PART);
    reduce_hl_kernel<<<512, 256>>>(PART, sum_b, S2H, S2L);
    gemm_smallk_kernel<<<dim3(8, 3, 4), 256, GEMM3_SMEM>>>(S2H, S2L, WH, WL, 5, PART);
    reduce_fp32_kernel<<<256, 256>>>(PART + 0 * 4 * PART_STRIDE, sq_b, Q2);
    reduce_fp32_kernel<<<256, 256>>>(PART + 1 * 4 * PART_STRIDE, sk_b, K2);
    reduce_fp32_kernel<<<256, 256>>>(PART + 2 * 4 * PART_STRIDE, sv_b, V2);
    summ_attn_kernel<<<dim3(4, NHEAD), 16>>>(Q2, K2, V2, S3H, S3L);
    gemm_smallk_kernel<<<dim3(8, 1, 4), 256, GEMM3_SMEM>>>(S3H, S3L, WH, WL, 8, PART);
    reduce_fp32_kernel<<<256, 256>>>(PART, so_b, SOUT);

    // ---- local path (2-term fp16 big GEMMs) ----
    gemm2_qkv_kernel<<<dim3(24, NTOK / 128), 256, GEMM2_SMEM>>>(
        XH, XL, wp.h[0], lq_b, lk_b, lv_b,
        QH, QL, KH, KL, VH, VL);
    vtrans_kernel<<<dim3(NBLK, 16), 256>>>(VH, VL, VTH, VTL);
    attn_mma_kernel<<<dim3(NBLK, NHEAD), 512, ATT_SMEM>>>(
        QH, QL, KH, KL, VTH, VTL, pbias, CH, CL);
    gemm2_kernel<<<dim3(8, NTOK / 128), 256, GEMM2_SMEM>>>(
        CH, CL, wp.h[3], lo_b, SOUT, out);
}

// round 8
// speedup vs baseline: 1.3471x; 1.3471x over previous
#include <cuda_runtime.h>
#include <cuda_fp16.h>
#include <cstdint>

#define D_MODEL 1024
#define NHEAD   16
#define DHEAD   64
#define BSZ     256
#define NTOK    16384
#define NBLK    64
#define NELEM   ((size_t)NTOK * D_MODEL)
#define WSTRIDE (1024 * 1024)
#define PART_STRIDE (128 * 1024)

// ---------------- fp32 scratch (small path) ----------------
__device__ __align__(16) float g_Q2  [NBLK * D_MODEL];
__device__ __align__(16) float g_K2  [NBLK * D_MODEL];
__device__ __align__(16) float g_V2  [NBLK * D_MODEL];
__device__ __align__(16) float g_SOUT[NBLK * D_MODEL];
__device__ __align__(16) float g_PART[12 * PART_STRIDE];   // split-K partials

// ---------------- fp16 split scratch ----------------
__device__ __align__(16) __half g_XH[NELEM];
__device__ __align__(16) __half g_XL[NELEM];
__device__ __align__(16) __half g_QH[NELEM];
__device__ __align__(16) __half g_QL[NELEM];
__device__ __align__(16) __half g_KH[NELEM];
__device__ __align__(16) __half g_KL[NELEM];
__device__ __align__(16) __half g_VH[NELEM];
__device__ __align__(16) __half g_VL[NELEM];
__device__ __align__(16) __half g_VTH[NELEM];   // [blk][dim][tok]
__device__ __align__(16) __half g_VTL[NELEM];
__device__ __align__(16) __half g_CH[NELEM];
__device__ __align__(16) __half g_CL[NELEM];
__device__ __align__(16) __half g_WH[9][WSTRIDE];  // transposed [N][K] hi
__device__ __align__(16) __half g_WL[9][WSTRIDE];  // transposed [N][K] lo
// per-stage small activations (distinct buffers -> replay-deterministic)
__device__ __align__(16) __half g_S1H[128 * 1024];  // meanpool out
__device__ __align__(16) __half g_S1L[128 * 1024];
__device__ __align__(16) __half g_S2H[128 * 1024];  // summarizer out
__device__ __align__(16) __half g_S2L[128 * 1024];
__device__ __align__(16) __half g_S3H[128 * 1024];  // summ attention ctx
__device__ __align__(16) __half g_S3L[128 * 1024];

// =================== helpers ===================
__device__ __forceinline__ uint32_t smem_u32(const void* p) {
    uint32_t a;
    asm("{ .reg .u64 t; cvta.to.shared.u64 t, %1; cvt.u32.u64 %0, t; }" : "=r"(a) : "l"(p));
    return a;
}
#define SWZ128(off) ((off) ^ (((off) >> 3) & 0x70))
#define SWZ512(off) ((off) ^ (((off) >> 5) & 0x70))

__device__ __forceinline__ void cp16(uint32_t dst, const void* src) {
    asm volatile("cp.async.cg.shared.global [%0], [%1], 16;" :: "r"(dst), "l"(src));
}
__device__ __forceinline__ void cp_commit() {
    asm volatile("cp.async.commit_group;" ::: "memory");
}
__device__ __forceinline__ void ldsm_x4(uint32_t addr, uint32_t r[4]) {
    asm volatile("ldmatrix.sync.aligned.m8n8.x4.shared.b16 {%0,%1,%2,%3}, [%4];"
        : "=r"(r[0]), "=r"(r[1]), "=r"(r[2]), "=r"(r[3]) : "r"(addr));
}
__device__ __forceinline__ void mma_f16(float c[4], const uint32_t a[4],
                                        uint32_t b0, uint32_t b1) {
    asm volatile(
        "mma.sync.aligned.m16n8k16.row.col.f32.f16.f16.f32 "
        "{%0,%1,%2,%3}, {%4,%5,%6,%7}, {%8,%9}, {%0,%1,%2,%3};"
        : "+f"(c[0]), "+f"(c[1]), "+f"(c[2]), "+f"(c[3])
        : "r"(a[0]), "r"(a[1]), "r"(a[2]), "r"(a[3]), "r"(b0), "r"(b1));
}
// fp16-accumulate HMMA (2x rate) — used ONLY for low-order correction terms.
__device__ __forceinline__ void mma_f16acc(uint32_t c[2], const uint32_t a[4],
                                           uint32_t b0, uint32_t b1) {
    asm volatile(
        "mma.sync.aligned.m16n8k16.row.col.f16.f16.f16.f16 "
        "{%0,%1}, {%2,%3,%4,%5}, {%6,%7}, {%0,%1};"
        : "+r"(c[0]), "+r"(c[1])
        : "r"(a[0]), "r"(a[1]), "r"(a[2]), "r"(a[3]), "r"(b0), "r"(b1));
}
__device__ __forceinline__ uint32_t pack_f16x2(float lo, float hi) {
    uint32_t r;
    asm("cvt.rn.f16x2.f32 %0, %1, %2;" : "=r"(r) : "f"(hi), "f"(lo));
    return r;
}

// =================== prep kernels ===================
__global__ void prep_act_kernel(const float4* __restrict__ A,
                                __half* __restrict__ H,
                                __half* __restrict__ L,
                                int nquads)
{
    const int i = blockIdx.x * blockDim.x + threadIdx.x;
    if (i >= nquads) return;
    const float4 v = A[i];
    const __half h0 = __float2half_rn(v.x);
    const __half h1 = __float2half_rn(v.y);
    const __half h2 = __float2half_rn(v.z);
    const __half h3 = __float2half_rn(v.w);
    *(__half2*)(H + (size_t)i * 4)     = __halves2half2(h0, h1);
    *(__half2*)(H + (size_t)i * 4 + 2) = __halves2half2(h2, h3);
    *(__half2*)(L + (size_t)i * 4)     = __halves2half2(
        __float2half_rn(v.x - __half2float(h0)), __float2half_rn(v.y - __half2float(h1)));
    *(__half2*)(L + (size_t)i * 4 + 2) = __halves2half2(
        __float2half_rn(v.z - __half2float(h2)), __float2half_rn(v.w - __half2float(h3)));
}

struct WP9 {
    const float* w[9];
    __half* h[9];
    __half* l[9];
};
__global__ void prep_w_kernel(WP9 wp)
{
    __shared__ float t[32][33];
    const int z  = blockIdx.z;
    const float* W = wp.w[z];
    __half* H = wp.h[z];
    __half* L = wp.l[z];
    const int bx = blockIdx.x;
    const int by = blockIdx.y;
    const int tx = threadIdx.x;
    const int ty = threadIdx.y;
    #pragma unroll
    for (int r = 0; r < 32; r += 8)
        t[ty + r][tx] = W[(size_t)(by * 32 + ty + r) * 1024 + bx * 32 + tx];
    __syncthreads();
    #pragma unroll
    for (int r = 0; r < 32; r += 8) {
        const float v = t[tx][ty + r];
        const __half h = __float2half_rn(v);
        const size_t o = (size_t)(bx * 32 + ty + r) * 1024 + by * 32 + tx;
        H[o] = h;
        if (z >= 4) L[o] = __float2half_rn(v - __half2float(h));  // lo only used by 3-term path
    }
}

// =================== fragment index helpers ===================
#define FRAG_IDX()                                                            \
    const int arow_in = (lane & 7) + ((lane >> 3) & 1) * 8;                   \
    const int acolx   = (lane >> 4) * 16;                                     \
    const int brow_in = (lane & 7) + ((lane >> 4) & 1) * 8;                   \
    const int bcolx   = ((lane >> 3) & 1) * 16;

#define BUF3_BYTES 65536
#define GEMM3_SMEM (2 * BUF3_BYTES)

#define ISSUE3(ic, buf) do {                                                  \
    const uint32_t sbase = sb + (buf) * BUF3_BYTES;                           \
    const size_t coff = (size_t)(ic) * 128 + cb;                              \
    _Pragma("unroll")                                                         \
    for (int i = 0; i < 4; i++) {                                             \
        const size_t go = (size_t)(rcp + i * 32) * 2048 + coff;               \
        cp16(sbase + dsw[i],          gAh + go);                              \
        cp16(sbase + 16384 + dsw[i],  gAl + go);                              \
        cp16(sbase + 32768 + dsw[i],  gBh + go);                              \
        cp16(sbase + 49152 + dsw[i],  gBl + go);                              \
    }                                                                         \
    cp_commit();                                                              \
} while (0)

// =================== split-K 3-term small GEMM -> fp32 partials ===================
// grid (8, nz, 4): bn, zi (weight = zbase+zi), ks (K-split slot). M fixed 128.
__global__ __launch_bounds__(256, 1) void gemm_smallk_kernel(
    const __half* __restrict__ Ah, const __half* __restrict__ Al,
    const __half* __restrict__ WHb, const __half* __restrict__ WLb,
    int zbase, float* __restrict__ P)
{
    extern __shared__ char smem[];
    const uint32_t sb = smem_u32(smem);
    const int tid  = threadIdx.x;
    const int lane = tid & 31;
    const int wid  = tid >> 5;
    const int wm   = wid & 3;
    const int wn   = wid >> 2;
    const int bn = blockIdx.x;
    const int zi = blockIdx.y;
    const int ks = blockIdx.z;
    const int rcp = tid >> 3;
    const int cb  = (tid & 7) << 4;
    uint32_t dsw[4];
    #pragma unroll
    for (int i = 0; i < 4; i++) dsw[i] = SWZ128((uint32_t)((rcp + i * 32) * 128 + cb));
    FRAG_IDX();

    const char* gAh = (const char*)Ah;
    const char* gAl = (const char*)Al;
    const char* gBh = (const char*)(WHb + (size_t)(zbase + zi) * WSTRIDE + (size_t)bn * 128 * 1024);
    const char* gBl = (const char*)(WLb + (size_t)(zbase + zi) * WSTRIDE + (size_t)bn * 128 * 1024);

    float c[2][8][4];
    #pragma unroll
    for (int mt = 0; mt < 2; mt++)
        #pragma unroll
        for (int nb = 0; nb < 8; nb++)
            #pragma unroll
            for (int j = 0; j < 4; j++) c[mt][nb][j] = 0.f;

    const int ic0 = ks * 4;
    ISSUE3(ic0, 0);
    #pragma unroll 1
    for (int it = 0; it < 4; it++) {
        const int cur = it & 1;
        if (it < 3) ISSUE3(ic0 + it + 1, cur ^ 1);
        if (it < 3) asm volatile("cp.async.wait_group 1;" ::: "memory");
        else        asm volatile("cp.async.wait_group 0;" ::: "memory");
        __syncthreads();
        const uint32_t base = sb + cur * BUF3_BYTES;
        #pragma unroll
        for (int kk = 0; kk < 4; kk++) {
            const uint32_t kb = kk * 32;
            uint32_t ah[2][4], al_[2][4];
            #pragma unroll
            for (int mt = 0; mt < 2; mt++) {
                const uint32_t off =
                    SWZ128((uint32_t)((wm * 32 + mt * 16 + arow_in) * 128 + kb + acolx));
                ldsm_x4(base + off,          ah[mt]);
                ldsm_x4(base + 16384 + off,  al_[mt]);
            }
            uint32_t bh[4][4], bl[4][4];
            #pragma unroll
            for (int p = 0; p < 4; p++) {
                const uint32_t off =
                    SWZ128((uint32_t)((wn * 64 + p * 16 + brow_in) * 128 + kb + bcolx));
                ldsm_x4(base + 32768 + off, bh[p]);
                ldsm_x4(base + 49152 + off, bl[p]);
            }
            #pragma unroll
            for (int mt = 0; mt < 2; mt++) {
                #pragma unroll
                for (int p = 0; p < 4; p++) {
                    mma_f16(c[mt][2 * p],     ah[mt],  bh[p][0], bh[p][1]);
                    mma_f16(c[mt][2 * p],     ah[mt],  bl[p][0], bl[p][1]);
                    mma_f16(c[mt][2 * p],     al_[mt], bh[p][0], bh[p][1]);
                    mma_f16(c[mt][2 * p + 1], ah[mt],  bh[p][2], bh[p][3]);
                    mma_f16(c[mt][2 * p + 1], ah[mt],  bl[p][2], bl[p][3]);
                    mma_f16(c[mt][2 * p + 1], al_[mt], bh[p][2], bh[p][3]);
                }
            }
        }
        __syncthreads();
    }

    float* Pp = P + (size_t)(zi * 4 + ks) * PART_STRIDE;
    const int row_base = wm * 32 + (lane >> 2);
    const int col_base = bn * 128 + wn * 64 + 2 * (lane & 3);
    #pragma unroll
    for (int mt = 0; mt < 2; mt++) {
        #pragma unroll
        for (int hh = 0; hh < 2; hh++) {
            const int row = row_base + mt * 16 + hh * 8;
            #pragma unroll
            for (int nb = 0; nb < 8; nb++) {
                const int col = col_base + nb * 8;
                float2 o;
                o.x = c[mt][nb][hh * 2 + 0];
                o.y = c[mt][nb][hh * 2 + 1];
                *(float2*)(Pp + (size_t)row * 1024 + col) = o;
            }
        }
    }
}

// ---- reduce 4 partials + bias -> fp32 (grid 256: rows 0..63 only) ----
__global__ void reduce_fp32_kernel(const float* __restrict__ P,
                                   const float* __restrict__ bias,
                                   float* __restrict__ C)
{
    const int idx = blockIdx.x * 256 + threadIdx.x;
    const float s = P[idx] + P[idx + PART_STRIDE] + P[idx + 2 * PART_STRIDE] + P[idx + 3 * PART_STRIDE];
    C[idx] = s + bias[idx & 1023];
}

// ---- reduce 4 partials + bias -> split fp16 (grid 512: all 128 rows) ----
__global__ void reduce_hl_kernel(const float* __restrict__ P,
                                 const float* __restrict__ bias,
                                 __half* __restrict__ H, __half* __restrict__ L)
{
    const int idx = blockIdx.x * 256 + threadIdx.x;
    const float v = P[idx] + P[idx + PART_STRIDE] + P[idx + 2 * PART_STRIDE] + P[idx + 3 * PART_STRIDE]
                  + bias[idx & 1023];
    const __half h = __float2half_rn(v);
    H[idx] = h;
    L[idx] = __float2half_rn(v - __half2float(h));
}

// =================== 2-term GEMM mainloop (big path) ===================
// C ~= Ah*Bh (fp32 acc) + Al*Bh (fp16 acc, 2x-rate HMMA)
#define BUF2_BYTES 49152
#define GEMM2_SMEM (2 * BUF2_BYTES)

#define GEMM2_BODY()                                                          \
    extern __shared__ char smem[];                                            \
    const uint32_t sb = smem_u32(smem);                                       \
    const int tid  = threadIdx.x;                                             \
    const int lane = tid & 31;                                                \
    const int wid  = tid >> 5;                                                \
    const int wm   = wid & 3;                                                 \
    const int wn   = wid >> 2;                                                \
    const int bn = blockIdx.x;                                                \
    const int bm = blockIdx.y;                                                \
    const int rcp = tid >> 3;                                                 \
    const int cb  = (tid & 7) << 4;                                           \
    uint32_t dsw[4];                                                          \
    _Pragma("unroll")                                                         \
    for (int i = 0; i < 4; i++) dsw[i] = SWZ128((uint32_t)((rcp + i * 32) * 128 + cb)); \
    FRAG_IDX();                                                               \
    float c[2][8][4];                                                         \
    uint32_t cl[2][8][2];                                                     \
    _Pragma("unroll")                                                         \
    for (int mt = 0; mt < 2; mt++)                                            \
        _Pragma("unroll")                                                     \
        for (int nb = 0; nb < 8; nb++) {                                      \
            _Pragma("unroll")                                                 \
            for (int j = 0; j < 4; j++) c[mt][nb][j] = 0.f;                   \
            cl[mt][nb][0] = 0u; cl[mt][nb][1] = 0u;                           \
        }                                                                     \
    ISSUE2(0, 0);                                                             \
    _Pragma("unroll 1")                                                       \
    for (int ic = 0; ic < 16; ic++) {                                         \
        const int cur = ic & 1;                                               \
        if (ic < 15) ISSUE2(ic + 1, cur ^ 1);                                 \
        if (ic < 15) asm volatile("cp.async.wait_group 1;" ::: "memory");     \
        else         asm volatile("cp.async.wait_group 0;" ::: "memory");     \
        __syncthreads();                                                      \
        const uint32_t base = sb + cur * BUF2_BYTES;                          \
        _Pragma("unroll")                                                     \
        for (int kk = 0; kk < 4; kk++) {                                      \
            const uint32_t kb = kk * 32;                                      \
            uint32_t ah[2][4], al_[2][4];                                     \
            _Pragma("unroll")                                                 \
            for (int mt = 0; mt < 2; mt++) {                                  \
                const uint32_t off =                                          \
                    SWZ128((uint32_t)((wm * 32 + mt * 16 + arow_in) * 128 + kb + acolx)); \
                ldsm_x4(base + off,          ah[mt]);                         \
                ldsm_x4(base + 16384 + off,  al_[mt]);                        \
            }                                                                 \
            uint32_t bh[4][4];                                                \
            _Pragma("unroll")                                                 \
            for (int p = 0; p < 4; p++) {                                     \
                const uint32_t off =                                          \
                    SWZ128((uint32_t)((wn * 64 + p * 16 + brow_in) * 128 + kb + bcolx)); \
                ldsm_x4(base + 32768 + off, bh[p]);                           \
            }                                                                 \
            _Pragma("unroll")                                                 \
            for (int mt = 0; mt < 2; mt++) {                                  \
                _Pragma("unroll")                                             \
                for (int p = 0; p < 4; p++) {                                 \
                    mma_f16(c[mt][2 * p],        ah[mt],  bh[p][0], bh[p][1]); \
                    mma_f16acc(cl[mt][2 * p],    al_[mt], bh[p][0], bh[p][1]); \
                    mma_f16(c[mt][2 * p + 1],    ah[mt],  bh[p][2], bh[p][3]); \
                    mma_f16acc(cl[mt][2 * p + 1], al_[mt], bh[p][2], bh[p][3]); \
                }                                                             \
            }                                                                 \
        }                                                                     \
        __syncthreads();                                                      \
    }

#define ISSUE2(ic, buf) do {                                                  \
    const uint32_t sbase = sb + (buf) * BUF2_BYTES;                           \
    const size_t coff = (size_t)(ic) * 128 + cb;                              \
    _Pragma("unroll")                                                         \
    for (int i = 0; i < 4; i++) {                                             \
        const size_t go = (size_t)(rcp + i * 32) * 2048 + coff;               \
        cp16(sbase + dsw[i],          gAh + go);                              \
        cp16(sbase + 16384 + dsw[i],  gAl + go);                              \
        cp16(sbase + 32768 + dsw[i],  gBh + go);                              \
    }                                                                         \
    cp_commit();                                                              \
} while (0)

// ---- o-proj: fp32 out, bias + summary add ----
__global__ __launch_bounds__(256, 1) void gemm2_kernel(
    const __half* __restrict__ Ah, const __half* __restrict__ Al,
    const __half* __restrict__ Bh,
    const float* __restrict__ bias, const float* __restrict__ addBlk,
    float* __restrict__ C)
{
    const char* gAh = (const char*)(Ah + (size_t)(blockIdx.y * 128) * 1024);
    const char* gAl = (const char*)(Al + (size_t)(blockIdx.y * 128) * 1024);
    const char* gBh = (const char*)(Bh + (size_t)(blockIdx.x * 128) * 1024);
    GEMM2_BODY();

    const int row_base = bm * 128 + wm * 32 + (lane >> 2);
    const int col_base = bn * 128 + wn * 64 + 2 * (lane & 3);
    #pragma unroll
    for (int mt = 0; mt < 2; mt++) {
        #pragma unroll
        for (int hh = 0; hh < 2; hh++) {
            const int row = row_base + mt * 16 + hh * 8;
            const int rb = row >> 8;
            #pragma unroll
            for (int nb = 0; nb < 8; nb++) {
                const int col = col_base + nb * 8;
                const __half2 lo2 = *(const __half2*)&cl[mt][nb][hh];
                float2 o;
                o.x = c[mt][nb][hh * 2 + 0] + __low2float(lo2)
                    + bias[col + 0] + addBlk[(size_t)rb * 1024 + col + 0];
                o.y = c[mt][nb][hh * 2 + 1] + __high2float(lo2)
                    + bias[col + 1] + addBlk[(size_t)rb * 1024 + col + 1];
                *(float2*)(C + (size_t)row * 1024 + col) = o;
            }
        }
    }
}

// ---- fused QKV: split-fp16 out ----
__global__ __launch_bounds__(256, 1) void gemm2_qkv_kernel(
    const __half* __restrict__ Ah, const __half* __restrict__ Al,
    const __half* __restrict__ Bh,
    const float* __restrict__ bq, const float* __restrict__ bk, const float* __restrict__ bv,
    __half* __restrict__ QH, __half* __restrict__ QL,
    __half* __restrict__ KH, __half* __restrict__ KL,
    __half* __restrict__ VH, __half* __restrict__ VL)
{
    const char* gAh = (const char*)(Ah + (size_t)(blockIdx.y * 128) * 1024);
    const char* gAl = (const char*)(Al + (size_t)(blockIdx.y * 128) * 1024);
    const char* gBh = (const char*)(Bh + (size_t)(blockIdx.x * 128) * 1024);
    GEMM2_BODY();

    const int tensor = bn >> 3;
    const float* bias = (tensor == 0) ? bq : (tensor == 1) ? bk : bv;
    __half* OH = (tensor == 0) ? QH : (tensor == 1) ? KH : VH;
    __half* OL = (tensor == 0) ? QL : (tensor == 1) ? KL : VL;

    const int row_base = bm * 128 + wm * 32 + (lane >> 2);
    const int col_base = (bn & 7) * 128 + wn * 64 + 2 * (lane & 3);
    #pragma unroll
    for (int mt = 0; mt < 2; mt++) {
        #pragma unroll
        for (int hh = 0; hh < 2; hh++) {
            const int row = row_base + mt * 16 + hh * 8;
            #pragma unroll
            for (int nb = 0; nb < 8; nb++) {
                const int col = col_base + nb * 8;
                const __half2 lo2 = *(const __half2*)&cl[mt][nb][hh];
                const float v0 = c[mt][nb][hh * 2 + 0] + __low2float(lo2) + bias[col + 0];
                const float v1 = c[mt][nb][hh * 2 + 1] + __high2float(lo2) + bias[col + 1];
                const __half h0 = __float2half_rn(v0);
                const __half h1 = __float2half_rn(v1);
                *(__half2*)(OH + (size_t)row * 1024 + col) = __halves2half2(h0, h1);
                *(__half2*)(OL + (size_t)row * 1024 + col) = __halves2half2(
                    __float2half_rn(v0 - __half2float(h0)),
                    __float2half_rn(v1 - __half2float(h1)));
            }
        }
    }
}

// =================== V transpose: [tok][dim] -> [blk][dim][tok] ===================
__global__ __launch_bounds__(256) void vtrans_kernel(
    const __half* __restrict__ VH, const __half* __restrict__ VL,
    __half* __restrict__ VTH, __half* __restrict__ VTL)
{
    __shared__ __half t[256][72];
    const int blk = blockIdx.x;
    const int dt  = blockIdx.y;
    const int tid = threadIdx.x;
    #pragma unroll 1
    for (int pass = 0; pass < 2; pass++) {
        const __half* src = pass ? VL : VH;
        __half* dst = pass ? VTL : VTH;
        #pragma unroll
        for (int it = 0; it < 8; it++) {
            const int task = it * 256 + tid;
            const int row = task >> 3;
            const int dc  = (task & 7) * 8;
            *(uint4*)&t[row][dc] =
                *(const uint4*)(src + ((size_t)(blk * 256 + row)) * 1024 + dt * 64 + dc);
        }
        __syncthreads();
        #pragma unroll
        for (int it = 0; it < 8; it++) {
            const int task = it * 256 + tid;
            const int d  = task >> 5;
            const int tc = (task & 31) * 8;
            __half tmp[8];
            #pragma unroll
            for (int j = 0; j < 8; j++) tmp[j] = t[tc + j][d];
            *(uint4*)(dst + ((size_t)(blk * 1024) + dt * 64 + d) * 256 + tc) = *(uint4*)tmp;
        }
        __syncthreads();
    }
}

// =================== HMMA local attention (3-term fp16) ===================
#define ATT_SMEM (6 * 32768)

__global__ __launch_bounds__(512, 1) void attn_mma_kernel(
    const __half* __restrict__ QH, const __half* __restrict__ QL,
    const __half* __restrict__ KH, const __half* __restrict__ KL,
    const __half* __restrict__ VTH, const __half* __restrict__ VTL,
    const float* __restrict__ bias,
    __half* __restrict__ CH, __half* __restrict__ CL)
{
    extern __shared__ char smem[];
    const uint32_t sb = smem_u32(smem);
    const int blk = blockIdx.x;
    const int h   = blockIdx.y;
    const int tid = threadIdx.x;
    const int lane = tid & 31;
    const int w    = tid >> 5;

    const uint32_t QHs = sb;
    const uint32_t QLs = sb + 32768;
    const uint32_t KHs = sb + 65536;
    const uint32_t KLs = sb + 98304;
    const uint32_t VHs = sb + 131072;
    const uint32_t VLs = sb + 163840;

    {
        const char* qh0 = (const char*)(QH + ((size_t)blk * 256) * 1024 + h * 64);
        const char* ql0 = (const char*)(QL + ((size_t)blk * 256) * 1024 + h * 64);
        const char* kh0 = (const char*)(KH + ((size_t)blk * 256) * 1024 + h * 64);
        const char* kl0 = (const char*)(KL + ((size_t)blk * 256) * 1024 + h * 64);
        #pragma unroll
        for (int i = 0; i < 4; i++) {
            const int cidx = tid + i * 512;
            const int row = cidx >> 3;
            const int cbo = (cidx & 7) << 4;
            const uint32_t d = SWZ128((uint32_t)(row * 128 + cbo));
            const size_t go = (size_t)row * 2048 + cbo;
            cp16(QHs + d, qh0 + go);
            cp16(QLs + d, ql0 + go);
            cp16(KHs + d, kh0 + go);
            cp16(KLs + d, kl0 + go);
        }
        const char* vh0 = (const char*)(VTH + ((size_t)blk * 1024 + h * 64) * 256);
        const char* vl0 = (const char*)(VTL + ((size_t)blk * 1024 + h * 64) * 256);
        #pragma unroll
        for (int i = 0; i < 4; i++) {
            const int cidx = tid + i * 512;
            const int row = cidx >> 5;
            const int cbo = (cidx & 31) << 4;
            const uint32_t d = SWZ512((uint32_t)(row * 512 + cbo));
            const size_t go = (size_t)row * 512 + cbo;
            cp16(VHs + d, vh0 + go);
            cp16(VLs + d, vl0 + go);
        }
        cp_commit();
        asm volatile("cp.async.wait_group 0;" ::: "memory");
        __syncthreads();
    }

    const int arow = (lane & 7) + ((lane >> 3) & 1) * 8;
    const int acol = (lane >> 4) * 16;
    const int brow = (lane & 7) + ((lane >> 4) & 1) * 8;
    const int bcol = ((lane >> 3) & 1) * 16;

    // ---- phase 1: S = Qh Kh^T + Qh Kl^T + Ql Kh^T ----
    float s[32][4];
    #pragma unroll
    for (int j = 0; j < 32; j++)
        #pragma unroll
        for (int q = 0; q < 4; q++) s[j][q] = 0.f;

    #pragma unroll
    for (int kk = 0; kk < 4; kk++) {
        const uint32_t kb = kk * 32;
        uint32_t qh[4], ql[4];
        const uint32_t aoff = SWZ128((uint32_t)((w * 16 + arow) * 128 + kb + acol));
        ldsm_x4(QHs + aoff, qh);
        ldsm_x4(QLs + aoff, ql);
        #pragma unroll
        for (int p = 0; p < 16; p++) {
            uint32_t bh[4], bl[4];
            const uint32_t boff = SWZ128((uint32_t)((p * 16 + brow) * 128 + kb + bcol));
            ldsm_x4(KHs + boff, bh);
            ldsm_x4(KLs + boff, bl);
            mma_f16(s[2 * p],     qh, bh[0], bh[1]);
            mma_f16(s[2 * p],     qh, bl[0], bl[1]);
            mma_f16(s[2 * p],     ql, bh[0], bh[1]);
            mma_f16(s[2 * p + 1], qh, bh[2], bh[3]);
            mma_f16(s[2 * p + 1], qh, bl[2], bl[3]);
            mma_f16(s[2 * p + 1], ql, bh[2], bh[3]);
        }
    }

    // ---- softmax ----
    const int r0 = w * 16 + (lane >> 2);
    const int cq = (lane & 3) * 2;
    const float* br0 = bias + ((size_t)h * 256 + r0) * 256;
    const float* br1 = br0 + 8 * 256;

    float m0 = -1e30f, m1 = -1e30f;
    #pragma unroll
    for (int j = 0; j < 32; j++) {
        const float2 b0 = *(const float2*)(br0 + j * 8 + cq);
        const float2 b1 = *(const float2*)(br1 + j * 8 + cq);
        s[j][0] = s[j][0] * 0.125f + b0.x;
        s[j][1] = s[j][1] * 0.125f + b0.y;
        s[j][2] = s[j][2] * 0.125f + b1.x;
        s[j][3] = s[j][3] * 0.125f + b1.y;
        m0 = fmaxf(m0, fmaxf(s[j][0], s[j][1]));
        m1 = fmaxf(m1, fmaxf(s[j][2], s[j][3]));
    }
    #pragma unroll
    for (int msk = 1; msk <= 2; msk <<= 1) {
        m0 = fmaxf(m0, __shfl_xor_sync(0xffffffffu, m0, msk));
        m1 = fmaxf(m1, __shfl_xor_sync(0xffffffffu, m1, msk));
    }
    float l0 = 0.f, l1 = 0.f;
    #pragma unroll
    for (int j = 0; j < 32; j++) {
        s[j][0] = __expf(s[j][0] - m0);
        s[j][1] = __expf(s[j][1] - m0);
        s[j][2] = __expf(s[j][2] - m1);
        s[j][3] = __expf(s[j][3] - m1);
        l0 += s[j][0] + s[j][1];
        l1 += s[j][2] + s[j][3];
    }
    #pragma unroll
    for (int msk = 1; msk <= 2; msk <<= 1) {
        l0 += __shfl_xor_sync(0xffffffffu, l0, msk);
        l1 += __shfl_xor_sync(0xffffffffu, l1, msk);
    }

    // ---- phase 2: O = Ph Vh + Ph Vl + Pl Vh ----
    float o[8][4];
    #pragma unroll
    for (int j = 0; j < 8; j++)
        #pragma unroll
        for (int q = 0; q < 4; q++) o[j][q] = 0.f;

    #pragma unroll
    for (int kt = 0; kt < 16; kt++) {
        uint32_t pah[4], pal[4];
        #pragma unroll
        for (int half_ = 0; half_ < 2; half_++) {
            const float* sv = s[2 * kt + half_];
            const float p0 = sv[0], p1 = sv[1], p2 = sv[2], p3 = sv[3];
            const __half h0 = __float2half_rn(p0);
            const __half h1 = __float2half_rn(p1);
            const __half h2 = __float2half_rn(p2);
            const __half h3 = __float2half_rn(p3);
            pah[2 * half_ + 0] = pack_f16x2(__half2float(h0), __half2float(h1));
            pah[2 * half_ + 1] = pack_f16x2(__half2float(h2), __half2float(h3));
            pal[2 * half_ + 0] = pack_f16x2(p0 - __half2float(h0), p1 - __half2float(h1));
            pal[2 * half_ + 1] = pack_f16x2(p2 - __half2float(h2), p3 - __half2float(h3));
        }
        #pragma unroll
        for (int nd = 0; nd < 4; nd++) {
            uint32_t bh[4], bl[4];
            const uint32_t boff = SWZ512((uint32_t)((nd * 16 + brow) * 512 + kt * 32 + bcol));
            ldsm_x4(VHs + boff, bh);
            ldsm_x4(VLs + boff, bl);
            mma_f16(o[2 * nd],     pah, bh[0], bh[1]);
            mma_f16(o[2 * nd],     pah, bl[0], bl[1]);
            mma_f16(o[2 * nd],     pal, bh[0], bh[1]);
            mma_f16(o[2 * nd + 1], pah, bh[2], bh[3]);
            mma_f16(o[2 * nd + 1], pah, bl[2], bl[3]);
            mma_f16(o[2 * nd + 1], pal, bh[2], bh[3]);
        }
    }

    // ---- epilogue ----
    const float inv0 = 1.f / l0;
    const float inv1 = 1.f / l1;
    const size_t row0 = (size_t)blk * 256 + r0;
    #pragma unroll
    for (int j = 0; j < 8; j++) {
        const int col = h * 64 + j * 8 + cq;
        {
            const float v0 = o[j][0] * inv0;
            const float v1 = o[j][1] * inv0;
            const __half h0 = __float2half_rn(v0);
            const __half h1 = __float2half_rn(v1);
            *(__half2*)(CH + row0 * 1024 + col) = __halves2half2(h0, h1);
            *(__half2*)(CL + row0 * 1024 + col) = __halves2half2(
                __float2half_rn(v0 - __half2float(h0)),
                __float2half_rn(v1 - __half2float(h1)));
        }
        {
            const float v0 = o[j][2] * inv1;
            const float v1 = o[j][3] * inv1;
            const __half h0 = __float2half_rn(v0);
            const __half h1 = __float2half_rn(v1);
            *(__half2*)(CH + (row0 + 8) * 1024 + col) = __halves2half2(h0, h1);
            *(__half2*)(CL + (row0 + 8) * 1024 + col) = __halves2half2(
                __float2half_rn(v0 - __half2float(h0)),
                __float2half_rn(v1 - __half2float(h1)));
        }
    }
}

// =================== mean pool -> split fp16 directly ===================
__global__ void meanpool_hl_kernel(const float* __restrict__ x,
                                   __half* __restrict__ H, __half* __restrict__ L)
{
    const int blk = blockIdx.x;                 // 0..63
    const int c   = blockIdx.y * 256 + threadIdx.x;
    const float* base = x + (size_t)blk * BSZ * D_MODEL + c;
    float s = 0.f;
    #pragma unroll 4
    for (int r = 0; r < BSZ; r++) s += base[(size_t)r * D_MODEL];
    const float v = s * (1.0f / BSZ);
    const __half h = __float2half_rn(v);
    H[blk * D_MODEL + c] = h;
    L[blk * D_MODEL + c] = __float2half_rn(v - __half2float(h));
}

// =================== summary attention (fp32 in, split fp16 out) ===================
__global__ void summ_attn_kernel(
    const float* __restrict__ Q2, const float* __restrict__ K2,
    const float* __restrict__ V2,
    __half* __restrict__ SCH, __half* __restrict__ SCL)
{
    const int b = blockIdx.x;
    const int h = blockIdx.y;
    const int l = threadIdx.x;

    const float* qr = Q2 + (size_t)(b * 16 + l) * D_MODEL + h * DHEAD;
    float q[DHEAD];
    #pragma unroll
    for (int d = 0; d < DHEAD; d += 4) {
        const float4 v = *(const float4*)(qr + d);
        q[d] = v.x; q[d + 1] = v.y; q[d + 2] = v.z; q[d + 3] = v.w;
    }

    float s[16];
    float m = -1e30f;
    for (int j = 0; j < 16; j++) {
        const float* kr = K2 + (size_t)(b * 16 + j) * D_MODEL + h * DHEAD;
        float a = 0.f;
        #pragma unroll
        for (int d = 0; d < DHEAD; d += 4) {
            const float4 v = *(const float4*)(kr + d);
            a += q[d] * v.x + q[d + 1] * v.y + q[d + 2] * v.z + q[d + 3] * v.w;
        }
        s[j] = a * 0.125f;
        m = fmaxf(m, s[j]);
    }
    float lsum = 0.f;
    for (int j = 0; j < 16; j++) { s[j] = __expf(s[j] - m); lsum += s[j]; }
    const float inv = 1.f / lsum;

    float o[DHEAD];
    #pragma unroll
    for (int d = 0; d < DHEAD; d++) o[d] = 0.f;
    for (int j = 0; j < 16; j++) {
        const float* vr = V2 + (size_t)(b * 16 + j) * D_MODEL + h * DHEAD;
        const float p = s[j] * inv;
        #pragma unroll
        for (int d = 0; d < DHEAD; d += 4) {
            const float4 v = *(const float4*)(vr + d);
            o[d] += p * v.x; o[d + 1] += p * v.y; o[d + 2] += p * v.z; o[d + 3] += p * v.w;
        }
    }
    const size_t ob = (size_t)(b * 16 + l) * D_MODEL + h * DHEAD;
    #pragma unroll
    for (int d = 0; d < DHEAD; d += 2) {
        const __half h0 = __float2half_rn(o[d]);
        const __half h1 = __float2half_rn(o[d + 1]);
        *(__half2*)(SCH + ob + d) = __halves2half2(h0, h1);
        *(__half2*)(SCL + ob + d) = __halves2half2(
            __float2half_rn(o[d] - __half2float(h0)),
            __float2half_rn(o[d + 1] - __half2float(h1)));
    }
}

// =================== launch ===================
extern "C" void kernel_launch(void* const* d_in, const int* in_sizes, int n_in,
                              void* d_out, int out_size)
{
    const float* x     = (const float*)d_in[0];
    const float* lq_w  = (const float*)d_in[1];
    const float* lq_b  = (const float*)d_in[2];
    const float* lk_w  = (const float*)d_in[3];
    const float* lk_b  = (const float*)d_in[4];
    const float* lv_w  = (const float*)d_in[5];
    const float* lv_b  = (const float*)d_in[6];
    const float* lo_w  = (const float*)d_in[7];
    const float* lo_b  = (const float*)d_in[8];
    const float* pbias = (const float*)d_in[9];
    const float* sq_w  = (const float*)d_in[10];
    const float* sq_b  = (const float*)d_in[11];
    const float* sk_w  = (const float*)d_in[12];
    const float* sk_b  = (const float*)d_in[13];
    const float* sv_w  = (const float*)d_in[14];
    const float* sv_b  = (const float*)d_in[15];
    const float* so_w  = (const float*)d_in[16];
    const float* so_b  = (const float*)d_in[17];
    const float* sum_w = (const float*)d_in[18];
    const float* sum_b = (const float*)d_in[19];
    float* out = (float*)d_out;

    float *Q2, *K2, *V2, *SOUT, *PART;
    cudaGetSymbolAddress((void**)&Q2,   g_Q2);
    cudaGetSymbolAddress((void**)&K2,   g_K2);
    cudaGetSymbolAddress((void**)&V2,   g_V2);
    cudaGetSymbolAddress((void**)&SOUT, g_SOUT);
    cudaGetSymbolAddress((void**)&PART, g_PART);

    __half *XH, *XL, *QH, *QL, *KH, *KL, *VH, *VL, *VTH, *VTL, *CH, *CL, *WH, *WL;
    __half *S1H, *S1L, *S2H, *S2L, *S3H, *S3L;
    cudaGetSymbolAddress((void**)&XH, g_XH);
    cudaGetSymbolAddress((void**)&XL, g_XL);
    cudaGetSymbolAddress((void**)&QH, g_QH);
    cudaGetSymbolAddress((void**)&QL, g_QL);
    cudaGetSymbolAddress((void**)&KH, g_KH);
    cudaGetSymbolAddress((void**)&KL, g_KL);
    cudaGetSymbolAddress((void**)&VH, g_VH);
    cudaGetSymbolAddress((void**)&VL, g_VL);
    cudaGetSymbolAddress((void**)&VTH, g_VTH);
    cudaGetSymbolAddress((void**)&VTL, g_VTL);
    cudaGetSymbolAddress((void**)&CH, g_CH);
    cudaGetSymbolAddress((void**)&CL, g_CL);
    cudaGetSymbolAddress((void**)&WH, g_WH);
    cudaGetSymbolAddress((void**)&WL, g_WL);
    cudaGetSymbolAddress((void**)&S1H, g_S1H);
    cudaGetSymbolAddress((void**)&S1L, g_S1L);
    cudaGetSymbolAddress((void**)&S2H, g_S2H);
    cudaGetSymbolAddress((void**)&S2L, g_S2L);
    cudaGetSymbolAddress((void**)&S3H, g_S3H);
    cudaGetSymbolAddress((void**)&S3L, g_S3L);

    // weight order: 0 lq, 1 lk, 2 lv (contiguous for fused QKV), 3 lo, 4 sum, 5 sq, 6 sk, 7 sv, 8 so
    WP9 wp;
    const float* ws[9] = {lq_w, lk_w, lv_w, lo_w, sum_w, sq_w, sk_w, sv_w, so_w};
    for (int i = 0; i < 9; i++) {
        wp.w[i] = ws[i];
        wp.h[i] = WH + (size_t)i * WSTRIDE;
        wp.l[i] = WL + (size_t)i * WSTRIDE;
    }

    cudaFuncSetAttribute(gemm_smallk_kernel,
                         cudaFuncAttributeMaxDynamicSharedMemorySize, GEMM3_SMEM);
    cudaFuncSetAttribute(gemm2_kernel,
                         cudaFuncAttributeMaxDynamicSharedMemorySize, GEMM2_SMEM);
    cudaFuncSetAttribute(gemm2_qkv_kernel,
                         cudaFuncAttributeMaxDynamicSharedMemorySize, GEMM2_SMEM);
    cudaFuncSetAttribute(attn_mma_kernel,
                         cudaFuncAttributeMaxDynamicSharedMemorySize, ATT_SMEM);

    // ---- prep ----
    prep_w_kernel<<<dim3(32, 32, 9), dim3(32, 8)>>>(wp);
    prep_act_kernel<<<16384, 256>>>((const float4*)x, XH, XL, 4194304);

    // ---- small summary path (split-K latency-optimized) ----
    meanpool_hl_kernel<<<dim3(NBLK, 4), 256>>>(x, S1H, S1L);
    gemm_smallk_kernel<<<dim3(8, 1, 4), 256, GEMM3_SMEM>>>(S1H, S1L, WH, WL, 4, PART);
    reduce_hl_kernel<<<512, 256>>>(PART, sum_b, S2H, S2L);
    gemm_smallk_kernel<<<dim3(8, 3, 4), 256, GEMM3_SMEM>>>(S2H, S2L, WH, WL, 5, PART);
    reduce_fp32_kernel<<<256, 256>>>(PART + 0 * 4 * PART_STRIDE, sq_b, Q2);
    reduce_fp32_kernel<<<256, 256>>>(PART + 1 * 4 * PART_STRIDE, sk_b, K2);
    reduce_fp32_kernel<<<256, 256>>>(PART + 2 * 4 * PART_STRIDE, sv_b, V2);
    summ_attn_kernel<<<dim3(4, NHEAD), 16>>>(Q2, K2, V2, S3H, S3L);
    gemm_smallk_kernel<<<dim3(8, 1, 4), 256, GEMM3_SMEM>>>(S3H, S3L, WH, WL, 8, PART);
    reduce_fp32_kernel<<<256, 256>>>(PART, so_b, SOUT);

    // ---- local path (2-term fp16 big GEMMs, lo-term in fp16-acc HMMA) ----
    gemm2_qkv_kernel<<<dim3(24, NTOK / 128), 256, GEMM2_SMEM>>>(
        XH, XL, wp.h[0], lq_b, lk_b, lv_b,
        QH, QL, KH, KL, VH, VL);
    vtrans_kernel<<<dim3(NBLK, 16), 256>>>(VH, VL, VTH, VTL);
    attn_mma_kernel<<<dim3(NBLK, NHEAD), 512, ATT_SMEM>>>(
        QH, QL, KH, KL, VTH, VTL, pbias, CH, CL);
    gemm2_kernel<<<dim3(8, NTOK / 128), 256, GEMM2_SMEM>>>(
        CH, CL, wp.h[3], lo_b, SOUT, out);
}

// round 9
// speedup vs baseline: 1.5853x; 1.1768x over previous
#include <cuda_runtime.h>
#include <cuda_fp16.h>
#include <cstdint>

#define D_MODEL 1024
#define NHEAD   16
#define DHEAD   64
#define BSZ     256
#define NTOK    16384
#define NBLK    64
#define NELEM   ((size_t)NTOK * D_MODEL)
#define WSTRIDE (1024 * 1024)
#define PART_STRIDE (128 * 1024)

// ---------------- fp32 scratch (small path) ----------------
__device__ __align__(16) float g_Q2  [NBLK * D_MODEL];
__device__ __align__(16) float g_K2  [NBLK * D_MODEL];
__device__ __align__(16) float g_V2  [NBLK * D_MODEL];
__device__ __align__(16) float g_SOUT[NBLK * D_MODEL];
__device__ __align__(16) float g_PART[12 * PART_STRIDE];   // split-K partials

// ---------------- fp16 split scratch ----------------
__device__ __align__(16) __half g_XH[NELEM];
__device__ __align__(16) __half g_QH[NELEM];
__device__ __align__(16) __half g_QL[NELEM];
__device__ __align__(16) __half g_KH[NELEM];
__device__ __align__(16) __half g_KL[NELEM];
__device__ __align__(16) __half g_VH[NELEM];
__device__ __align__(16) __half g_VL[NELEM];
__device__ __align__(16) __half g_VTH[NELEM];   // [blk][dim][tok]
__device__ __align__(16) __half g_VTL[NELEM];
__device__ __align__(16) __half g_CH[NELEM];
__device__ __align__(16) __half g_CL[NELEM];
__device__ __align__(16) __half g_WH[9][WSTRIDE];  // transposed [N][K] hi
__device__ __align__(16) __half g_WL[9][WSTRIDE];  // transposed [N][K] lo
// per-stage small activations (distinct buffers -> replay-deterministic)
__device__ __align__(16) __half g_S1H[128 * 1024];  // meanpool out
__device__ __align__(16) __half g_S1L[128 * 1024];
__device__ __align__(16) __half g_S2H[128 * 1024];  // summarizer out
__device__ __align__(16) __half g_S2L[128 * 1024];
__device__ __align__(16) __half g_S3H[128 * 1024];  // summ attention ctx
__device__ __align__(16) __half g_S3L[128 * 1024];

// =================== helpers ===================
__device__ __forceinline__ uint32_t smem_u32(const void* p) {
    uint32_t a;
    asm("{ .reg .u64 t; cvta.to.shared.u64 t, %1; cvt.u32.u64 %0, t; }" : "=r"(a) : "l"(p));
    return a;
}
#define SWZ128(off) ((off) ^ (((off) >> 3) & 0x70))
#define SWZ512(off) ((off) ^ (((off) >> 5) & 0x70))

__device__ __forceinline__ void cp16(uint32_t dst, const void* src) {
    asm volatile("cp.async.cg.shared.global [%0], [%1], 16;" :: "r"(dst), "l"(src));
}
__device__ __forceinline__ void cp_commit() {
    asm volatile("cp.async.commit_group;" ::: "memory");
}
__device__ __forceinline__ void ldsm_x4(uint32_t addr, uint32_t r[4]) {
    asm volatile("ldmatrix.sync.aligned.m8n8.x4.shared.b16 {%0,%1,%2,%3}, [%4];"
        : "=r"(r[0]), "=r"(r[1]), "=r"(r[2]), "=r"(r[3]) : "r"(addr));
}
__device__ __forceinline__ void mma_f16(float c[4], const uint32_t a[4],
                                        uint32_t b0, uint32_t b1) {
    asm volatile(
        "mma.sync.aligned.m16n8k16.row.col.f32.f16.f16.f32 "
        "{%0,%1,%2,%3}, {%4,%5,%6,%7}, {%8,%9}, {%0,%1,%2,%3};"
        : "+f"(c[0]), "+f"(c[1]), "+f"(c[2]), "+f"(c[3])
        : "r"(a[0]), "r"(a[1]), "r"(a[2]), "r"(a[3]), "r"(b0), "r"(b1));
}
// fp16-accumulate HMMA — used ONLY for low-order correction terms (o-proj).
__device__ __forceinline__ void mma_f16acc(uint32_t c[2], const uint32_t a[4],
                                           uint32_t b0, uint32_t b1) {
    asm volatile(
        "mma.sync.aligned.m16n8k16.row.col.f16.f16.f16.f16 "
        "{%0,%1}, {%2,%3,%4,%5}, {%6,%7}, {%0,%1};"
        : "+r"(c[0]), "+r"(c[1])
        : "r"(a[0]), "r"(a[1]), "r"(a[2]), "r"(a[3]), "r"(b0), "r"(b1));
}
__device__ __forceinline__ uint32_t pack_f16x2(float lo, float hi) {
    uint32_t r;
    asm("cvt.rn.f16x2.f32 %0, %1, %2;" : "=r"(r) : "f"(hi), "f"(lo));
    return r;
}

// =================== prep kernels ===================
// hi-only (QKV input is 1-term now)
__global__ void prep_act_h_kernel(const float4* __restrict__ A,
                                  __half* __restrict__ H, int nquads)
{
    const int i = blockIdx.x * blockDim.x + threadIdx.x;
    if (i >= nquads) return;
    const float4 v = A[i];
    *(__half2*)(H + (size_t)i * 4)     = __halves2half2(__float2half_rn(v.x), __float2half_rn(v.y));
    *(__half2*)(H + (size_t)i * 4 + 2) = __halves2half2(__float2half_rn(v.z), __float2half_rn(v.w));
}

struct WP9 {
    const float* w[9];
    __half* h[9];
    __half* l[9];
};
__global__ void prep_w_kernel(WP9 wp)
{
    __shared__ float t[32][33];
    const int z  = blockIdx.z;
    const float* W = wp.w[z];
    __half* H = wp.h[z];
    __half* L = wp.l[z];
    const int bx = blockIdx.x;
    const int by = blockIdx.y;
    const int tx = threadIdx.x;
    const int ty = threadIdx.y;
    #pragma unroll
    for (int r = 0; r < 32; r += 8)
        t[ty + r][tx] = W[(size_t)(by * 32 + ty + r) * 1024 + bx * 32 + tx];
    __syncthreads();
    #pragma unroll
    for (int r = 0; r < 32; r += 8) {
        const float v = t[tx][ty + r];
        const __half h = __float2half_rn(v);
        const size_t o = (size_t)(bx * 32 + ty + r) * 1024 + by * 32 + tx;
        H[o] = h;
        if (z >= 4) L[o] = __float2half_rn(v - __half2float(h));  // lo only used by 3-term path
    }
}

// =================== fragment index helpers ===================
#define FRAG_IDX()                                                            \
    const int arow_in = (lane & 7) + ((lane >> 3) & 1) * 8;                   \
    const int acolx   = (lane >> 4) * 16;                                     \
    const int brow_in = (lane & 7) + ((lane >> 4) & 1) * 8;                   \
    const int bcolx   = ((lane >> 3) & 1) * 16;

#define BUF3_BYTES 65536
#define GEMM3_SMEM (2 * BUF3_BYTES)

#define ISSUE3(ic, buf) do {                                                  \
    const uint32_t sbase = sb + (buf) * BUF3_BYTES;                           \
    const size_t coff = (size_t)(ic) * 128 + cb;                              \
    _Pragma("unroll")                                                         \
    for (int i = 0; i < 4; i++) {                                             \
        const size_t go = (size_t)(rcp + i * 32) * 2048 + coff;               \
        cp16(sbase + dsw[i],          gAh + go);                              \
        cp16(sbase + 16384 + dsw[i],  gAl + go);                              \
        cp16(sbase + 32768 + dsw[i],  gBh + go);                              \
        cp16(sbase + 49152 + dsw[i],  gBl + go);                              \
    }                                                                         \
    cp_commit();                                                              \
} while (0)

// =================== split-K 3-term small GEMM -> fp32 partials ===================
// grid (8, nz, 4): bn, zi (weight = zbase+zi), ks (K-split slot). M fixed 128.
__global__ __launch_bounds__(256, 1) void gemm_smallk_kernel(
    const __half* __restrict__ Ah, const __half* __restrict__ Al,
    const __half* __restrict__ WHb, const __half* __restrict__ WLb,
    int zbase, float* __restrict__ P)
{
    extern __shared__ char smem[];
    const uint32_t sb = smem_u32(smem);
    const int tid  = threadIdx.x;
    const int lane = tid & 31;
    const int wid  = tid >> 5;
    const int wm   = wid & 3;
    const int wn   = wid >> 2;
    const int bn = blockIdx.x;
    const int zi = blockIdx.y;
    const int ks = blockIdx.z;
    const int rcp = tid >> 3;
    const int cb  = (tid & 7) << 4;
    uint32_t dsw[4];
    #pragma unroll
    for (int i = 0; i < 4; i++) dsw[i] = SWZ128((uint32_t)((rcp + i * 32) * 128 + cb));
    FRAG_IDX();

    const char* gAh = (const char*)Ah;
    const char* gAl = (const char*)Al;
    const char* gBh = (const char*)(WHb + (size_t)(zbase + zi) * WSTRIDE + (size_t)bn * 128 * 1024);
    const char* gBl = (const char*)(WLb + (size_t)(zbase + zi) * WSTRIDE + (size_t)bn * 128 * 1024);

    float c[2][8][4];
    #pragma unroll
    for (int mt = 0; mt < 2; mt++)
        #pragma unroll
        for (int nb = 0; nb < 8; nb++)
            #pragma unroll
            for (int j = 0; j < 4; j++) c[mt][nb][j] = 0.f;

    const int ic0 = ks * 4;
    ISSUE3(ic0, 0);
    #pragma unroll 1
    for (int it = 0; it < 4; it++) {
        const int cur = it & 1;
        if (it < 3) ISSUE3(ic0 + it + 1, cur ^ 1);
        if (it < 3) asm volatile("cp.async.wait_group 1;" ::: "memory");
        else        asm volatile("cp.async.wait_group 0;" ::: "memory");
        __syncthreads();
        const uint32_t base = sb + cur * BUF3_BYTES;
        #pragma unroll
        for (int kk = 0; kk < 4; kk++) {
            const uint32_t kb = kk * 32;
            uint32_t ah[2][4], al_[2][4];
            #pragma unroll
            for (int mt = 0; mt < 2; mt++) {
                const uint32_t off =
                    SWZ128((uint32_t)((wm * 32 + mt * 16 + arow_in) * 128 + kb + acolx));
                ldsm_x4(base + off,          ah[mt]);
                ldsm_x4(base + 16384 + off,  al_[mt]);
            }
            uint32_t bh[4][4], bl[4][4];
            #pragma unroll
            for (int p = 0; p < 4; p++) {
                const uint32_t off =
                    SWZ128((uint32_t)((wn * 64 + p * 16 + brow_in) * 128 + kb + bcolx));
                ldsm_x4(base + 32768 + off, bh[p]);
                ldsm_x4(base + 49152 + off, bl[p]);
            }
            #pragma unroll
            for (int mt = 0; mt < 2; mt++) {
                #pragma unroll
                for (int p = 0; p < 4; p++) {
                    mma_f16(c[mt][2 * p],     ah[mt],  bh[p][0], bh[p][1]);
                    mma_f16(c[mt][2 * p],     ah[mt],  bl[p][0], bl[p][1]);
                    mma_f16(c[mt][2 * p],     al_[mt], bh[p][0], bh[p][1]);
                    mma_f16(c[mt][2 * p + 1], ah[mt],  bh[p][2], bh[p][3]);
                    mma_f16(c[mt][2 * p + 1], ah[mt],  bl[p][2], bl[p][3]);
                    mma_f16(c[mt][2 * p + 1], al_[mt], bh[p][2], bh[p][3]);
                }
            }
        }
        __syncthreads();
    }

    float* Pp = P + (size_t)(zi * 4 + ks) * PART_STRIDE;
    const int row_base = wm * 32 + (lane >> 2);
    const int col_base = bn * 128 + wn * 64 + 2 * (lane & 3);
    #pragma unroll
    for (int mt = 0; mt < 2; mt++) {
        #pragma unroll
        for (int hh = 0; hh < 2; hh++) {
            const int row = row_base + mt * 16 + hh * 8;
            #pragma unroll
            for (int nb = 0; nb < 8; nb++) {
                const int col = col_base + nb * 8;
                float2 o;
                o.x = c[mt][nb][hh * 2 + 0];
                o.y = c[mt][nb][hh * 2 + 1];
                *(float2*)(Pp + (size_t)row * 1024 + col) = o;
            }
        }
    }
}

// ---- reduce 4 partials + bias -> fp32 (grid 256: rows 0..63 only) ----
__global__ void reduce_fp32_kernel(const float* __restrict__ P,
                                   const float* __restrict__ bias,
                                   float* __restrict__ C)
{
    const int idx = blockIdx.x * 256 + threadIdx.x;
    const float s = P[idx] + P[idx + PART_STRIDE] + P[idx + 2 * PART_STRIDE] + P[idx + 3 * PART_STRIDE];
    C[idx] = s + bias[idx & 1023];
}

// ---- reduce 4 partials + bias -> split fp16 (grid 512: all 128 rows) ----
__global__ void reduce_hl_kernel(const float* __restrict__ P,
                                 const float* __restrict__ bias,
                                 __half* __restrict__ H, __half* __restrict__ L)
{
    const int idx = blockIdx.x * 256 + threadIdx.x;
    const float v = P[idx] + P[idx + PART_STRIDE] + P[idx + 2 * PART_STRIDE] + P[idx + 3 * PART_STRIDE]
                  + bias[idx & 1023];
    const __half h = __float2half_rn(v);
    H[idx] = h;
    L[idx] = __float2half_rn(v - __half2float(h));
}

// =================== 1-term GEMM (QKV): C ~= Ah * Bh ===================
#define BUF1_BYTES 32768
#define GEMM1_SMEM (2 * BUF1_BYTES)

#define ISSUE1(ic, buf) do {                                                  \
    const uint32_t sbase = sb + (buf) * BUF1_BYTES;                           \
    const size_t coff = (size_t)(ic) * 128 + cb;                              \
    _Pragma("unroll")                                                         \
    for (int i = 0; i < 4; i++) {                                             \
        const size_t go = (size_t)(rcp + i * 32) * 2048 + coff;               \
        cp16(sbase + dsw[i],          gAh + go);                              \
        cp16(sbase + 16384 + dsw[i],  gBh + go);                              \
    }                                                                         \
    cp_commit();                                                              \
} while (0)

// ---- fused QKV: 1-term fp16, split-fp16 out ----
__global__ __launch_bounds__(256, 1) void gemm1_qkv_kernel(
    const __half* __restrict__ Ah, const __half* __restrict__ Bh,
    const float* __restrict__ bq, const float* __restrict__ bk, const float* __restrict__ bv,
    __half* __restrict__ QH, __half* __restrict__ QL,
    __half* __restrict__ KH, __half* __restrict__ KL,
    __half* __restrict__ VH, __half* __restrict__ VL)
{
    extern __shared__ char smem[];
    const uint32_t sb = smem_u32(smem);
    const int tid  = threadIdx.x;
    const int lane = tid & 31;
    const int wid  = tid >> 5;
    const int wm   = wid & 3;
    const int wn   = wid >> 2;
    const int bn = blockIdx.x;
    const int bm = blockIdx.y;
    const int rcp = tid >> 3;
    const int cb  = (tid & 7) << 4;
    uint32_t dsw[4];
    #pragma unroll
    for (int i = 0; i < 4; i++) dsw[i] = SWZ128((uint32_t)((rcp + i * 32) * 128 + cb));
    FRAG_IDX();

    const char* gAh = (const char*)(Ah + (size_t)(bm * 128) * 1024);
    const char* gBh = (const char*)(Bh + (size_t)(bn * 128) * 1024);

    float c[2][8][4];
    #pragma unroll
    for (int mt = 0; mt < 2; mt++)
        #pragma unroll
        for (int nb = 0; nb < 8; nb++)
            #pragma unroll
            for (int j = 0; j < 4; j++) c[mt][nb][j] = 0.f;

    ISSUE1(0, 0);
    #pragma unroll 1
    for (int ic = 0; ic < 16; ic++) {
        const int cur = ic & 1;
        if (ic < 15) ISSUE1(ic + 1, cur ^ 1);
        if (ic < 15) asm volatile("cp.async.wait_group 1;" ::: "memory");
        else         asm volatile("cp.async.wait_group 0;" ::: "memory");
        __syncthreads();
        const uint32_t base = sb + cur * BUF1_BYTES;
        #pragma unroll
        for (int kk = 0; kk < 4; kk++) {
            const uint32_t kb = kk * 32;
            uint32_t ah[2][4];
            #pragma unroll
            for (int mt = 0; mt < 2; mt++) {
                const uint32_t off =
                    SWZ128((uint32_t)((wm * 32 + mt * 16 + arow_in) * 128 + kb + acolx));
                ldsm_x4(base + off, ah[mt]);
            }
            uint32_t bh[4][4];
            #pragma unroll
            for (int p = 0; p < 4; p++) {
                const uint32_t off =
                    SWZ128((uint32_t)((wn * 64 + p * 16 + brow_in) * 128 + kb + bcolx));
                ldsm_x4(base + 16384 + off, bh[p]);
            }
            #pragma unroll
            for (int mt = 0; mt < 2; mt++) {
                #pragma unroll
                for (int p = 0; p < 4; p++) {
                    mma_f16(c[mt][2 * p],     ah[mt], bh[p][0], bh[p][1]);
                    mma_f16(c[mt][2 * p + 1], ah[mt], bh[p][2], bh[p][3]);
                }
            }
        }
        __syncthreads();
    }

    const int tensor = bn >> 3;
    const float* bias = (tensor == 0) ? bq : (tensor == 1) ? bk : bv;
    __half* OH = (tensor == 0) ? QH : (tensor == 1) ? KH : VH;
    __half* OL = (tensor == 0) ? QL : (tensor == 1) ? KL : VL;

    const int row_base = bm * 128 + wm * 32 + (lane >> 2);
    const int col_base = (bn & 7) * 128 + wn * 64 + 2 * (lane & 3);
    #pragma unroll
    for (int mt = 0; mt < 2; mt++) {
        #pragma unroll
        for (int hh = 0; hh < 2; hh++) {
            const int row = row_base + mt * 16 + hh * 8;
            #pragma unroll
            for (int nb = 0; nb < 8; nb++) {
                const int col = col_base + nb * 8;
                const float v0 = c[mt][nb][hh * 2 + 0] + bias[col + 0];
                const float v1 = c[mt][nb][hh * 2 + 1] + bias[col + 1];
                const __half h0 = __float2half_rn(v0);
                const __half h1 = __float2half_rn(v1);
                *(__half2*)(OH + (size_t)row * 1024 + col) = __halves2half2(h0, h1);
                *(__half2*)(OL + (size_t)row * 1024 + col) = __halves2half2(
                    __float2half_rn(v0 - __half2float(h0)),
                    __float2half_rn(v1 - __half2float(h1)));
            }
        }
    }
}

// =================== 2-term GEMM (o-proj): C ~= Ah*Bh (fp32) + Al*Bh (fp16acc) ===================
#define BUF2_BYTES 49152
#define GEMM2_SMEM (2 * BUF2_BYTES)

#define ISSUE2(ic, buf) do {                                                  \
    const uint32_t sbase = sb + (buf) * BUF2_BYTES;                           \
    const size_t coff = (size_t)(ic) * 128 + cb;                              \
    _Pragma("unroll")                                                         \
    for (int i = 0; i < 4; i++) {                                             \
        const size_t go = (size_t)(rcp + i * 32) * 2048 + coff;               \
        cp16(sbase + dsw[i],          gAh + go);                              \
        cp16(sbase + 16384 + dsw[i],  gAl + go);                              \
        cp16(sbase + 32768 + dsw[i],  gBh + go);                              \
    }                                                                         \
    cp_commit();                                                              \
} while (0)

__global__ __launch_bounds__(256, 1) void gemm2_kernel(
    const __half* __restrict__ Ah, const __half* __restrict__ Al,
    const __half* __restrict__ Bh,
    const float* __restrict__ bias, const float* __restrict__ addBlk,
    float* __restrict__ C)
{
    extern __shared__ char smem[];
    const uint32_t sb = smem_u32(smem);
    const int tid  = threadIdx.x;
    const int lane = tid & 31;
    const int wid  = tid >> 5;
    const int wm   = wid & 3;
    const int wn   = wid >> 2;
    const int bn = blockIdx.x;
    const int bm = blockIdx.y;
    const int rcp = tid >> 3;
    const int cb  = (tid & 7) << 4;
    uint32_t dsw[4];
    #pragma unroll
    for (int i = 0; i < 4; i++) dsw[i] = SWZ128((uint32_t)((rcp + i * 32) * 128 + cb));
    FRAG_IDX();

    const char* gAh = (const char*)(Ah + (size_t)(bm * 128) * 1024);
    const char* gAl = (const char*)(Al + (size_t)(bm * 128) * 1024);
    const char* gBh = (const char*)(Bh + (size_t)(bn * 128) * 1024);

    float c[2][8][4];
    uint32_t cl[2][8][2];
    #pragma unroll
    for (int mt = 0; mt < 2; mt++)
        #pragma unroll
        for (int nb = 0; nb < 8; nb++) {
            #pragma unroll
            for (int j = 0; j < 4; j++) c[mt][nb][j] = 0.f;
            cl[mt][nb][0] = 0u; cl[mt][nb][1] = 0u;
        }

    ISSUE2(0, 0);
    #pragma unroll 1
    for (int ic = 0; ic < 16; ic++) {
        const int cur = ic & 1;
        if (ic < 15) ISSUE2(ic + 1, cur ^ 1);
        if (ic < 15) asm volatile("cp.async.wait_group 1;" ::: "memory");
        else         asm volatile("cp.async.wait_group 0;" ::: "memory");
        __syncthreads();
        const uint32_t base = sb + cur * BUF2_BYTES;
        #pragma unroll
        for (int kk = 0; kk < 4; kk++) {
            const uint32_t kb = kk * 32;
            uint32_t ah[2][4], al_[2][4];
            #pragma unroll
            for (int mt = 0; mt < 2; mt++) {
                const uint32_t off =
                    SWZ128((uint32_t)((wm * 32 + mt * 16 + arow_in) * 128 + kb + acolx));
                ldsm_x4(base + off,          ah[mt]);
                ldsm_x4(base + 16384 + off,  al_[mt]);
            }
            uint32_t bh[4][4];
            #pragma unroll
            for (int p = 0; p < 4; p++) {
                const uint32_t off =
                    SWZ128((uint32_t)((wn * 64 + p * 16 + brow_in) * 128 + kb + bcolx));
                ldsm_x4(base + 32768 + off, bh[p]);
            }
            #pragma unroll
            for (int mt = 0; mt < 2; mt++) {
                #pragma unroll
                for (int p = 0; p < 4; p++) {
                    mma_f16(c[mt][2 * p],         ah[mt],  bh[p][0], bh[p][1]);
                    mma_f16acc(cl[mt][2 * p],     al_[mt], bh[p][0], bh[p][1]);
                    mma_f16(c[mt][2 * p + 1],     ah[mt],  bh[p][2], bh[p][3]);
                    mma_f16acc(cl[mt][2 * p + 1], al_[mt], bh[p][2], bh[p][3]);
                }
            }
        }
        __syncthreads();
    }

    const int row_base = bm * 128 + wm * 32 + (lane >> 2);
    const int col_base = bn * 128 + wn * 64 + 2 * (lane & 3);
    #pragma unroll
    for (int mt = 0; mt < 2; mt++) {
        #pragma unroll
        for (int hh = 0; hh < 2; hh++) {
            const int row = row_base + mt * 16 + hh * 8;
            const int rb = row >> 8;
            #pragma unroll
            for (int nb = 0; nb < 8; nb++) {
                const int col = col_base + nb * 8;
                const __half2 lo2 = *(const __half2*)&cl[mt][nb][hh];
                float2 o;
                o.x = c[mt][nb][hh * 2 + 0] + __low2float(lo2)
                    + bias[col + 0] + addBlk[(size_t)rb * 1024 + col + 0];
                o.y = c[mt][nb][hh * 2 + 1] + __high2float(lo2)
                    + bias[col + 1] + addBlk[(size_t)rb * 1024 + col + 1];
                *(float2*)(C + (size_t)row * 1024 + col) = o;
            }
        }
    }
}

// =================== V transpose: [tok][dim] -> [blk][dim][tok] ===================
__global__ __launch_bounds__(256) void vtrans_kernel(
    const __half* __restrict__ VH, const __half* __restrict__ VL,
    __half* __restrict__ VTH, __half* __restrict__ VTL)
{
    __shared__ __half t[256][72];
    const int blk = blockIdx.x;
    const int dt  = blockIdx.y;
    const int tid = threadIdx.x;
    #pragma unroll 1
    for (int pass = 0; pass < 2; pass++) {
        const __half* src = pass ? VL : VH;
        __half* dst = pass ? VTL : VTH;
        #pragma unroll
        for (int it = 0; it < 8; it++) {
            const int task = it * 256 + tid;
            const int row = task >> 3;
            const int dc  = (task & 7) * 8;
            *(uint4*)&t[row][dc] =
                *(const uint4*)(src + ((size_t)(blk * 256 + row)) * 1024 + dt * 64 + dc);
        }
        __syncthreads();
        #pragma unroll
        for (int it = 0; it < 8; it++) {
            const int task = it * 256 + tid;
            const int d  = task >> 5;
            const int tc = (task & 31) * 8;
            __half tmp[8];
            #pragma unroll
            for (int j = 0; j < 8; j++) tmp[j] = t[tc + j][d];
            *(uint4*)(dst + ((size_t)(blk * 1024) + dt * 64 + d) * 256 + tc) = *(uint4*)tmp;
        }
        __syncthreads();
    }
}

// =================== HMMA local attention (3-term fp16) ===================
#define ATT_SMEM (6 * 32768)

__global__ __launch_bounds__(512, 1) void attn_mma_kernel(
    const __half* __restrict__ QH, const __half* __restrict__ QL,
    const __half* __restrict__ KH, const __half* __restrict__ KL,
    const __half* __restrict__ VTH, const __half* __restrict__ VTL,
    const float* __restrict__ bias,
    __half* __restrict__ CH, __half* __restrict__ CL)
{
    extern __shared__ char smem[];
    const uint32_t sb = smem_u32(smem);
    const int blk = blockIdx.x;
    const int h   = blockIdx.y;
    const int tid = threadIdx.x;
    const int lane = tid & 31;
    const int w    = tid >> 5;

    const uint32_t QHs = sb;
    const uint32_t QLs = sb + 32768;
    const uint32_t KHs = sb + 65536;
    const uint32_t KLs = sb + 98304;
    const uint32_t VHs = sb + 131072;
    const uint32_t VLs = sb + 163840;

    {
        const char* qh0 = (const char*)(QH + ((size_t)blk * 256) * 1024 + h * 64);
        const char* ql0 = (const char*)(QL + ((size_t)blk * 256) * 1024 + h * 64);
        const char* kh0 = (const char*)(KH + ((size_t)blk * 256) * 1024 + h * 64);
        const char* kl0 = (const char*)(KL + ((size_t)blk * 256) * 1024 + h * 64);
        #pragma unroll
        for (int i = 0; i < 4; i++) {
            const int cidx = tid + i * 512;
            const int row = cidx >> 3;
            const int cbo = (cidx & 7) << 4;
            const uint32_t d = SWZ128((uint32_t)(row * 128 + cbo));
            const size_t go = (size_t)row * 2048 + cbo;
            cp16(QHs + d, qh0 + go);
            cp16(QLs + d, ql0 + go);
            cp16(KHs + d, kh0 + go);
            cp16(KLs + d, kl0 + go);
        }
        const char* vh0 = (const char*)(VTH + ((size_t)blk * 1024 + h * 64) * 256);
        const char* vl0 = (const char*)(VTL + ((size_t)blk * 1024 + h * 64) * 256);
        #pragma unroll
        for (int i = 0; i < 4; i++) {
            const int cidx = tid + i * 512;
            const int row = cidx >> 5;
            const int cbo = (cidx & 31) << 4;
            const uint32_t d = SWZ512((uint32_t)(row * 512 + cbo));
            const size_t go = (size_t)row * 512 + cbo;
            cp16(VHs + d, vh0 + go);
            cp16(VLs + d, vl0 + go);
        }
        cp_commit();
        asm volatile("cp.async.wait_group 0;" ::: "memory");
        __syncthreads();
    }

    const int arow = (lane & 7) + ((lane >> 3) & 1) * 8;
    const int acol = (lane >> 4) * 16;
    const int brow = (lane & 7) + ((lane >> 4) & 1) * 8;
    const int bcol = ((lane >> 3) & 1) * 16;

    // ---- phase 1: S = Qh Kh^T + Qh Kl^T + Ql Kh^T ----
    float s[32][4];
    #pragma unroll
    for (int j = 0; j < 32; j++)
        #pragma unroll
        for (int q = 0; q < 4; q++) s[j][q] = 0.f;

    #pragma unroll
    for (int kk = 0; kk < 4; kk++) {
        const uint32_t kb = kk * 32;
        uint32_t qh[4], ql[4];
        const uint32_t aoff = SWZ128((uint32_t)((w * 16 + arow) * 128 + kb + acol));
        ldsm_x4(QHs + aoff, qh);
        ldsm_x4(QLs + aoff, ql);
        #pragma unroll
        for (int p = 0; p < 16; p++) {
            uint32_t bh[4], bl[4];
            const uint32_t boff = SWZ128((uint32_t)((p * 16 + brow) * 128 + kb + bcol));
            ldsm_x4(KHs + boff, bh);
            ldsm_x4(KLs + boff, bl);
            mma_f16(s[2 * p],     qh, bh[0], bh[1]);
            mma_f16(s[2 * p],     qh, bl[0], bl[1]);
            mma_f16(s[2 * p],     ql, bh[0], bh[1]);
            mma_f16(s[2 * p + 1], qh, bh[2], bh[3]);
            mma_f16(s[2 * p + 1], qh, bl[2], bl[3]);
            mma_f16(s[2 * p + 1], ql, bh[2], bh[3]);
        }
    }

    // ---- softmax ----
    const int r0 = w * 16 + (lane >> 2);
    const int cq = (lane & 3) * 2;
    const float* br0 = bias + ((size_t)h * 256 + r0) * 256;
    const float* br1 = br0 + 8 * 256;

    float m0 = -1e30f, m1 = -1e30f;
    #pragma unroll
    for (int j = 0; j < 32; j++) {
        const float2 b0 = *(const float2*)(br0 + j * 8 + cq);
        const float2 b1 = *(const float2*)(br1 + j * 8 + cq);
        s[j][0] = s[j][0] * 0.125f + b0.x;
        s[j][1] = s[j][1] * 0.125f + b0.y;
        s[j][2] = s[j][2] * 0.125f + b1.x;
        s[j][3] = s[j][3] * 0.125f + b1.y;
        m0 = fmaxf(m0, fmaxf(s[j][0], s[j][1]));
        m1 = fmaxf(m1, fmaxf(s[j][2], s[j][3]));
    }
    #pragma unroll
    for (int msk = 1; msk <= 2; msk <<= 1) {
        m0 = fmaxf(m0, __shfl_xor_sync(0xffffffffu, m0, msk));
        m1 = fmaxf(m1, __shfl_xor_sync(0xffffffffu, m1, msk));
    }
    float l0 = 0.f, l1 = 0.f;
    #pragma unroll
    for (int j = 0; j < 32; j++) {
        s[j][0] = __expf(s[j][0] - m0);
        s[j][1] = __expf(s[j][1] - m0);
        s[j][2] = __expf(s[j][2] - m1);
        s[j][3] = __expf(s[j][3] - m1);
        l0 += s[j][0] + s[j][1];
        l1 += s[j][2] + s[j][3];
    }
    #pragma unroll
    for (int msk = 1; msk <= 2; msk <<= 1) {
        l0 += __shfl_xor_sync(0xffffffffu, l0, msk);
        l1 += __shfl_xor_sync(0xffffffffu, l1, msk);
    }

    // ---- phase 2: O = Ph Vh + Ph Vl + Pl Vh ----
    float o[8][4];
    #pragma unroll
    for (int j = 0; j < 8; j++)
        #pragma unroll
        for (int q = 0; q < 4; q++) o[j][q] = 0.f;

    #pragma unroll
    for (int kt = 0; kt < 16; kt++) {
        uint32_t pah[4], pal[4];
        #pragma unroll
        for (int half_ = 0; half_ < 2; half_++) {
            const float* sv = s[2 * kt + half_];
            const float p0 = sv[0], p1 = sv[1], p2 = sv[2], p3 = sv[3];
            const __half h0 = __float2half_rn(p0);
            const __half h1 = __float2half_rn(p1);
            const __half h2 = __float2half_rn(p2);
            const __half h3 = __float2half_rn(p3);
            pah[2 * half_ + 0] = pack_f16x2(__half2float(h0), __half2float(h1));
            pah[2 * half_ + 1] = pack_f16x2(__half2float(h2), __half2float(h3));
            pal[2 * half_ + 0] = pack_f16x2(p0 - __half2float(h0), p1 - __half2float(h1));
            pal[2 * half_ + 1] = pack_f16x2(p2 - __half2float(h2), p3 - __half2float(h3));
        }
        #pragma unroll
        for (int nd = 0; nd < 4; nd++) {
            uint32_t bh[4], bl[4];
            const uint32_t boff = SWZ512((uint32_t)((nd * 16 + brow) * 512 + kt * 32 + bcol));
            ldsm_x4(VHs + boff, bh);
            ldsm_x4(VLs + boff, bl);
            mma_f16(o[2 * nd],     pah, bh[0], bh[1]);
            mma_f16(o[2 * nd],     pah, bl[0], bl[1]);
            mma_f16(o[2 * nd],     pal, bh[0], bh[1]);
            mma_f16(o[2 * nd + 1], pah, bh[2], bh[3]);
            mma_f16(o[2 * nd + 1], pah, bl[2], bl[3]);
            mma_f16(o[2 * nd + 1], pal, bh[2], bh[3]);
        }
    }

    // ---- epilogue ----
    const float inv0 = 1.f / l0;
    const float inv1 = 1.f / l1;
    const size_t row0 = (size_t)blk * 256 + r0;
    #pragma unroll
    for (int j = 0; j < 8; j++) {
        const int col = h * 64 + j * 8 + cq;
        {
            const float v0 = o[j][0] * inv0;
            const float v1 = o[j][1] * inv0;
            const __half h0 = __float2half_rn(v0);
            const __half h1 = __float2half_rn(v1);
            *(__half2*)(CH + row0 * 1024 + col) = __halves2half2(h0, h1);
            *(__half2*)(CL + row0 * 1024 + col) = __halves2half2(
                __float2half_rn(v0 - __half2float(h0)),
                __float2half_rn(v1 - __half2float(h1)));
        }
        {
            const float v0 = o[j][2] * inv1;
            const float v1 = o[j][3] * inv1;
            const __half h0 = __float2half_rn(v0);
            const __half h1 = __float2half_rn(v1);
            *(__half2*)(CH + (row0 + 8) * 1024 + col) = __halves2half2(h0, h1);
            *(__half2*)(CL + (row0 + 8) * 1024 + col) = __halves2half2(
                __float2half_rn(v0 - __half2float(h0)),
                __float2half_rn(v1 - __half2float(h1)));
        }
    }
}

// =================== mean pool -> split fp16 directly ===================
__global__ void meanpool_hl_kernel(const float* __restrict__ x,
                                   __half* __restrict__ H, __half* __restrict__ L)
{
    const int blk = blockIdx.x;                 // 0..63
    const int c   = blockIdx.y * 256 + threadIdx.x;
    const float* base = x + (size_t)blk * BSZ * D_MODEL + c;
    float s = 0.f;
    #pragma unroll 4
    for (int r = 0; r < BSZ; r++) s += base[(size_t)r * D_MODEL];
    const float v = s * (1.0f / BSZ);
    const __half h = __float2half_rn(v);
    H[blk * D_MODEL + c] = h;
    L[blk * D_MODEL + c] = __float2half_rn(v - __half2float(h));
}

// =================== summary attention (fp32 in, split fp16 out) ===================
__global__ void summ_attn_kernel(
    const float* __restrict__ Q2, const float* __restrict__ K2,
    const float* __restrict__ V2,
    __half* __restrict__ SCH, __half* __restrict__ SCL)
{
    const int b = blockIdx.x;
    const int h = blockIdx.y;
    const int l = threadIdx.x;

    const float* qr = Q2 + (size_t)(b * 16 + l) * D_MODEL + h * DHEAD;
    float q[DHEAD];
    #pragma unroll
    for (int d = 0; d < DHEAD; d += 4) {
        const float4 v = *(const float4*)(qr + d);
        q[d] = v.x; q[d + 1] = v.y; q[d + 2] = v.z; q[d + 3] = v.w;
    }

    float s[16];
    float m = -1e30f;
    for (int j = 0; j < 16; j++) {
        const float* kr = K2 + (size_t)(b * 16 + j) * D_MODEL + h * DHEAD;
        float a = 0.f;
        #pragma unroll
        for (int d = 0; d < DHEAD; d += 4) {
            const float4 v = *(const float4*)(kr + d);
            a += q[d] * v.x + q[d + 1] * v.y + q[d + 2] * v.z + q[d + 3] * v.w;
        }
        s[j] = a * 0.125f;
        m = fmaxf(m, s[j]);
    }
    float lsum = 0.f;
    for (int j = 0; j < 16; j++) { s[j] = __expf(s[j] - m); lsum += s[j]; }
    const float inv = 1.f / lsum;

    float o[DHEAD];
    #pragma unroll
    for (int d = 0; d < DHEAD; d++) o[d] = 0.f;
    for (int j = 0; j < 16; j++) {
        const float* vr = V2 + (size_t)(b * 16 + j) * D_MODEL + h * DHEAD;
        const float p = s[j] * inv;
        #pragma unroll
        for (int d = 0; d < DHEAD; d += 4) {
            const float4 v = *(const float4*)(vr + d);
            o[d] += p * v.x; o[d + 1] += p * v.y; o[d + 2] += p * v.z; o[d + 3] += p * v.w;
        }
    }
    const size_t ob = (size_t)(b * 16 + l) * D_MODEL + h * DHEAD;
    #pragma unroll
    for (int d = 0; d < DHEAD; d += 2) {
        const __half h0 = __float2half_rn(o[d]);
        const __half h1 = __float2half_rn(o[d + 1]);
        *(__half2*)(SCH + ob + d) = __halves2half2(h0, h1);
        *(__half2*)(SCL + ob + d) = __halves2half2(
            __float2half_rn(o[d] - __half2float(h0)),
            __float2half_rn(o[d + 1] - __half2float(h1)));
    }
}

// =================== launch ===================
extern "C" void kernel_launch(void* const* d_in, const int* in_sizes, int n_in,
                              void* d_out, int out_size)
{
    const float* x     = (const float*)d_in[0];
    const float* lq_w  = (const float*)d_in[1];
    const float* lq_b  = (const float*)d_in[2];
    const float* lk_w  = (const float*)d_in[3];
    const float* lk_b  = (const float*)d_in[4];
    const float* lv_w  = (const float*)d_in[5];
    const float* lv_b  = (const float*)d_in[6];
    const float* lo_w  = (const float*)d_in[7];
    const float* lo_b  = (const float*)d_in[8];
    const float* pbias = (const float*)d_in[9];
    const float* sq_w  = (const float*)d_in[10];
    const float* sq_b  = (const float*)d_in[11];
    const float* sk_w  = (const float*)d_in[12];
    const float* sk_b  = (const float*)d_in[13];
    const float* sv_w  = (const float*)d_in[14];
    const float* sv_b  = (const float*)d_in[15];
    const float* so_w  = (const float*)d_in[16];
    const float* so_b  = (const float*)d_in[17];
    const float* sum_w = (const float*)d_in[18];
    const float* sum_b = (const float*)d_in[19];
    float* out = (float*)d_out;

    float *Q2, *K2, *V2, *SOUT, *PART;
    cudaGetSymbolAddress((void**)&Q2,   g_Q2);
    cudaGetSymbolAddress((void**)&K2,   g_K2);
    cudaGetSymbolAddress((void**)&V2,   g_V2);
    cudaGetSymbolAddress((void**)&SOUT, g_SOUT);
    cudaGetSymbolAddress((void**)&PART, g_PART);

    __half *XH, *QH, *QL, *KH, *KL, *VH, *VL, *VTH, *VTL, *CH, *CL, *WH, *WL;
    __half *S1H, *S1L, *S2H, *S2L, *S3H, *S3L;
    cudaGetSymbolAddress((void**)&XH, g_XH);
    cudaGetSymbolAddress((void**)&QH, g_QH);
    cudaGetSymbolAddress((void**)&QL, g_QL);
    cudaGetSymbolAddress((void**)&KH, g_KH);
    cudaGetSymbolAddress((void**)&KL, g_KL);
    cudaGetSymbolAddress((void**)&VH, g_VH);
    cudaGetSymbolAddress((void**)&VL, g_VL);
    cudaGetSymbolAddress((void**)&VTH, g_VTH);
    cudaGetSymbolAddress((void**)&VTL, g_VTL);
    cudaGetSymbolAddress((void**)&CH, g_CH);
    cudaGetSymbolAddress((void**)&CL, g_CL);
    cudaGetSymbolAddress((void**)&WH, g_WH);
    cudaGetSymbolAddress((void**)&WL, g_WL);
    cudaGetSymbolAddress((void**)&S1H, g_S1H);
    cudaGetSymbolAddress((void**)&S1L, g_S1L);
    cudaGetSymbolAddress((void**)&S2H, g_S2H);
    cudaGetSymbolAddress((void**)&S2L, g_S2L);
    cudaGetSymbolAddress((void**)&S3H, g_S3H);
    cudaGetSymbolAddress((void**)&S3L, g_S3L);

    // weight order: 0 lq, 1 lk, 2 lv (contiguous for fused QKV), 3 lo, 4 sum, 5 sq, 6 sk, 7 sv, 8 so
    WP9 wp;
    const float* ws[9] = {lq_w, lk_w, lv_w, lo_w, sum_w, sq_w, sk_w, sv_w, so_w};
    for (int i = 0; i < 9; i++) {
        wp.w[i] = ws[i];
        wp.h[i] = WH + (size_t)i * WSTRIDE;
        wp.l[i] = WL + (size_t)i * WSTRIDE;
    }

    cudaFuncSetAttribute(gemm_smallk_kernel,
                         cudaFuncAttributeMaxDynamicSharedMemorySize, GEMM3_SMEM);
    cudaFuncSetAttribute(gemm1_qkv_kernel,
                         cudaFuncAttributeMaxDynamicSharedMemorySize, GEMM1_SMEM);
    cudaFuncSetAttribute(gemm2_kernel,
                         cudaFuncAttributeMaxDynamicSharedMemorySize, GEMM2_SMEM);
    cudaFuncSetAttribute(attn_mma_kernel,
                         cudaFuncAttributeMaxDynamicSharedMemorySize, ATT_SMEM);

    // ---- prep ----
    prep_w_kernel<<<dim3(32, 32, 9), dim3(32, 8)>>>(wp);
    prep_act_h_kernel<<<16384, 256>>>((const float4*)x, XH, 4194304);

    // ---- small summary path (split-K latency-optimized) ----
    meanpool_hl_kernel<<<dim3(NBLK, 4), 256>>>(x, S1H, S1L);
    gemm_smallk_kernel<<<dim3(8, 1, 4), 256, GEMM3_SMEM>>>(S1H, S1L, WH, WL, 4, PART);
    reduce_hl_kernel<<<512, 256>>>(PART, sum_b, S2H, S2L);
    gemm_smallk_kernel<<<dim3(8, 3, 4), 256, GEMM3_SMEM>>>(S2H, S2L, WH, WL, 5, PART);
    reduce_fp32_kernel<<<256, 256>>>(PART + 0 * 4 * PART_STRIDE, sq_b, Q2);
    reduce_fp32_kernel<<<256, 256>>>(PART + 1 * 4 * PART_STRIDE, sk_b, K2);
    reduce_fp32_kernel<<<256, 256>>>(PART + 2 * 4 * PART_STRIDE, sv_b, V2);
    summ_attn_kernel<<<dim3(4, NHEAD), 16>>>(Q2, K2, V2, S3H, S3L);
    gemm_smallk_kernel<<<dim3(8, 1, 4), 256, GEMM3_SMEM>>>(S3H, S3L, WH, WL, 8, PART);
    reduce_fp32_kernel<<<256, 256>>>(PART, so_b, SOUT);

    // ---- local path: 1-term QKV, 3-term attention, 2-term o-proj ----
    gemm1_qkv_kernel<<<dim3(24, NTOK / 128), 256, GEMM1_SMEM>>>(
        XH, wp.h[0], lq_b, lk_b, lv_b,
        QH, QL, KH, KL, VH, VL);
    vtrans_kernel<<<dim3(NBLK, 16), 256>>>(VH, VL, VTH, VTL);
    attn_mma_kernel<<<dim3(NBLK, NHEAD), 512, ATT_SMEM>>>(
        QH, QL, KH, KL, VTH, VTL, pbias, CH, CL);
    gemm2_kernel<<<dim3(8, NTOK / 128), 256, GEMM2_SMEM>>>(
        CH, CL, wp.h[3], lo_b, SOUT, out);
}

// round 10
// speedup vs baseline: 1.9392x; 1.2232x over previous
#include <cuda_runtime.h>
#include <cuda_fp16.h>
#include <cstdint>

#define D_MODEL 1024
#define NHEAD   16
#define DHEAD   64
#define BSZ     256
#define NTOK    16384
#define NBLK    64
#define NELEM   ((size_t)NTOK * D_MODEL)
#define WSTRIDE (1024 * 1024)
#define PART_STRIDE (128 * 1024)

// ---------------- fp32 scratch (small path) ----------------
__device__ __align__(16) float g_Q2  [NBLK * D_MODEL];
__device__ __align__(16) float g_K2  [NBLK * D_MODEL];
__device__ __align__(16) float g_V2  [NBLK * D_MODEL];
__device__ __align__(16) float g_SOUT[NBLK * D_MODEL];
__device__ __align__(16) float g_PART[12 * PART_STRIDE];   // split-K partials

// ---------------- fp16 split scratch ----------------
__device__ __align__(16) __half g_XH[NELEM];
__device__ __align__(16) __half g_QH[NELEM];
__device__ __align__(16) __half g_QL[NELEM];
__device__ __align__(16) __half g_KH[NELEM];
__device__ __align__(16) __half g_KL[NELEM];
__device__ __align__(16) __half g_VH[NELEM];
__device__ __align__(16) __half g_VL[NELEM];
__device__ __align__(16) __half g_VTH[NELEM];   // [blk][dim][tok]
__device__ __align__(16) __half g_VTL[NELEM];
__device__ __align__(16) __half g_CH[NELEM];
__device__ __align__(16) __half g_WH[9][WSTRIDE];  // transposed [N][K] hi
__device__ __align__(16) __half g_WL[9][WSTRIDE];  // transposed [N][K] lo (3-term small path only)
// per-stage small activations (distinct buffers -> replay-deterministic)
__device__ __align__(16) __half g_S1H[128 * 1024];  // meanpool out
__device__ __align__(16) __half g_S1L[128 * 1024];
__device__ __align__(16) __half g_S2H[128 * 1024];  // summarizer out
__device__ __align__(16) __half g_S2L[128 * 1024];
__device__ __align__(16) __half g_S3H[128 * 1024];  // summ attention ctx
__device__ __align__(16) __half g_S3L[128 * 1024];

// =================== helpers ===================
__device__ __forceinline__ uint32_t smem_u32(const void* p) {
    uint32_t a;
    asm("{ .reg .u64 t; cvta.to.shared.u64 t, %1; cvt.u32.u64 %0, t; }" : "=r"(a) : "l"(p));
    return a;
}
#define SWZ128(off) ((off) ^ (((off) >> 3) & 0x70))
#define SWZ512(off) ((off) ^ (((off) >> 5) & 0x70))

__device__ __forceinline__ void cp16(uint32_t dst, const void* src) {
    asm volatile("cp.async.cg.shared.global [%0], [%1], 16;" :: "r"(dst), "l"(src));
}
__device__ __forceinline__ void cp_commit() {
    asm volatile("cp.async.commit_group;" ::: "memory");
}
__device__ __forceinline__ void ldsm_x4(uint32_t addr, uint32_t r[4]) {
    asm volatile("ldmatrix.sync.aligned.m8n8.x4.shared.b16 {%0,%1,%2,%3}, [%4];"
        : "=r"(r[0]), "=r"(r[1]), "=r"(r[2]), "=r"(r[3]) : "r"(addr));
}
__device__ __forceinline__ void mma_f16(float c[4], const uint32_t a[4],
                                        uint32_t b0, uint32_t b1) {
    asm volatile(
        "mma.sync.aligned.m16n8k16.row.col.f32.f16.f16.f32 "
        "{%0,%1,%2,%3}, {%4,%5,%6,%7}, {%8,%9}, {%0,%1,%2,%3};"
        : "+f"(c[0]), "+f"(c[1]), "+f"(c[2]), "+f"(c[3])
        : "r"(a[0]), "r"(a[1]), "r"(a[2]), "r"(a[3]), "r"(b0), "r"(b1));
}
__device__ __forceinline__ uint32_t pack_f16x2(float lo, float hi) {
    uint32_t r;
    asm("cvt.rn.f16x2.f32 %0, %1, %2;" : "=r"(r) : "f"(hi), "f"(lo));
    return r;
}

// =================== prep kernels ===================
// hi-only (1-term big GEMM inputs)
__global__ void prep_act_h_kernel(const float4* __restrict__ A,
                                  __half* __restrict__ H, int nquads)
{
    const int i = blockIdx.x * blockDim.x + threadIdx.x;
    if (i >= nquads) return;
    const float4 v = A[i];
    *(__half2*)(H + (size_t)i * 4)     = __halves2half2(__float2half_rn(v.x), __float2half_rn(v.y));
    *(__half2*)(H + (size_t)i * 4 + 2) = __halves2half2(__float2half_rn(v.z), __float2half_rn(v.w));
}

struct WP9 {
    const float* w[9];
    __half* h[9];
    __half* l[9];
};
__global__ void prep_w_kernel(WP9 wp)
{
    __shared__ float t[32][33];
    const int z  = blockIdx.z;
    const float* W = wp.w[z];
    __half* H = wp.h[z];
    __half* L = wp.l[z];
    const int bx = blockIdx.x;
    const int by = blockIdx.y;
    const int tx = threadIdx.x;
    const int ty = threadIdx.y;
    #pragma unroll
    for (int r = 0; r < 32; r += 8)
        t[ty + r][tx] = W[(size_t)(by * 32 + ty + r) * 1024 + bx * 32 + tx];
    __syncthreads();
    #pragma unroll
    for (int r = 0; r < 32; r += 8) {
        const float v = t[tx][ty + r];
        const __half h = __float2half_rn(v);
        const size_t o = (size_t)(bx * 32 + ty + r) * 1024 + by * 32 + tx;
        H[o] = h;
        if (z >= 4) L[o] = __float2half_rn(v - __half2float(h));  // lo only used by 3-term path
    }
}

// =================== fragment index helpers ===================
#define FRAG_IDX()                                                            \
    const int arow_in = (lane & 7) + ((lane >> 3) & 1) * 8;                   \
    const int acolx   = (lane >> 4) * 16;                                     \
    const int brow_in = (lane & 7) + ((lane >> 4) & 1) * 8;                   \
    const int bcolx   = ((lane >> 3) & 1) * 16;

#define BUF3_BYTES 65536
#define GEMM3_SMEM (2 * BUF3_BYTES)

#define ISSUE3(ic, buf) do {                                                  \
    const uint32_t sbase = sb + (buf) * BUF3_BYTES;                           \
    const size_t coff = (size_t)(ic) * 128 + cb;                              \
    _Pragma("unroll")                                                         \
    for (int i = 0; i < 4; i++) {                                             \
        const size_t go = (size_t)(rcp + i * 32) * 2048 + coff;               \
        cp16(sbase + dsw[i],          gAh + go);                              \
        cp16(sbase + 16384 + dsw[i],  gAl + go);                              \
        cp16(sbase + 32768 + dsw[i],  gBh + go);                              \
        cp16(sbase + 49152 + dsw[i],  gBl + go);                              \
    }                                                                         \
    cp_commit();                                                              \
} while (0)

// =================== split-K 3-term small GEMM -> fp32 partials ===================
__global__ __launch_bounds__(256, 1) void gemm_smallk_kernel(
    const __half* __restrict__ Ah, const __half* __restrict__ Al,
    const __half* __restrict__ WHb, const __half* __restrict__ WLb,
    int zbase, float* __restrict__ P)
{
    extern __shared__ char smem[];
    const uint32_t sb = smem_u32(smem);
    const int tid  = threadIdx.x;
    const int lane = tid & 31;
    const int wid  = tid >> 5;
    const int wm   = wid & 3;
    const int wn   = wid >> 2;
    const int bn = blockIdx.x;
    const int zi = blockIdx.y;
    const int ks = blockIdx.z;
    const int rcp = tid >> 3;
    const int cb  = (tid & 7) << 4;
    uint32_t dsw[4];
    #pragma unroll
    for (int i = 0; i < 4; i++) dsw[i] = SWZ128((uint32_t)((rcp + i * 32) * 128 + cb));
    FRAG_IDX();

    const char* gAh = (const char*)Ah;
    const char* gAl = (const char*)Al;
    const char* gBh = (const char*)(WHb + (size_t)(zbase + zi) * WSTRIDE + (size_t)bn * 128 * 1024);
    const char* gBl = (const char*)(WLb + (size_t)(zbase + zi) * WSTRIDE + (size_t)bn * 128 * 1024);

    float c[2][8][4];
    #pragma unroll
    for (int mt = 0; mt < 2; mt++)
        #pragma unroll
        for (int nb = 0; nb < 8; nb++)
            #pragma unroll
            for (int j = 0; j < 4; j++) c[mt][nb][j] = 0.f;

    const int ic0 = ks * 4;
    ISSUE3(ic0, 0);
    #pragma unroll 1
    for (int it = 0; it < 4; it++) {
        const int cur = it & 1;
        if (it < 3) ISSUE3(ic0 + it + 1, cur ^ 1);
        if (it < 3) asm volatile("cp.async.wait_group 1;" ::: "memory");
        else        asm volatile("cp.async.wait_group 0;" ::: "memory");
        __syncthreads();
        const uint32_t base = sb + cur * BUF3_BYTES;
        #pragma unroll
        for (int kk = 0; kk < 4; kk++) {
            const uint32_t kb = kk * 32;
            uint32_t ah[2][4], al_[2][4];
            #pragma unroll
            for (int mt = 0; mt < 2; mt++) {
                const uint32_t off =
                    SWZ128((uint32_t)((wm * 32 + mt * 16 + arow_in) * 128 + kb + acolx));
                ldsm_x4(base + off,          ah[mt]);
                ldsm_x4(base + 16384 + off,  al_[mt]);
            }
            uint32_t bh[4][4], bl[4][4];
            #pragma unroll
            for (int p = 0; p < 4; p++) {
                const uint32_t off =
                    SWZ128((uint32_t)((wn * 64 + p * 16 + brow_in) * 128 + kb + bcolx));
                ldsm_x4(base + 32768 + off, bh[p]);
                ldsm_x4(base + 49152 + off, bl[p]);
            }
            #pragma unroll
            for (int mt = 0; mt < 2; mt++) {
                #pragma unroll
                for (int p = 0; p < 4; p++) {
                    mma_f16(c[mt][2 * p],     ah[mt],  bh[p][0], bh[p][1]);
                    mma_f16(c[mt][2 * p],     ah[mt],  bl[p][0], bl[p][1]);
                    mma_f16(c[mt][2 * p],     al_[mt], bh[p][0], bh[p][1]);
                    mma_f16(c[mt][2 * p + 1], ah[mt],  bh[p][2], bh[p][3]);
                    mma_f16(c[mt][2 * p + 1], ah[mt],  bl[p][2], bl[p][3]);
                    mma_f16(c[mt][2 * p + 1], al_[mt], bh[p][2], bh[p][3]);
                }
            }
        }
        __syncthreads();
    }

    float* Pp = P + (size_t)(zi * 4 + ks) * PART_STRIDE;
    const int row_base = wm * 32 + (lane >> 2);
    const int col_base = bn * 128 + wn * 64 + 2 * (lane & 3);
    #pragma unroll
    for (int mt = 0; mt < 2; mt++) {
        #pragma unroll
        for (int hh = 0; hh < 2; hh++) {
            const int row = row_base + mt * 16 + hh * 8;
            #pragma unroll
            for (int nb = 0; nb < 8; nb++) {
                const int col = col_base + nb * 8;
                float2 o;
                o.x = c[mt][nb][hh * 2 + 0];
                o.y = c[mt][nb][hh * 2 + 1];
                *(float2*)(Pp + (size_t)row * 1024 + col) = o;
            }
        }
    }
}

// ---- reduce 4 partials + bias -> fp32 (grid 256: rows 0..63 only) ----
__global__ void reduce_fp32_kernel(const float* __restrict__ P,
                                   const float* __restrict__ bias,
                                   float* __restrict__ C)
{
    const int idx = blockIdx.x * 256 + threadIdx.x;
    const float s = P[idx] + P[idx + PART_STRIDE] + P[idx + 2 * PART_STRIDE] + P[idx + 3 * PART_STRIDE];
    C[idx] = s + bias[idx & 1023];
}

// ---- reduce 4 partials + bias -> split fp16 (grid 512: all 128 rows) ----
__global__ void reduce_hl_kernel(const float* __restrict__ P,
                                 const float* __restrict__ bias,
                                 __half* __restrict__ H, __half* __restrict__ L)
{
    const int idx = blockIdx.x * 256 + threadIdx.x;
    const float v = P[idx] + P[idx + PART_STRIDE] + P[idx + 2 * PART_STRIDE] + P[idx + 3 * PART_STRIDE]
                  + bias[idx & 1023];
    const __half h = __float2half_rn(v);
    H[idx] = h;
    L[idx] = __float2half_rn(v - __half2float(h));
}

// =================== 1-term GEMM mainloop (big path): C ~= Ah * Bh ===================
#define BUF1_BYTES 32768
#define GEMM1_SMEM (2 * BUF1_BYTES)

#define ISSUE1(ic, buf) do {                                                  \
    const uint32_t sbase = sb + (buf) * BUF1_BYTES;                           \
    const size_t coff = (size_t)(ic) * 128 + cb;                              \
    _Pragma("unroll")                                                         \
    for (int i = 0; i < 4; i++) {                                             \
        const size_t go = (size_t)(rcp + i * 32) * 2048 + coff;               \
        cp16(sbase + dsw[i],          gAh + go);                              \
        cp16(sbase + 16384 + dsw[i],  gBh + go);                              \
    }                                                                         \
    cp_commit();                                                              \
} while (0)

#define GEMM1_BODY()                                                          \
    extern __shared__ char smem[];                                            \
    const uint32_t sb = smem_u32(smem);                                       \
    const int tid  = threadIdx.x;                                             \
    const int lane = tid & 31;                                                \
    const int wid  = tid >> 5;                                                \
    const int wm   = wid & 3;                                                 \
    const int wn   = wid >> 2;                                                \
    const int bn = blockIdx.x;                                                \
    const int bm = blockIdx.y;                                                \
    const int rcp = tid >> 3;                                                 \
    const int cb  = (tid & 7) << 4;                                           \
    uint32_t dsw[4];                                                          \
    _Pragma("unroll")                                                         \
    for (int i = 0; i < 4; i++) dsw[i] = SWZ128((uint32_t)((rcp + i * 32) * 128 + cb)); \
    FRAG_IDX();                                                               \
    float c[2][8][4];                                                         \
    _Pragma("unroll")                                                         \
    for (int mt = 0; mt < 2; mt++)                                            \
        _Pragma("unroll")                                                     \
        for (int nb = 0; nb < 8; nb++)                                        \
            _Pragma("unroll")                                                 \
            for (int j = 0; j < 4; j++) c[mt][nb][j] = 0.f;                   \
    ISSUE1(0, 0);                                                             \
    _Pragma("unroll 1")                                                       \
    for (int ic = 0; ic < 16; ic++) {                                         \
        const int cur = ic & 1;                                               \
        if (ic < 15) ISSUE1(ic + 1, cur ^ 1);                                 \
        if (ic < 15) asm volatile("cp.async.wait_group 1;" ::: "memory");     \
        else         asm volatile("cp.async.wait_group 0;" ::: "memory");     \
        __syncthreads();                                                      \
        const uint32_t base = sb + cur * BUF1_BYTES;                          \
        _Pragma("unroll")                                                     \
        for (int kk = 0; kk < 4; kk++) {                                      \
            const uint32_t kb = kk * 32;                                      \
            uint32_t ah[2][4];                                                \
            _Pragma("unroll")                                                 \
            for (int mt = 0; mt < 2; mt++) {                                  \
                const uint32_t off =                                          \
                    SWZ128((uint32_t)((wm * 32 + mt * 16 + arow_in) * 128 + kb + acolx)); \
                ldsm_x4(base + off, ah[mt]);                                  \
            }                                                                 \
            uint32_t bh[4][4];                                                \
            _Pragma("unroll")                                                 \
            for (int p = 0; p < 4; p++) {                                     \
                const uint32_t off =                                          \
                    SWZ128((uint32_t)((wn * 64 + p * 16 + brow_in) * 128 + kb + bcolx)); \
                ldsm_x4(base + 16384 + off, bh[p]);                           \
            }                                                                 \
            _Pragma("unroll")                                                 \
            for (int mt = 0; mt < 2; mt++) {                                  \
                _Pragma("unroll")                                             \
                for (int p = 0; p < 4; p++) {                                 \
                    mma_f16(c[mt][2 * p],     ah[mt], bh[p][0], bh[p][1]);    \
                    mma_f16(c[mt][2 * p + 1], ah[mt], bh[p][2], bh[p][3]);    \
                }                                                             \
            }                                                                 \
        }                                                                     \
        __syncthreads();                                                      \
    }

// ---- fused QKV: 1-term fp16, split-fp16 out ----
__global__ __launch_bounds__(256, 2) void gemm1_qkv_kernel(
    const __half* __restrict__ Ah, const __half* __restrict__ Bh,
    const float* __restrict__ bq, const float* __restrict__ bk, const float* __restrict__ bv,
    __half* __restrict__ QH, __half* __restrict__ QL,
    __half* __restrict__ KH, __half* __restrict__ KL,
    __half* __restrict__ VH, __half* __restrict__ VL)
{
    const char* gAh = (const char*)(Ah + (size_t)(blockIdx.y * 128) * 1024);
    const char* gBh = (const char*)(Bh + (size_t)(blockIdx.x * 128) * 1024);
    GEMM1_BODY();

    const int tensor = bn >> 3;
    const float* bias = (tensor == 0) ? bq : (tensor == 1) ? bk : bv;
    __half* OH = (tensor == 0) ? QH : (tensor == 1) ? KH : VH;
    __half* OL = (tensor == 0) ? QL : (tensor == 1) ? KL : VL;

    const int row_base = bm * 128 + wm * 32 + (lane >> 2);
    const int col_base = (bn & 7) * 128 + wn * 64 + 2 * (lane & 3);
    #pragma unroll
    for (int mt = 0; mt < 2; mt++) {
        #pragma unroll
        for (int hh = 0; hh < 2; hh++) {
            const int row = row_base + mt * 16 + hh * 8;
            #pragma unroll
            for (int nb = 0; nb < 8; nb++) {
                const int col = col_base + nb * 8;
                const float v0 = c[mt][nb][hh * 2 + 0] + bias[col + 0];
                const float v1 = c[mt][nb][hh * 2 + 1] + bias[col + 1];
                const __half h0 = __float2half_rn(v0);
                const __half h1 = __float2half_rn(v1);
                *(__half2*)(OH + (size_t)row * 1024 + col) = __halves2half2(h0, h1);
                *(__half2*)(OL + (size_t)row * 1024 + col) = __halves2half2(
                    __float2half_rn(v0 - __half2float(h0)),
                    __float2half_rn(v1 - __half2float(h1)));
            }
        }
    }
}

// ---- o-proj: 1-term fp16, fp32 out + bias + summary add ----
__global__ __launch_bounds__(256, 2) void gemm1_oproj_kernel(
    const __half* __restrict__ Ah, const __half* __restrict__ Bh,
    const float* __restrict__ bias, const float* __restrict__ addBlk,
    float* __restrict__ C)
{
    const char* gAh = (const char*)(Ah + (size_t)(blockIdx.y * 128) * 1024);
    const char* gBh = (const char*)(Bh + (size_t)(blockIdx.x * 128) * 1024);
    GEMM1_BODY();

    const int row_base = bm * 128 + wm * 32 + (lane >> 2);
    const int col_base = bn * 128 + wn * 64 + 2 * (lane & 3);
    #pragma unroll
    for (int mt = 0; mt < 2; mt++) {
        #pragma unroll
        for (int hh = 0; hh < 2; hh++) {
            const int row = row_base + mt * 16 + hh * 8;
            const int rb = row >> 8;
            #pragma unroll
            for (int nb = 0; nb < 8; nb++) {
                const int col = col_base + nb * 8;
                float2 o;
                o.x = c[mt][nb][hh * 2 + 0] + bias[col + 0] + addBlk[(size_t)rb * 1024 + col + 0];
                o.y = c[mt][nb][hh * 2 + 1] + bias[col + 1] + addBlk[(size_t)rb * 1024 + col + 1];
                *(float2*)(C + (size_t)row * 1024 + col) = o;
            }
        }
    }
}

// =================== V transpose: [tok][dim] -> [blk][dim][tok] ===================
__global__ __launch_bounds__(256) void vtrans_kernel(
    const __half* __restrict__ VH, const __half* __restrict__ VL,
    __half* __restrict__ VTH, __half* __restrict__ VTL)
{
    __shared__ __half t[256][72];
    const int blk = blockIdx.x;
    const int dt  = blockIdx.y;
    const int tid = threadIdx.x;
    #pragma unroll 1
    for (int pass = 0; pass < 2; pass++) {
        const __half* src = pass ? VL : VH;
        __half* dst = pass ? VTL : VTH;
        #pragma unroll
        for (int it = 0; it < 8; it++) {
            const int task = it * 256 + tid;
            const int row = task >> 3;
            const int dc  = (task & 7) * 8;
            *(uint4*)&t[row][dc] =
                *(const uint4*)(src + ((size_t)(blk * 256 + row)) * 1024 + dt * 64 + dc);
        }
        __syncthreads();
        #pragma unroll
        for (int it = 0; it < 8; it++) {
            const int task = it * 256 + tid;
            const int d  = task >> 5;
            const int tc = (task & 31) * 8;
            __half tmp[8];
            #pragma unroll
            for (int j = 0; j < 8; j++) tmp[j] = t[tc + j][d];
            *(uint4*)(dst + ((size_t)(blk * 1024) + dt * 64 + d) * 256 + tc) = *(uint4*)tmp;
        }
        __syncthreads();
    }
}

// =================== HMMA local attention (3-term fp16, hi-only ctx out) ===================
#define ATT_SMEM (6 * 32768)

__global__ __launch_bounds__(512, 1) void attn_mma_kernel(
    const __half* __restrict__ QH, const __half* __restrict__ QL,
    const __half* __restrict__ KH, const __half* __restrict__ KL,
    const __half* __restrict__ VTH, const __half* __restrict__ VTL,
    const float* __restrict__ bias,
    __half* __restrict__ CH)
{
    extern __shared__ char smem[];
    const uint32_t sb = smem_u32(smem);
    const int blk = blockIdx.x;
    const int h   = blockIdx.y;
    const int tid = threadIdx.x;
    const int lane = tid & 31;
    const int w    = tid >> 5;

    const uint32_t QHs = sb;
    const uint32_t QLs = sb + 32768;
    const uint32_t KHs = sb + 65536;
    const uint32_t KLs = sb + 98304;
    const uint32_t VHs = sb + 131072;
    const uint32_t VLs = sb + 163840;

    {
        const char* qh0 = (const char*)(QH + ((size_t)blk * 256) * 1024 + h * 64);
        const char* ql0 = (const char*)(QL + ((size_t)blk * 256) * 1024 + h * 64);
        const char* kh0 = (const char*)(KH + ((size_t)blk * 256) * 1024 + h * 64);
        const char* kl0 = (const char*)(KL + ((size_t)blk * 256) * 1024 + h * 64);
        #pragma unroll
        for (int i = 0; i < 4; i++) {
            const int cidx = tid + i * 512;
            const int row = cidx >> 3;
            const int cbo = (cidx & 7) << 4;
            const uint32_t d = SWZ128((uint32_t)(row * 128 + cbo));
            const size_t go = (size_t)row * 2048 + cbo;
            cp16(QHs + d, qh0 + go);
            cp16(QLs + d, ql0 + go);
            cp16(KHs + d, kh0 + go);
            cp16(KLs + d, kl0 + go);
        }
        const char* vh0 = (const char*)(VTH + ((size_t)blk * 1024 + h * 64) * 256);
        const char* vl0 = (const char*)(VTL + ((size_t)blk * 1024 + h * 64) * 256);
        #pragma unroll
        for (int i = 0; i < 4; i++) {
            const int cidx = tid + i * 512;
            const int row = cidx >> 5;
            const int cbo = (cidx & 31) << 4;
            const uint32_t d = SWZ512((uint32_t)(row * 512 + cbo));
            const size_t go = (size_t)row * 512 + cbo;
            cp16(VHs + d, vh0 + go);
            cp16(VLs + d, vl0 + go);
        }
        cp_commit();
        asm volatile("cp.async.wait_group 0;" ::: "memory");
        __syncthreads();
    }

    const int arow = (lane & 7) + ((lane >> 3) & 1) * 8;
    const int acol = (lane >> 4) * 16;
    const int brow = (lane & 7) + ((lane >> 4) & 1) * 8;
    const int bcol = ((lane >> 3) & 1) * 16;

    // ---- phase 1: S = Qh Kh^T + Qh Kl^T + Ql Kh^T ----
    float s[32][4];
    #pragma unroll
    for (int j = 0; j < 32; j++)
        #pragma unroll
        for (int q = 0; q < 4; q++) s[j][q] = 0.f;

    #pragma unroll
    for (int kk = 0; kk < 4; kk++) {
        const uint32_t kb = kk * 32;
        uint32_t qh[4], ql[4];
        const uint32_t aoff = SWZ128((uint32_t)((w * 16 + arow) * 128 + kb + acol));
        ldsm_x4(QHs + aoff, qh);
        ldsm_x4(QLs + aoff, ql);
        #pragma unroll
        for (int p = 0; p < 16; p++) {
            uint32_t bh[4], bl[4];
            const uint32_t boff = SWZ128((uint32_t)((p * 16 + brow) * 128 + kb + bcol));
            ldsm_x4(KHs + boff, bh);
            ldsm_x4(KLs + boff, bl);
            mma_f16(s[2 * p],     qh, bh[0], bh[1]);
            mma_f16(s[2 * p],     qh, bl[0], bl[1]);
            mma_f16(s[2 * p],     ql, bh[0], bh[1]);
            mma_f16(s[2 * p + 1], qh, bh[2], bh[3]);
            mma_f16(s[2 * p + 1], qh, bl[2], bl[3]);
            mma_f16(s[2 * p + 1], ql, bh[2], bh[3]);
        }
    }

    // ---- softmax ----
    const int r0 = w * 16 + (lane >> 2);
    const int cq = (lane & 3) * 2;
    const float* br0 = bias + ((size_t)h * 256 + r0) * 256;
    const float* br1 = br0 + 8 * 256;

    float m0 = -1e30f, m1 = -1e30f;
    #pragma unroll
    for (int j = 0; j < 32; j++) {
        const float2 b0 = *(const float2*)(br0 + j * 8 + cq);
        const float2 b1 = *(const float2*)(br1 + j * 8 + cq);
        s[j][0] = s[j][0] * 0.125f + b0.x;
        s[j][1] = s[j][1] * 0.125f + b0.y;
        s[j][2] = s[j][2] * 0.125f + b1.x;
        s[j][3] = s[j][3] * 0.125f + b1.y;
        m0 = fmaxf(m0, fmaxf(s[j][0], s[j][1]));
        m1 = fmaxf(m1, fmaxf(s[j][2], s[j][3]));
    }
    #pragma unroll
    for (int msk = 1; msk <= 2; msk <<= 1) {
        m0 = fmaxf(m0, __shfl_xor_sync(0xffffffffu, m0, msk));
        m1 = fmaxf(m1, __shfl_xor_sync(0xffffffffu, m1, msk));
    }
    float l0 = 0.f, l1 = 0.f;
    #pragma unroll
    for (int j = 0; j < 32; j++) {
        s[j][0] = __expf(s[j][0] - m0);
        s[j][1] = __expf(s[j][1] - m0);
        s[j][2] = __expf(s[j][2] - m1);
        s[j][3] = __expf(s[j][3] - m1);
        l0 += s[j][0] + s[j][1];
        l1 += s[j][2] + s[j][3];
    }
    #pragma unroll
    for (int msk = 1; msk <= 2; msk <<= 1) {
        l0 += __shfl_xor_sync(0xffffffffu, l0, msk);
        l1 += __shfl_xor_sync(0xffffffffu, l1, msk);
    }

    // ---- phase 2: O = Ph Vh + Ph Vl + Pl Vh ----
    float o[8][4];
    #pragma unroll
    for (int j = 0; j < 8; j++)
        #pragma unroll
        for (int q = 0; q < 4; q++) o[j][q] = 0.f;

    #pragma unroll
    for (int kt = 0; kt < 16; kt++) {
        uint32_t pah[4], pal[4];
        #pragma unroll
        for (int half_ = 0; half_ < 2; half_++) {
            const float* sv = s[2 * kt + half_];
            const float p0 = sv[0], p1 = sv[1], p2 = sv[2], p3 = sv[3];
            const __half h0 = __float2half_rn(p0);
            const __half h1 = __float2half_rn(p1);
            const __half h2 = __float2half_rn(p2);
            const __half h3 = __float2half_rn(p3);
            pah[2 * half_ + 0] = pack_f16x2(__half2float(h0), __half2float(h1));
            pah[2 * half_ + 1] = pack_f16x2(__half2float(h2), __half2float(h3));
            pal[2 * half_ + 0] = pack_f16x2(p0 - __half2float(h0), p1 - __half2float(h1));
            pal[2 * half_ + 1] = pack_f16x2(p2 - __half2float(h2), p3 - __half2float(h3));
        }
        #pragma unroll
        for (int nd = 0; nd < 4; nd++) {
            uint32_t bh[4], bl[4];
            const uint32_t boff = SWZ512((uint32_t)((nd * 16 + brow) * 512 + kt * 32 + bcol));
            ldsm_x4(VHs + boff, bh);
            ldsm_x4(VLs + boff, bl);
            mma_f16(o[2 * nd],     pah, bh[0], bh[1]);
            mma_f16(o[2 * nd],     pah, bl[0], bl[1]);
            mma_f16(o[2 * nd],     pal, bh[0], bh[1]);
            mma_f16(o[2 * nd + 1], pah, bh[2], bh[3]);
            mma_f16(o[2 * nd + 1], pah, bl[2], bl[3]);
            mma_f16(o[2 * nd + 1], pal, bh[2], bh[3]);
        }
    }

    // ---- epilogue (hi-only: o-proj is 1-term) ----
    const float inv0 = 1.f / l0;
    const float inv1 = 1.f / l1;
    const size_t row0 = (size_t)blk * 256 + r0;
    #pragma unroll
    for (int j = 0; j < 8; j++) {
        const int col = h * 64 + j * 8 + cq;
        *(__half2*)(CH + row0 * 1024 + col) = __halves2half2(
            __float2half_rn(o[j][0] * inv0), __float2half_rn(o[j][1] * inv0));
        *(__half2*)(CH + (row0 + 8) * 1024 + col) = __halves2half2(
            __float2half_rn(o[j][2] * inv1), __float2half_rn(o[j][3] * inv1));
    }
}

// =================== mean pool -> split fp16 directly ===================
__global__ void meanpool_hl_kernel(const float* __restrict__ x,
                                   __half* __restrict__ H, __half* __restrict__ L)
{
    const int blk = blockIdx.x;                 // 0..63
    const int c   = blockIdx.y * 256 + threadIdx.x;
    const float* base = x + (size_t)blk * BSZ * D_MODEL + c;
    float s = 0.f;
    #pragma unroll 4
    for (int r = 0; r < BSZ; r++) s += base[(size_t)r * D_MODEL];
    const float v = s * (1.0f / BSZ);
    const __half h = __float2half_rn(v);
    H[blk * D_MODEL + c] = h;
    L[blk * D_MODEL + c] = __float2half_rn(v - __half2float(h));
}

// =================== summary attention (fp32 in, split fp16 out) ===================
__global__ void summ_attn_kernel(
    const float* __restrict__ Q2, const float* __restrict__ K2,
    const float* __restrict__ V2,
    __half* __restrict__ SCH, __half* __restrict__ SCL)
{
    const int b = blockIdx.x;
    const int h = blockIdx.y;
    const int l = threadIdx.x;

    const float* qr = Q2 + (size_t)(b * 16 + l) * D_MODEL + h * DHEAD;
    float q[DHEAD];
    #pragma unroll
    for (int d = 0; d < DHEAD; d += 4) {
        const float4 v = *(const float4*)(qr + d);
        q[d] = v.x; q[d + 1] = v.y; q[d + 2] = v.z; q[d + 3] = v.w;
    }

    float s[16];
    float m = -1e30f;
    for (int j = 0; j < 16; j++) {
        const float* kr = K2 + (size_t)(b * 16 + j) * D_MODEL + h * DHEAD;
        float a = 0.f;
        #pragma unroll
        for (int d = 0; d < DHEAD; d += 4) {
            const float4 v = *(const float4*)(kr + d);
            a += q[d] * v.x + q[d + 1] * v.y + q[d + 2] * v.z + q[d + 3] * v.w;
        }
        s[j] = a * 0.125f;
        m = fmaxf(m, s[j]);
    }
    float lsum = 0.f;
    for (int j = 0; j < 16; j++) { s[j] = __expf(s[j] - m); lsum += s[j]; }
    const float inv = 1.f / lsum;

    float o[DHEAD];
    #pragma unroll
    for (int d = 0; d < DHEAD; d++) o[d] = 0.f;
    for (int j = 0; j < 16; j++) {
        const float* vr = V2 + (size_t)(b * 16 + j) * D_MODEL + h * DHEAD;
        const float p = s[j] * inv;
        #pragma unroll
        for (int d = 0; d < DHEAD; d += 4) {
            const float4 v = *(const float4*)(vr + d);
            o[d] += p * v.x; o[d + 1] += p * v.y; o[d + 2] += p * v.z; o[d + 3] += p * v.w;
        }
    }
    const size_t ob = (size_t)(b * 16 + l) * D_MODEL + h * DHEAD;
    #pragma unroll
    for (int d = 0; d < DHEAD; d += 2) {
        const __half h0 = __float2half_rn(o[d]);
        const __half h1 = __float2half_rn(o[d + 1]);
        *(__half2*)(SCH + ob + d) = __halves2half2(h0, h1);
        *(__half2*)(SCL + ob + d) = __halves2half2(
            __float2half_rn(o[d] - __half2float(h0)),
            __float2half_rn(o[d + 1] - __half2float(h1)));
    }
}

// =================== launch ===================
extern "C" void kernel_launch(void* const* d_in, const int* in_sizes, int n_in,
                              void* d_out, int out_size)
{
    const float* x     = (const float*)d_in[0];
    const float* lq_w  = (const float*)d_in[1];
    const float* lq_b  = (const float*)d_in[2];
    const float* lk_w  = (const float*)d_in[3];
    const float* lk_b  = (const float*)d_in[4];
    const float* lv_w  = (const float*)d_in[5];
    const float* lv_b  = (const float*)d_in[6];
    const float* lo_w  = (const float*)d_in[7];
    const float* lo_b  = (const float*)d_in[8];
    const float* pbias = (const float*)d_in[9];
    const float* sq_w  = (const float*)d_in[10];
    const float* sq_b  = (const float*)d_in[11];
    const float* sk_w  = (const float*)d_in[12];
    const float* sk_b  = (const float*)d_in[13];
    const float* sv_w  = (const float*)d_in[14];
    const float* sv_b  = (const float*)d_in[15];
    const float* so_w  = (const float*)d_in[16];
    const float* so_b  = (const float*)d_in[17];
    const float* sum_w = (const float*)d_in[18];
    const float* sum_b = (const float*)d_in[19];
    float* out = (float*)d_out;

    float *Q2, *K2, *V2, *SOUT, *PART;
    cudaGetSymbolAddress((void**)&Q2,   g_Q2);
    cudaGetSymbolAddress((void**)&K2,   g_K2);
    cudaGetSymbolAddress((void**)&V2,   g_V2);
    cudaGetSymbolAddress((void**)&SOUT, g_SOUT);
    cudaGetSymbolAddress((void**)&PART, g_PART);

    __half *XH, *QH, *QL, *KH, *KL, *VH, *VL, *VTH, *VTL, *CH, *WH, *WL;
    __half *S1H, *S1L, *S2H, *S2L, *S3H, *S3L;
    cudaGetSymbolAddress((void**)&XH, g_XH);
    cudaGetSymbolAddress((void**)&QH, g_QH);
    cudaGetSymbolAddress((void**)&QL, g_QL);
    cudaGetSymbolAddress((void**)&KH, g_KH);
    cudaGetSymbolAddress((void**)&KL, g_KL);
    cudaGetSymbolAddress((void**)&VH, g_VH);
    cudaGetSymbolAddress((void**)&VL, g_VL);
    cudaGetSymbolAddress((void**)&VTH, g_VTH);
    cudaGetSymbolAddress((void**)&VTL, g_VTL);
    cudaGetSymbolAddress((void**)&CH, g_CH);
    cudaGetSymbolAddress((void**)&WH, g_WH);
    cudaGetSymbolAddress((void**)&WL, g_WL);
    cudaGetSymbolAddress((void**)&S1H, g_S1H);
    cudaGetSymbolAddress((void**)&S1L, g_S1L);
    cudaGetSymbolAddress((void**)&S2H, g_S2H);
    cudaGetSymbolAddress((void**)&S2L, g_S2L);
    cudaGetSymbolAddress((void**)&S3H, g_S3H);
    cudaGetSymbolAddress((void**)&S3L, g_S3L);

    // weight order: 0 lq, 1 lk, 2 lv (contiguous for fused QKV), 3 lo, 4 sum, 5 sq, 6 sk, 7 sv, 8 so
    WP9 wp;
    const float* ws[9] = {lq_w, lk_w, lv_w, lo_w, sum_w, sq_w, sk_w, sv_w, so_w};
    for (int i = 0; i < 9; i++) {
        wp.w[i] = ws[i];
        wp.h[i] = WH + (size_t)i * WSTRIDE;
        wp.l[i] = WL + (size_t)i * WSTRIDE;
    }

    cudaFuncSetAttribute(gemm_smallk_kernel,
                         cudaFuncAttributeMaxDynamicSharedMemorySize, GEMM3_SMEM);
    cudaFuncSetAttribute(gemm1_qkv_kernel,
                         cudaFuncAttributeMaxDynamicSharedMemorySize, GEMM1_SMEM);
    cudaFuncSetAttribute(gemm1_oproj_kernel,
                         cudaFuncAttributeMaxDynamicSharedMemorySize, GEMM1_SMEM);
    cudaFuncSetAttribute(attn_mma_kernel,
                         cudaFuncAttributeMaxDynamicSharedMemorySize, ATT_SMEM);

    // ---- prep ----
    prep_w_kernel<<<dim3(32, 32, 9), dim3(32, 8)>>>(wp);
    prep_act_h_kernel<<<16384, 256>>>((const float4*)x, XH, 4194304);

    // ---- small summary path (split-K latency-optimized, 3-term) ----
    meanpool_hl_kernel<<<dim3(NBLK, 4), 256>>>(x, S1H, S1L);
    gemm_smallk_kernel<<<dim3(8, 1, 4), 256, GEMM3_SMEM>>>(S1H, S1L, WH, WL, 4, PART);
    reduce_hl_kernel<<<512, 256>>>(PART, sum_b, S2H, S2L);
    gemm_smallk_kernel<<<dim3(8, 3, 4), 256, GEMM3_SMEM>>>(S2H, S2L, WH, WL, 5, PART);
    reduce_fp32_kernel<<<256, 256>>>(PART + 0 * 4 * PART_STRIDE, sq_b, Q2);
    reduce_fp32_kernel<<<256, 256>>>(PART + 1 * 4 * PART_STRIDE, sk_b, K2);
    reduce_fp32_kernel<<<256, 256>>>(PART + 2 * 4 * PART_STRIDE, sv_b, V2);
    summ_attn_kernel<<<dim3(4, NHEAD), 16>>>(Q2, K2, V2, S3H, S3L);
    gemm_smallk_kernel<<<dim3(8, 1, 4), 256, GEMM3_SMEM>>>(S3H, S3L, WH, WL, 8, PART);
    reduce_fp32_kernel<<<256, 256>>>(PART, so_b, SOUT);

    // ---- local path: 1-term QKV, 3-term attention, 1-term o-proj ----
    gemm1_qkv_kernel<<<dim3(24, NTOK / 128), 256, GEMM1_SMEM>>>(
        XH, wp.h[0], lq_b, lk_b, lv_b,
        QH, QL, KH, KL, VH, VL);
    vtrans_kernel<<<dim3(NBLK, 16), 256>>>(VH, VL, VTH, VTL);
    attn_mma_kernel<<<dim3(NBLK, NHEAD), 512, ATT_SMEM>>>(
        QH, QL, KH, KL, VTH, VTL, pbias, CH);
    gemm1_oproj_kernel<<<dim3(8, NTOK / 128), 256, GEMM1_SMEM>>>(
        CH, wp.h[3], lo_b, SOUT, out);
}

// round 11
// speedup vs baseline: 2.1561x; 1.1118x over previous
#include <cuda_runtime.h>
#include <cuda_fp16.h>
#include <cstdint>

#define D_MODEL 1024
#define NHEAD   16
#define DHEAD   64
#define BSZ     256
#define NTOK    16384
#define NBLK    64
#define NELEM   ((size_t)NTOK * D_MODEL)
#define WSTRIDE (1024 * 1024)
#define PART_STRIDE (128 * 1024)

// ---------------- fp32 scratch (small path) ----------------
__device__ __align__(16) float g_QKV2[3 * NBLK * D_MODEL];   // Q2|K2|V2
__device__ __align__(16) float g_SOUT[NBLK * D_MODEL];
__device__ __align__(16) float g_PART[12 * PART_STRIDE];     // split-K partials

// ---------------- fp16 split scratch ----------------
__device__ __align__(16) __half g_XH[NELEM];
__device__ __align__(16) __half g_QH[NELEM];
__device__ __align__(16) __half g_QL[NELEM];
__device__ __align__(16) __half g_KH[NELEM];
__device__ __align__(16) __half g_KL[NELEM];
__device__ __align__(16) __half g_VH[NELEM];
__device__ __align__(16) __half g_VL[NELEM];
__device__ __align__(16) __half g_VTH[NELEM];   // [blk][dim][tok]
__device__ __align__(16) __half g_VTL[NELEM];
__device__ __align__(16) __half g_CH[NELEM];
__device__ __align__(16) __half g_WH[9][WSTRIDE];  // transposed [N][K] hi
__device__ __align__(16) __half g_WL[9][WSTRIDE];  // transposed [N][K] lo (3-term small path only)
// per-stage small activations (distinct buffers -> replay-deterministic)
__device__ __align__(16) __half g_S1H[128 * 1024];
__device__ __align__(16) __half g_S1L[128 * 1024];
__device__ __align__(16) __half g_S2H[128 * 1024];
__device__ __align__(16) __half g_S2L[128 * 1024];
__device__ __align__(16) __half g_S3H[128 * 1024];
__device__ __align__(16) __half g_S3L[128 * 1024];

// =================== helpers ===================
__device__ __forceinline__ uint32_t smem_u32(const void* p) {
    uint32_t a;
    asm("{ .reg .u64 t; cvta.to.shared.u64 t, %1; cvt.u32.u64 %0, t; }" : "=r"(a) : "l"(p));
    return a;
}
#define SWZ128(off) ((off) ^ (((off) >> 3) & 0x70))
#define SWZ512(off) ((off) ^ (((off) >> 5) & 0x70))

__device__ __forceinline__ void cp16(uint32_t dst, const void* src) {
    asm volatile("cp.async.cg.shared.global [%0], [%1], 16;" :: "r"(dst), "l"(src));
}
__device__ __forceinline__ void cp_commit() {
    asm volatile("cp.async.commit_group;" ::: "memory");
}
__device__ __forceinline__ void ldsm_x4(uint32_t addr, uint32_t r[4]) {
    asm volatile("ldmatrix.sync.aligned.m8n8.x4.shared.b16 {%0,%1,%2,%3}, [%4];"
        : "=r"(r[0]), "=r"(r[1]), "=r"(r[2]), "=r"(r[3]) : "r"(addr));
}
__device__ __forceinline__ void mma_f16(float c[4], const uint32_t a[4],
                                        uint32_t b0, uint32_t b1) {
    asm volatile(
        "mma.sync.aligned.m16n8k16.row.col.f32.f16.f16.f32 "
        "{%0,%1,%2,%3}, {%4,%5,%6,%7}, {%8,%9}, {%0,%1,%2,%3};"
        : "+f"(c[0]), "+f"(c[1]), "+f"(c[2]), "+f"(c[3])
        : "r"(a[0]), "r"(a[1]), "r"(a[2]), "r"(a[3]), "r"(b0), "r"(b1));
}
__device__ __forceinline__ uint32_t pack_f16x2(float lo, float hi) {
    uint32_t r;
    asm("cvt.rn.f16x2.f32 %0, %1, %2;" : "=r"(r) : "f"(hi), "f"(lo));
    return r;
}

// =================== prep kernels ===================
__global__ void prep_act_h_kernel(const float4* __restrict__ A,
                                  __half* __restrict__ H, int nquads)
{
    const int i = blockIdx.x * blockDim.x + threadIdx.x;
    if (i >= nquads) return;
    const float4 v = A[i];
    *(__half2*)(H + (size_t)i * 4)     = __halves2half2(__float2half_rn(v.x), __float2half_rn(v.y));
    *(__half2*)(H + (size_t)i * 4 + 2) = __halves2half2(__float2half_rn(v.z), __float2half_rn(v.w));
}

struct WP9 {
    const float* w[9];
    __half* h[9];
    __half* l[9];
};
__global__ void prep_w_kernel(WP9 wp)
{
    __shared__ float t[32][33];
    const int z  = blockIdx.z;
    const float* W = wp.w[z];
    __half* H = wp.h[z];
    __half* L = wp.l[z];
    const int bx = blockIdx.x;
    const int by = blockIdx.y;
    const int tx = threadIdx.x;
    const int ty = threadIdx.y;
    #pragma unroll
    for (int r = 0; r < 32; r += 8)
        t[ty + r][tx] = W[(size_t)(by * 32 + ty + r) * 1024 + bx * 32 + tx];
    __syncthreads();
    #pragma unroll
    for (int r = 0; r < 32; r += 8) {
        const float v = t[tx][ty + r];
        const __half h = __float2half_rn(v);
        const size_t o = (size_t)(bx * 32 + ty + r) * 1024 + by * 32 + tx;
        H[o] = h;
        if (z >= 4) L[o] = __float2half_rn(v - __half2float(h));
    }
}

// =================== fragment index helpers ===================
#define FRAG_IDX()                                                            \
    const int arow_in = (lane & 7) + ((lane >> 3) & 1) * 8;                   \
    const int acolx   = (lane >> 4) * 16;                                     \
    const int brow_in = (lane & 7) + ((lane >> 4) & 1) * 8;                   \
    const int bcolx   = ((lane >> 3) & 1) * 16;

#define BUF3_BYTES 65536
#define GEMM3_SMEM (2 * BUF3_BYTES)

#define ISSUE3(ic, buf) do {                                                  \
    const uint32_t sbase = sb + (buf) * BUF3_BYTES;                           \
    const size_t coff = (size_t)(ic) * 128 + cb;                              \
    _Pragma("unroll")                                                         \
    for (int i = 0; i < 4; i++) {                                             \
        const size_t go = (size_t)(rcp + i * 32) * 2048 + coff;               \
        cp16(sbase + dsw[i],          gAh + go);                              \
        cp16(sbase + 16384 + dsw[i],  gAl + go);                              \
        cp16(sbase + 32768 + dsw[i],  gBh + go);                              \
        cp16(sbase + 49152 + dsw[i],  gBl + go);                              \
    }                                                                         \
    cp_commit();                                                              \
} while (0)

// =================== split-K 3-term small GEMM -> fp32 partials ===================
__global__ __launch_bounds__(256, 1) void gemm_smallk_kernel(
    const __half* __restrict__ Ah, const __half* __restrict__ Al,
    const __half* __restrict__ WHb, const __half* __restrict__ WLb,
    int zbase, float* __restrict__ P)
{
    extern __shared__ char smem[];
    const uint32_t sb = smem_u32(smem);
    const int tid  = threadIdx.x;
    const int lane = tid & 31;
    const int wid  = tid >> 5;
    const int wm   = wid & 3;
    const int wn   = wid >> 2;
    const int bn = blockIdx.x;
    const int zi = blockIdx.y;
    const int ks = blockIdx.z;
    const int rcp = tid >> 3;
    const int cb  = (tid & 7) << 4;
    uint32_t dsw[4];
    #pragma unroll
    for (int i = 0; i < 4; i++) dsw[i] = SWZ128((uint32_t)((rcp + i * 32) * 128 + cb));
    FRAG_IDX();

    const char* gAh = (const char*)Ah;
    const char* gAl = (const char*)Al;
    const char* gBh = (const char*)(WHb + (size_t)(zbase + zi) * WSTRIDE + (size_t)bn * 128 * 1024);
    const char* gBl = (const char*)(WLb + (size_t)(zbase + zi) * WSTRIDE + (size_t)bn * 128 * 1024);

    float c[2][8][4];
    #pragma unroll
    for (int mt = 0; mt < 2; mt++)
        #pragma unroll
        for (int nb = 0; nb < 8; nb++)
            #pragma unroll
            for (int j = 0; j < 4; j++) c[mt][nb][j] = 0.f;

    const int ic0 = ks * 4;
    ISSUE3(ic0, 0);
    #pragma unroll 1
    for (int it = 0; it < 4; it++) {
        const int cur = it & 1;
        if (it < 3) ISSUE3(ic0 + it + 1, cur ^ 1);
        if (it < 3) asm volatile("cp.async.wait_group 1;" ::: "memory");
        else        asm volatile("cp.async.wait_group 0;" ::: "memory");
        __syncthreads();
        const uint32_t base = sb + cur * BUF3_BYTES;
        #pragma unroll
        for (int kk = 0; kk < 4; kk++) {
            const uint32_t kb = kk * 32;
            uint32_t ah[2][4], al_[2][4];
            #pragma unroll
            for (int mt = 0; mt < 2; mt++) {
                const uint32_t off =
                    SWZ128((uint32_t)((wm * 32 + mt * 16 + arow_in) * 128 + kb + acolx));
                ldsm_x4(base + off,          ah[mt]);
                ldsm_x4(base + 16384 + off,  al_[mt]);
            }
            uint32_t bh[4][4], bl[4][4];
            #pragma unroll
            for (int p = 0; p < 4; p++) {
                const uint32_t off =
                    SWZ128((uint32_t)((wn * 64 + p * 16 + brow_in) * 128 + kb + bcolx));
                ldsm_x4(base + 32768 + off, bh[p]);
                ldsm_x4(base + 49152 + off, bl[p]);
            }
            #pragma unroll
            for (int mt = 0; mt < 2; mt++) {
                #pragma unroll
                for (int p = 0; p < 4; p++) {
                    mma_f16(c[mt][2 * p],     ah[mt],  bh[p][0], bh[p][1]);
                    mma_f16(c[mt][2 * p],     ah[mt],  bl[p][0], bl[p][1]);
                    mma_f16(c[mt][2 * p],     al_[mt], bh[p][0], bh[p][1]);
                    mma_f16(c[mt][2 * p + 1], ah[mt],  bh[p][2], bh[p][3]);
                    mma_f16(c[mt][2 * p + 1], ah[mt],  bl[p][2], bl[p][3]);
                    mma_f16(c[mt][2 * p + 1], al_[mt], bh[p][2], bh[p][3]);
                }
            }
        }
        __syncthreads();
    }

    float* Pp = P + (size_t)(zi * 4 + ks) * PART_STRIDE;
    const int row_base = wm * 32 + (lane >> 2);
    const int col_base = bn * 128 + wn * 64 + 2 * (lane & 3);
    #pragma unroll
    for (int mt = 0; mt < 2; mt++) {
        #pragma unroll
        for (int hh = 0; hh < 2; hh++) {
            const int row = row_base + mt * 16 + hh * 8;
            #pragma unroll
            for (int nb = 0; nb < 8; nb++) {
                const int col = col_base + nb * 8;
                float2 o;
                o.x = c[mt][nb][hh * 2 + 0];
                o.y = c[mt][nb][hh * 2 + 1];
                *(float2*)(Pp + (size_t)row * 1024 + col) = o;
            }
        }
    }
}

// ---- fused reduce: 3 GEMMs' partials + per-tensor bias -> fp32 (rows 0..63) ----
__global__ void reduce3_fp32_kernel(const float* __restrict__ P,
                                    const float* __restrict__ b0,
                                    const float* __restrict__ b1,
                                    const float* __restrict__ b2,
                                    float* __restrict__ C)
{
    const int zi  = blockIdx.y;
    const int idx = blockIdx.x * 256 + threadIdx.x;
    const float* Pp = P + (size_t)zi * 4 * PART_STRIDE;
    const float s = Pp[idx] + Pp[idx + PART_STRIDE] + Pp[idx + 2 * PART_STRIDE] + Pp[idx + 3 * PART_STRIDE];
    const float* bias = (zi == 0) ? b0 : (zi == 1) ? b1 : b2;
    C[(size_t)zi * NBLK * D_MODEL + idx] = s + bias[idx & 1023];
}

__global__ void reduce_fp32_kernel(const float* __restrict__ P,
                                   const float* __restrict__ bias,
                                   float* __restrict__ C)
{
    const int idx = blockIdx.x * 256 + threadIdx.x;
    const float s = P[idx] + P[idx + PART_STRIDE] + P[idx + 2 * PART_STRIDE] + P[idx + 3 * PART_STRIDE];
    C[idx] = s + bias[idx & 1023];
}

__global__ void reduce_hl_kernel(const float* __restrict__ P,
                                 const float* __restrict__ bias,
                                 __half* __restrict__ H, __half* __restrict__ L)
{
    const int idx = blockIdx.x * 256 + threadIdx.x;
    const float v = P[idx] + P[idx + PART_STRIDE] + P[idx + 2 * PART_STRIDE] + P[idx + 3 * PART_STRIDE]
                  + bias[idx & 1023];
    const __half h = __float2half_rn(v);
    H[idx] = h;
    L[idx] = __float2half_rn(v - __half2float(h));
}

// =================== 1-term GEMM mainloop (big path): C ~= Ah * Bh ===================
#define BUF1_BYTES 32768
#define GEMM1_SMEM (2 * BUF1_BYTES)

#define ISSUE1(ic, buf) do {                                                  \
    const uint32_t sbase = sb + (buf) * BUF1_BYTES;                           \
    const size_t coff = (size_t)(ic) * 128 + cb;                              \
    _Pragma("unroll")                                                         \
    for (int i = 0; i < 4; i++) {                                             \
        const size_t go = (size_t)(rcp + i * 32) * 2048 + coff;               \
        cp16(sbase + dsw[i],          gAh + go);                              \
        cp16(sbase + 16384 + dsw[i],  gBh + go);                              \
    }                                                                         \
    cp_commit();                                                              \
} while (0)

#define GEMM1_BODY()                                                          \
    extern __shared__ char smem[];                                            \
    const uint32_t sb = smem_u32(smem);                                       \
    const int tid  = threadIdx.x;                                             \
    const int lane = tid & 31;                                                \
    const int wid  = tid >> 5;                                                \
    const int wm   = wid & 3;                                                 \
    const int wn   = wid >> 2;                                                \
    const int bn = blockIdx.x;                                                \
    const int bm = blockIdx.y;                                                \
    const int rcp = tid >> 3;                                                 \
    const int cb  = (tid & 7) << 4;                                           \
    uint32_t dsw[4];                                                          \
    _Pragma("unroll")                                                         \
    for (int i = 0; i < 4; i++) dsw[i] = SWZ128((uint32_t)((rcp + i * 32) * 128 + cb)); \
    FRAG_IDX();                                                               \
    float c[2][8][4];                                                         \
    _Pragma("unroll")                                                         \
    for (int mt = 0; mt < 2; mt++)                                            \
        _Pragma("unroll")                                                     \
        for (int nb = 0; nb < 8; nb++)                                        \
            _Pragma("unroll")                                                 \
            for (int j = 0; j < 4; j++) c[mt][nb][j] = 0.f;                   \
    ISSUE1(0, 0);                                                             \
    _Pragma("unroll 1")                                                       \
    for (int ic = 0; ic < 16; ic++) {                                         \
        const int cur = ic & 1;                                               \
        if (ic < 15) ISSUE1(ic + 1, cur ^ 1);                                 \
        if (ic < 15) asm volatile("cp.async.wait_group 1;" ::: "memory");     \
        else         asm volatile("cp.async.wait_group 0;" ::: "memory");     \
        __syncthreads();                                                      \
        const uint32_t base = sb + cur * BUF1_BYTES;                          \
        _Pragma("unroll")                                                     \
        for (int kk = 0; kk < 4; kk++) {                                      \
            const uint32_t kb = kk * 32;                                      \
            uint32_t ah[2][4];                                                \
            _Pragma("unroll")                                                 \
            for (int mt = 0; mt < 2; mt++) {                                  \
                const uint32_t off =                                          \
                    SWZ128((uint32_t)((wm * 32 + mt * 16 + arow_in) * 128 + kb + acolx)); \
                ldsm_x4(base + off, ah[mt]);                                  \
            }                                                                 \
            uint32_t bh[4][4];                                                \
            _Pragma("unroll")                                                 \
            for (int p = 0; p < 4; p++) {                                     \
                const uint32_t off =                                          \
                    SWZ128((uint32_t)((wn * 64 + p * 16 + brow_in) * 128 + kb + bcolx)); \
                ldsm_x4(base + 16384 + off, bh[p]);                           \
            }                                                                 \
            _Pragma("unroll")                                                 \
            for (int mt = 0; mt < 2; mt++) {                                  \
                _Pragma("unroll")                                             \
                for (int p = 0; p < 4; p++) {                                 \
                    mma_f16(c[mt][2 * p],     ah[mt], bh[p][0], bh[p][1]);    \
                    mma_f16(c[mt][2 * p + 1], ah[mt], bh[p][2], bh[p][3]);    \
                }                                                             \
            }                                                                 \
        }                                                                     \
        __syncthreads();                                                      \
    }

// ---- fused QKV: 1-term fp16, split-fp16 out ----
__global__ __launch_bounds__(256, 2) void gemm1_qkv_kernel(
    const __half* __restrict__ Ah, const __half* __restrict__ Bh,
    const float* __restrict__ bq, const float* __restrict__ bk, const float* __restrict__ bv,
    __half* __restrict__ QH, __half* __restrict__ QL,
    __half* __restrict__ KH, __half* __restrict__ KL,
    __half* __restrict__ VH, __half* __restrict__ VL)
{
    const char* gAh = (const char*)(Ah + (size_t)(blockIdx.y * 128) * 1024);
    const char* gBh = (const char*)(Bh + (size_t)(blockIdx.x * 128) * 1024);
    GEMM1_BODY();

    const int tensor = bn >> 3;
    const float* bias = (tensor == 0) ? bq : (tensor == 1) ? bk : bv;
    __half* OH = (tensor == 0) ? QH : (tensor == 1) ? KH : VH;
    __half* OL = (tensor == 0) ? QL : (tensor == 1) ? KL : VL;

    const int row_base = bm * 128 + wm * 32 + (lane >> 2);
    const int col_base = (bn & 7) * 128 + wn * 64 + 2 * (lane & 3);
    #pragma unroll
    for (int mt = 0; mt < 2; mt++) {
        #pragma unroll
        for (int hh = 0; hh < 2; hh++) {
            const int row = row_base + mt * 16 + hh * 8;
            #pragma unroll
            for (int nb = 0; nb < 8; nb++) {
                const int col = col_base + nb * 8;
                const float v0 = c[mt][nb][hh * 2 + 0] + bias[col + 0];
                const float v1 = c[mt][nb][hh * 2 + 1] + bias[col + 1];
                const __half h0 = __float2half_rn(v0);
                const __half h1 = __float2half_rn(v1);
                *(__half2*)(OH + (size_t)row * 1024 + col) = __halves2half2(h0, h1);
                *(__half2*)(OL + (size_t)row * 1024 + col) = __halves2half2(
                    __float2half_rn(v0 - __half2float(h0)),
                    __float2half_rn(v1 - __half2float(h1)));
            }
        }
    }
}

// ---- o-proj: 1-term fp16, fp32 out + bias + summary add ----
__global__ __launch_bounds__(256, 2) void gemm1_oproj_kernel(
    const __half* __restrict__ Ah, const __half* __restrict__ Bh,
    const float* __restrict__ bias, const float* __restrict__ addBlk,
    float* __restrict__ C)
{
    const char* gAh = (const char*)(Ah + (size_t)(blockIdx.y * 128) * 1024);
    const char* gBh = (const char*)(Bh + (size_t)(blockIdx.x * 128) * 1024);
    GEMM1_BODY();

    const int row_base = bm * 128 + wm * 32 + (lane >> 2);
    const int col_base = bn * 128 + wn * 64 + 2 * (lane & 3);
    #pragma unroll
    for (int mt = 0; mt < 2; mt++) {
        #pragma unroll
        for (int hh = 0; hh < 2; hh++) {
            const int row = row_base + mt * 16 + hh * 8;
            const int rb = row >> 8;
            #pragma unroll
            for (int nb = 0; nb < 8; nb++) {
                const int col = col_base + nb * 8;
                float2 o;
                o.x = c[mt][nb][hh * 2 + 0] + bias[col + 0] + addBlk[(size_t)rb * 1024 + col + 0];
                o.y = c[mt][nb][hh * 2 + 1] + bias[col + 1] + addBlk[(size_t)rb * 1024 + col + 1];
                *(float2*)(C + (size_t)row * 1024 + col) = o;
            }
        }
    }
}

// =================== V transpose ===================
__global__ __launch_bounds__(256) void vtrans_kernel(
    const __half* __restrict__ VH, const __half* __restrict__ VL,
    __half* __restrict__ VTH, __half* __restrict__ VTL)
{
    __shared__ __half t[256][72];
    const int blk = blockIdx.x;
    const int dt  = blockIdx.y;
    const int tid = threadIdx.x;
    #pragma unroll 1
    for (int pass = 0; pass < 2; pass++) {
        const __half* src = pass ? VL : VH;
        __half* dst = pass ? VTL : VTH;
        #pragma unroll
        for (int it = 0; it < 8; it++) {
            const int task = it * 256 + tid;
            const int row = task >> 3;
            const int dc  = (task & 7) * 8;
            *(uint4*)&t[row][dc] =
                *(const uint4*)(src + ((size_t)(blk * 256 + row)) * 1024 + dt * 64 + dc);
        }
        __syncthreads();
        #pragma unroll
        for (int it = 0; it < 8; it++) {
            const int task = it * 256 + tid;
            const int d  = task >> 5;
            const int tc = (task & 31) * 8;
            __half tmp[8];
            #pragma unroll
            for (int j = 0; j < 8; j++) tmp[j] = t[tc + j][d];
            *(uint4*)(dst + ((size_t)(blk * 1024) + dt * 64 + d) * 256 + tc) = *(uint4*)tmp;
        }
        __syncthreads();
    }
}

// =================== HMMA local attention (3-term fp16, hi-only ctx out) ===================
#define ATT_SMEM (6 * 32768)

__global__ __launch_bounds__(512, 1) void attn_mma_kernel(
    const __half* __restrict__ QH, const __half* __restrict__ QL,
    const __half* __restrict__ KH, const __half* __restrict__ KL,
    const __half* __restrict__ VTH, const __half* __restrict__ VTL,
    const float* __restrict__ bias,
    __half* __restrict__ CH)
{
    extern __shared__ char smem[];
    const uint32_t sb = smem_u32(smem);
    const int blk = blockIdx.x;
    const int h   = blockIdx.y;
    const int tid = threadIdx.x;
    const int lane = tid & 31;
    const int w    = tid >> 5;

    const uint32_t QHs = sb;
    const uint32_t QLs = sb + 32768;
    const uint32_t KHs = sb + 65536;
    const uint32_t KLs = sb + 98304;
    const uint32_t VHs = sb + 131072;
    const uint32_t VLs = sb + 163840;

    {
        const char* qh0 = (const char*)(QH + ((size_t)blk * 256) * 1024 + h * 64);
        const char* ql0 = (const char*)(QL + ((size_t)blk * 256) * 1024 + h * 64);
        const char* kh0 = (const char*)(KH + ((size_t)blk * 256) * 1024 + h * 64);
        const char* kl0 = (const char*)(KL + ((size_t)blk * 256) * 1024 + h * 64);
        #pragma unroll
        for (int i = 0; i < 4; i++) {
            const int cidx = tid + i * 512;
            const int row = cidx >> 3;
            const int cbo = (cidx & 7) << 4;
            const uint32_t d = SWZ128((uint32_t)(row * 128 + cbo));
            const size_t go = (size_t)row * 2048 + cbo;
            cp16(QHs + d, qh0 + go);
            cp16(QLs + d, ql0 + go);
            cp16(KHs + d, kh0 + go);
            cp16(KLs + d, kl0 + go);
        }
        const char* vh0 = (const char*)(VTH + ((size_t)blk * 1024 + h * 64) * 256);
        const char* vl0 = (const char*)(VTL + ((size_t)blk * 1024 + h * 64) * 256);
        #pragma unroll
        for (int i = 0; i < 4; i++) {
            const int cidx = tid + i * 512;
            const int row = cidx >> 5;
            const int cbo = (cidx & 31) << 4;
            const uint32_t d = SWZ512((uint32_t)(row * 512 + cbo));
            const size_t go = (size_t)row * 512 + cbo;
            cp16(VHs + d, vh0 + go);
            cp16(VLs + d, vl0 + go);
        }
        cp_commit();
        asm volatile("cp.async.wait_group 0;" ::: "memory");
        __syncthreads();
    }

    const int arow = (lane & 7) + ((lane >> 3) & 1) * 8;
    const int acol = (lane >> 4) * 16;
    const int brow = (lane & 7) + ((lane >> 4) & 1) * 8;
    const int bcol = ((lane >> 3) & 1) * 16;

    float s[32][4];
    #pragma unroll
    for (int j = 0; j < 32; j++)
        #pragma unroll
        for (int q = 0; q < 4; q++) s[j][q] = 0.f;

    #pragma unroll
    for (int kk = 0; kk < 4; kk++) {
        const uint32_t kb = kk * 32;
        uint32_t qh[4], ql[4];
        const uint32_t aoff = SWZ128((uint32_t)((w * 16 + arow) * 128 + kb + acol));
        ldsm_x4(QHs + aoff, qh);
        ldsm_x4(QLs + aoff, ql);
        #pragma unroll
        for (int p = 0; p < 16; p++) {
            uint32_t bh[4], bl[4];
            const uint32_t boff = SWZ128((uint32_t)((p * 16 + brow) * 128 + kb + bcol));
            ldsm_x4(KHs + boff, bh);
            ldsm_x4(KLs + boff, bl);
            mma_f16(s[2 * p],     qh, bh[0], bh[1]);
            mma_f16(s[2 * p],     qh, bl[0], bl[1]);
            mma_f16(s[2 * p],     ql, bh[0], bh[1]);
            mma_f16(s[2 * p + 1], qh, bh[2], bh[3]);
            mma_f16(s[2 * p + 1], qh, bl[2], bl[3]);
            mma_f16(s[2 * p + 1], ql, bh[2], bh[3]);
        }
    }

    const int r0 = w * 16 + (lane >> 2);
    const int cq = (lane & 3) * 2;
    const float* br0 = bias + ((size_t)h * 256 + r0) * 256;
    const float* br1 = br0 + 8 * 256;

    float m0 = -1e30f, m1 = -1e30f;
    #pragma unroll
    for (int j = 0; j < 32; j++) {
        const float2 b0 = *(const float2*)(br0 + j * 8 + cq);
        const float2 b1 = *(const float2*)(br1 + j * 8 + cq);
        s[j][0] = s[j][0] * 0.125f + b0.x;
        s[j][1] = s[j][1] * 0.125f + b0.y;
        s[j][2] = s[j][2] * 0.125f + b1.x;
        s[j][3] = s[j][3] * 0.125f + b1.y;
        m0 = fmaxf(m0, fmaxf(s[j][0], s[j][1]));
        m1 = fmaxf(m1, fmaxf(s[j][2], s[j][3]));
    }
    #pragma unroll
    for (int msk = 1; msk <= 2; msk <<= 1) {
        m0 = fmaxf(m0, __shfl_xor_sync(0xffffffffu, m0, msk));
        m1 = fmaxf(m1, __shfl_xor_sync(0xffffffffu, m1, msk));
    }
    float l0 = 0.f, l1 = 0.f;
    #pragma unroll
    for (int j = 0; j < 32; j++) {
        s[j][0] = __expf(s[j][0] - m0);
        s[j][1] = __expf(s[j][1] - m0);
        s[j][2] = __expf(s[j][2] - m1);
        s[j][3] = __expf(s[j][3] - m1);
        l0 += s[j][0] + s[j][1];
        l1 += s[j][2] + s[j][3];
    }
    #pragma unroll
    for (int msk = 1; msk <= 2; msk <<= 1) {
        l0 += __shfl_xor_sync(0xffffffffu, l0, msk);
        l1 += __shfl_xor_sync(0xffffffffu, l1, msk);
    }

    float o[8][4];
    #pragma unroll
    for (int j = 0; j < 8; j++)
        #pragma unroll
        for (int q = 0; q < 4; q++) o[j][q] = 0.f;

    #pragma unroll
    for (int kt = 0; kt < 16; kt++) {
        uint32_t pah[4], pal[4];
        #pragma unroll
        for (int half_ = 0; half_ < 2; half_++) {
            const float* sv = s[2 * kt + half_];
            const float p0 = sv[0], p1 = sv[1], p2 = sv[2], p3 = sv[3];
            const __half h0 = __float2half_rn(p0);
            const __half h1 = __float2half_rn(p1);
            const __half h2 = __float2half_rn(p2);
            const __half h3 = __float2half_rn(p3);
            pah[2 * half_ + 0] = pack_f16x2(__half2float(h0), __half2float(h1));
            pah[2 * half_ + 1] = pack_f16x2(__half2float(h2), __half2float(h3));
            pal[2 * half_ + 0] = pack_f16x2(p0 - __half2float(h0), p1 - __half2float(h1));
            pal[2 * half_ + 1] = pack_f16x2(p2 - __half2float(h2), p3 - __half2float(h3));
        }
        #pragma unroll
        for (int nd = 0; nd < 4; nd++) {
            uint32_t bh[4], bl[4];
            const uint32_t boff = SWZ512((uint32_t)((nd * 16 + brow) * 512 + kt * 32 + bcol));
            ldsm_x4(VHs + boff, bh);
            ldsm_x4(VLs + boff, bl);
            mma_f16(o[2 * nd],     pah, bh[0], bh[1]);
            mma_f16(o[2 * nd],     pah, bl[0], bl[1]);
            mma_f16(o[2 * nd],     pal, bh[0], bh[1]);
            mma_f16(o[2 * nd + 1], pah, bh[2], bh[3]);
            mma_f16(o[2 * nd + 1], pah, bl[2], bl[3]);
            mma_f16(o[2 * nd + 1], pal, bh[2], bh[3]);
        }
    }

    const float inv0 = 1.f / l0;
    const float inv1 = 1.f / l1;
    const size_t row0 = (size_t)blk * 256 + r0;
    #pragma unroll
    for (int j = 0; j < 8; j++) {
        const int col = h * 64 + j * 8 + cq;
        *(__half2*)(CH + row0 * 1024 + col) = __halves2half2(
            __float2half_rn(o[j][0] * inv0), __float2half_rn(o[j][1] * inv0));
        *(__half2*)(CH + (row0 + 8) * 1024 + col) = __halves2half2(
            __float2half_rn(o[j][2] * inv1), __float2half_rn(o[j][3] * inv1));
    }
}

// =================== mean pool -> split fp16 directly ===================
__global__ void meanpool_hl_kernel(const float* __restrict__ x,
                                   __half* __restrict__ H, __half* __restrict__ L)
{
    const int blk = blockIdx.x;
    const int c   = blockIdx.y * 256 + threadIdx.x;
    const float* base = x + (size_t)blk * BSZ * D_MODEL + c;
    float s = 0.f;
    #pragma unroll 4
    for (int r = 0; r < BSZ; r++) s += base[(size_t)r * D_MODEL];
    const float v = s * (1.0f / BSZ);
    const __half h = __float2half_rn(v);
    H[blk * D_MODEL + c] = h;
    L[blk * D_MODEL + c] = __float2half_rn(v - __half2float(h));
}

// =================== summary attention (fp32 in, split fp16 out) ===================
__global__ void summ_attn_kernel(
    const float* __restrict__ QKV2,
    __half* __restrict__ SCH, __half* __restrict__ SCL)
{
    const float* Q2 = QKV2;
    const float* K2 = QKV2 + (size_t)NBLK * D_MODEL;
    const float* V2 = QKV2 + (size_t)2 * NBLK * D_MODEL;
    const int b = blockIdx.x;
    const int h = blockIdx.y;
    const int l = threadIdx.x;

    const float* qr = Q2 + (size_t)(b * 16 + l) * D_MODEL + h * DHEAD;
    float q[DHEAD];
    #pragma unroll
    for (int d = 0; d < DHEAD; d += 4) {
        const float4 v = *(const float4*)(qr + d);
        q[d] = v.x; q[d + 1] = v.y; q[d + 2] = v.z; q[d + 3] = v.w;
    }

    float s[16];
    float m = -1e30f;
    for (int j = 0; j < 16; j++) {
        const float* kr = K2 + (size_t)(b * 16 + j) * D_MODEL + h * DHEAD;
        float a = 0.f;
        #pragma unroll
        for (int d = 0; d < DHEAD; d += 4) {
            const float4 v = *(const float4*)(kr + d);
            a += q[d] * v.x + q[d + 1] * v.y + q[d + 2] * v.z + q[d + 3] * v.w;
        }
        s[j] = a * 0.125f;
        m = fmaxf(m, s[j]);
    }
    float lsum = 0.f;
    for (int j = 0; j < 16; j++) { s[j] = __expf(s[j] - m); lsum += s[j]; }
    const float inv = 1.f / lsum;

    float o[DHEAD];
    #pragma unroll
    for (int d = 0; d < DHEAD; d++) o[d] = 0.f;
    for (int j = 0; j < 16; j++) {
        const float* vr = V2 + (size_t)(b * 16 + j) * D_MODEL + h * DHEAD;
        const float p = s[j] * inv;
        #pragma unroll
        for (int d = 0; d < DHEAD; d += 4) {
            const float4 v = *(const float4*)(vr + d);
            o[d] += p * v.x; o[d + 1] += p * v.y; o[d + 2] += p * v.z; o[d + 3] += p * v.w;
        }
    }
    const size_t ob = (size_t)(b * 16 + l) * D_MODEL + h * DHEAD;
    #pragma unroll
    for (int d = 0; d < DHEAD; d += 2) {
        const __half h0 = __float2half_rn(o[d]);
        const __half h1 = __float2half_rn(o[d + 1]);
        *(__half2*)(SCH + ob + d) = __halves2half2(h0, h1);
        *(__half2*)(SCL + ob + d) = __halves2half2(
            __float2half_rn(o[d] - __half2float(h0)),
            __float2half_rn(o[d + 1] - __half2float(h1)));
    }
}

// =================== launch ===================
extern "C" void kernel_launch(void* const* d_in, const int* in_sizes, int n_in,
                              void* d_out, int out_size)
{
    const float* x     = (const float*)d_in[0];
    const float* lq_w  = (const float*)d_in[1];
    const float* lq_b  = (const float*)d_in[2];
    const float* lk_w  = (const float*)d_in[3];
    const float* lk_b  = (const float*)d_in[4];
    const float* lv_w  = (const float*)d_in[5];
    const float* lv_b  = (const float*)d_in[6];
    const float* lo_w  = (const float*)d_in[7];
    const float* lo_b  = (const float*)d_in[8];
    const float* pbias = (const float*)d_in[9];
    const float* sq_w  = (const float*)d_in[10];
    const float* sq_b  = (const float*)d_in[11];
    const float* sk_w  = (const float*)d_in[12];
    const float* sk_b  = (const float*)d_in[13];
    const float* sv_w  = (const float*)d_in[14];
    const float* sv_b  = (const float*)d_in[15];
    const float* so_w  = (const float*)d_in[16];
    const float* so_b  = (const float*)d_in[17];
    const float* sum_w = (const float*)d_in[18];
    const float* sum_b = (const float*)d_in[19];
    float* out = (float*)d_out;

    float *QKV2, *SOUT, *PART;
    cudaGetSymbolAddress((void**)&QKV2, g_QKV2);
    cudaGetSymbolAddress((void**)&SOUT, g_SOUT);
    cudaGetSymbolAddress((void**)&PART, g_PART);

    __half *XH, *QH, *QL, *KH, *KL, *VH, *VL, *VTH, *VTL, *CH, *WH, *WL;
    __half *S1H, *S1L, *S2H, *S2L, *S3H, *S3L;
    cudaGetSymbolAddress((void**)&XH, g_XH);
    cudaGetSymbolAddress((void**)&QH, g_QH);
    cudaGetSymbolAddress((void**)&QL, g_QL);
    cudaGetSymbolAddress((void**)&KH, g_KH);
    cudaGetSymbolAddress((void**)&KL, g_KL);
    cudaGetSymbolAddress((void**)&VH, g_VH);
    cudaGetSymbolAddress((void**)&VL, g_VL);
    cudaGetSymbolAddress((void**)&VTH, g_VTH);
    cudaGetSymbolAddress((void**)&VTL, g_VTL);
    cudaGetSymbolAddress((void**)&CH, g_CH);
    cudaGetSymbolAddress((void**)&WH, g_WH);
    cudaGetSymbolAddress((void**)&WL, g_WL);
    cudaGetSymbolAddress((void**)&S1H, g_S1H);
    cudaGetSymbolAddress((void**)&S1L, g_S1L);
    cudaGetSymbolAddress((void**)&S2H, g_S2H);
    cudaGetSymbolAddress((void**)&S2L, g_S2L);
    cudaGetSymbolAddress((void**)&S3H, g_S3H);
    cudaGetSymbolAddress((void**)&S3L, g_S3L);

    WP9 wp;
    const float* ws[9] = {lq_w, lk_w, lv_w, lo_w, sum_w, sq_w, sk_w, sv_w, so_w};
    for (int i = 0; i < 9; i++) {
        wp.w[i] = ws[i];
        wp.h[i] = WH + (size_t)i * WSTRIDE;
        wp.l[i] = WL + (size_t)i * WSTRIDE;
    }

    cudaFuncSetAttribute(gemm_smallk_kernel,
                         cudaFuncAttributeMaxDynamicSharedMemorySize, GEMM3_SMEM);
    cudaFuncSetAttribute(gemm1_qkv_kernel,
                         cudaFuncAttributeMaxDynamicSharedMemorySize, GEMM1_SMEM);
    cudaFuncSetAttribute(gemm1_oproj_kernel,
                         cudaFuncAttributeMaxDynamicSharedMemorySize, GEMM1_SMEM);
    cudaFuncSetAttribute(attn_mma_kernel,
                         cudaFuncAttributeMaxDynamicSharedMemorySize, ATT_SMEM);

    // one-time side stream + fork/join events (created on first, uncaptured call;
    // no device-memory allocation involved — host stream/event objects only)
    static cudaStream_t s2 = nullptr;
    static cudaEvent_t evFork = nullptr, evJoin = nullptr;
    if (s2 == nullptr) {
        cudaStreamCreateWithFlags(&s2, cudaStreamNonBlocking);
        cudaEventCreateWithFlags(&evFork, cudaEventDisableTiming);
        cudaEventCreateWithFlags(&evJoin, cudaEventDisableTiming);
    }

    // ---- prep (main stream) ----
    prep_w_kernel<<<dim3(32, 32, 9), dim3(32, 8)>>>(wp);

    // fork: small path runs concurrently on s2
    cudaEventRecord(evFork, 0);
    cudaStreamWaitEvent(s2, evFork, 0);

    // ---- small summary path on s2 (3-term split-K) ----
    meanpool_hl_kernel<<<dim3(NBLK, 4), 256, 0, s2>>>(x, S1H, S1L);
    gemm_smallk_kernel<<<dim3(8, 1, 4), 256, GEMM3_SMEM, s2>>>(S1H, S1L, WH, WL, 4, PART);
    reduce_hl_kernel<<<512, 256, 0, s2>>>(PART, sum_b, S2H, S2L);
    gemm_smallk_kernel<<<dim3(8, 3, 4), 256, GEMM3_SMEM, s2>>>(S2H, S2L, WH, WL, 5, PART);
    reduce3_fp32_kernel<<<dim3(256, 3), 256, 0, s2>>>(PART, sq_b, sk_b, sv_b, QKV2);
    summ_attn_kernel<<<dim3(4, NHEAD), 16, 0, s2>>>(QKV2, S3H, S3L);
    gemm_smallk_kernel<<<dim3(8, 1, 4), 256, GEMM3_SMEM, s2>>>(S3H, S3L, WH, WL, 8, PART);
    reduce_fp32_kernel<<<256, 256, 0, s2>>>(PART, so_b, SOUT);
    cudaEventRecord(evJoin, s2);

    // ---- big local path on main stream ----
    prep_act_h_kernel<<<16384, 256>>>((const float4*)x, XH, 4194304);
    gemm1_qkv_kernel<<<dim3(24, NTOK / 128), 256, GEMM1_SMEM>>>(
        XH, wp.h[0], lq_b, lk_b, lv_b,
        QH, QL, KH, KL, VH, VL);
    vtrans_kernel<<<dim3(NBLK, 16), 256>>>(VH, VL, VTH, VTL);
    attn_mma_kernel<<<dim3(NBLK, NHEAD), 512, ATT_SMEM>>>(
        QH, QL, KH, KL, VTH, VTL, pbias, CH);

    // join: o-proj needs SOUT from the small path
    cudaStreamWaitEvent(0, evJoin, 0);
    gemm1_oproj_kernel<<<dim3(8, NTOK / 128), 256, GEMM1_SMEM>>>(
        CH, wp.h[3], lo_b, SOUT, out);
}

// round 13
// speedup vs baseline: 2.4305x; 1.1273x over previous
#include <cuda_runtime.h>
#include <cuda_fp16.h>
#include <cstdint>

#define D_MODEL 1024
#define NHEAD   16
#define DHEAD   64
#define BSZ     256
#define NTOK    16384
#define NBLK    64
#define NELEM   ((size_t)NTOK * D_MODEL)
#define WSTRIDE (1024 * 1024)
#define PART_STRIDE (128 * 1024)

// ---------------- fp32 scratch (small path) ----------------
__device__ __align__(16) float g_QKV2[3 * NBLK * D_MODEL];   // Q2|K2|V2
__device__ __align__(16) float g_SOUT[NBLK * D_MODEL];
__device__ __align__(16) float g_PART[12 * PART_STRIDE];     // split-K partials

// ---------------- fp16 split scratch ----------------
__device__ __align__(16) __half g_XH[NELEM];
__device__ __align__(16) __half g_QH[NELEM];
__device__ __align__(16) __half g_KH[NELEM];
__device__ __align__(16) __half g_KL[NELEM];
__device__ __align__(16) __half g_VH[NELEM];
__device__ __align__(16) __half g_VL[NELEM];
__device__ __align__(16) __half g_VTH[NELEM];   // [blk][dim][tok]
__device__ __align__(16) __half g_VTL[NELEM];
__device__ __align__(16) __half g_CH[NELEM];
__device__ __align__(16) __half g_WH[9][WSTRIDE];  // transposed [N][K] hi
__device__ __align__(16) __half g_WL[9][WSTRIDE];  // transposed [N][K] lo (3-term small path only)
// per-stage small activations (distinct buffers -> replay-deterministic)
__device__ __align__(16) __half g_S1H[128 * 1024];
__device__ __align__(16) __half g_S1L[128 * 1024];
__device__ __align__(16) __half g_S2H[128 * 1024];
__device__ __align__(16) __half g_S2L[128 * 1024];
__device__ __align__(16) __half g_S3H[128 * 1024];
__device__ __align__(16) __half g_S3L[128 * 1024];

// =================== helpers ===================
__device__ __forceinline__ uint32_t smem_u32(const void* p) {
    uint32_t a;
    asm("{ .reg .u64 t; cvta.to.shared.u64 t, %1; cvt.u32.u64 %0, t; }" : "=r"(a) : "l"(p));
    return a;
}
#define SWZ128(off) ((off) ^ (((off) >> 3) & 0x70))
#define SWZ512(off) ((off) ^ (((off) >> 5) & 0x70))

__device__ __forceinline__ void cp16(uint32_t dst, const void* src) {
    asm volatile("cp.async.cg.shared.global [%0], [%1], 16;" :: "r"(dst), "l"(src));
}
__device__ __forceinline__ void cp_commit() {
    asm volatile("cp.async.commit_group;" ::: "memory");
}
__device__ __forceinline__ void ldsm_x4(uint32_t addr, uint32_t r[4]) {
    asm volatile("ldmatrix.sync.aligned.m8n8.x4.shared.b16 {%0,%1,%2,%3}, [%4];"
        : "=r"(r[0]), "=r"(r[1]), "=r"(r[2]), "=r"(r[3]) : "r"(addr));
}
__device__ __forceinline__ void mma_f16(float c[4], const uint32_t a[4],
                                        uint32_t b0, uint32_t b1) {
    asm volatile(
        "mma.sync.aligned.m16n8k16.row.col.f32.f16.f16.f32 "
        "{%0,%1,%2,%3}, {%4,%5,%6,%7}, {%8,%9}, {%0,%1,%2,%3};"
        : "+f"(c[0]), "+f"(c[1]), "+f"(c[2]), "+f"(c[3])
        : "r"(a[0]), "r"(a[1]), "r"(a[2]), "r"(a[3]), "r"(b0), "r"(b1));
}
__device__ __forceinline__ uint32_t pack_f16x2(float lo, float hi) {
    uint32_t r;
    asm("cvt.rn.f16x2.f32 %0, %1, %2;" : "=r"(r) : "f"(hi), "f"(lo));
    return r;
}

// =================== prep kernels ===================
__global__ void prep_act_h_kernel(const float4* __restrict__ A,
                                  __half* __restrict__ H, int nquads)
{
    const int i = blockIdx.x * blockDim.x + threadIdx.x;
    if (i >= nquads) return;
    const float4 v = A[i];
    *(__half2*)(H + (size_t)i * 4)     = __halves2half2(__float2half_rn(v.x), __float2half_rn(v.y));
    *(__half2*)(H + (size_t)i * 4 + 2) = __halves2half2(__float2half_rn(v.z), __float2half_rn(v.w));
}

struct WP9 {
    const float* w[9];
    __half* h[9];
    __half* l[9];
};
// zoff splits the 9 weights across streams: main does [0,4) (hi only), side does [4,9) (hi+lo)
__global__ void prep_w_kernel(WP9 wp, int zoff)
{
    __shared__ float t[32][33];
    const int z  = blockIdx.z + zoff;
    const float* W = wp.w[z];
    __half* H = wp.h[z];
    __half* L = wp.l[z];
    const int bx = blockIdx.x;
    const int by = blockIdx.y;
    const int tx = threadIdx.x;
    const int ty = threadIdx.y;
    #pragma unroll
    for (int r = 0; r < 32; r += 8)
        t[ty + r][tx] = W[(size_t)(by * 32 + ty + r) * 1024 + bx * 32 + tx];
    __syncthreads();
    #pragma unroll
    for (int r = 0; r < 32; r += 8) {
        const float v = t[tx][ty + r];
        const __half h = __float2half_rn(v);
        const size_t o = (size_t)(bx * 32 + ty + r) * 1024 + by * 32 + tx;
        H[o] = h;
        if (z >= 4) L[o] = __float2half_rn(v - __half2float(h));
    }
}

// =================== fragment index helpers ===================
#define FRAG_IDX()                                                            \
    const int arow_in = (lane & 7) + ((lane >> 3) & 1) * 8;                   \
    const int acolx   = (lane >> 4) * 16;                                     \
    const int brow_in = (lane & 7) + ((lane >> 4) & 1) * 8;                   \
    const int bcolx   = ((lane >> 3) & 1) * 16;

#define BUF3_BYTES 65536
#define GEMM3_SMEM (2 * BUF3_BYTES)

#define ISSUE3(ic, buf) do {                                                  \
    const uint32_t sbase = sb + (buf) * BUF3_BYTES;                           \
    const size_t coff = (size_t)(ic) * 128 + cb;                              \
    _Pragma("unroll")                                                         \
    for (int i = 0; i < 4; i++) {                                             \
        const size_t go = (size_t)(rcp + i * 32) * 2048 + coff;               \
        cp16(sbase + dsw[i],          gAh + go);                              \
        cp16(sbase + 16384 + dsw[i],  gAl + go);                              \
        cp16(sbase + 32768 + dsw[i],  gBh + go);                              \
        cp16(sbase + 49152 + dsw[i],  gBl + go);                              \
    }                                                                         \
    cp_commit();                                                              \
} while (0)

// =================== split-K 3-term small GEMM -> fp32 partials ===================
__global__ __launch_bounds__(256, 1) void gemm_smallk_kernel(
    const __half* __restrict__ Ah, const __half* __restrict__ Al,
    const __half* __restrict__ WHb, const __half* __restrict__ WLb,
    int zbase, float* __restrict__ P)
{
    extern __shared__ char smem[];
    const uint32_t sb = smem_u32(smem);
    const int tid  = threadIdx.x;
    const int lane = tid & 31;
    const int wid  = tid >> 5;
    const int wm   = wid & 3;
    const int wn   = wid >> 2;
    const int bn = blockIdx.x;
    const int zi = blockIdx.y;
    const int ks = blockIdx.z;
    const int rcp = tid >> 3;
    const int cb  = (tid & 7) << 4;
    uint32_t dsw[4];
    #pragma unroll
    for (int i = 0; i < 4; i++) dsw[i] = SWZ128((uint32_t)((rcp + i * 32) * 128 + cb));
    FRAG_IDX();

    const char* gAh = (const char*)Ah;
    const char* gAl = (const char*)Al;
    const char* gBh = (const char*)(WHb + (size_t)(zbase + zi) * WSTRIDE + (size_t)bn * 128 * 1024);
    const char* gBl = (const char*)(WLb + (size_t)(zbase + zi) * WSTRIDE + (size_t)bn * 128 * 1024);

    float c[2][8][4];
    #pragma unroll
    for (int mt = 0; mt < 2; mt++)
        #pragma unroll
        for (int nb = 0; nb < 8; nb++)
            #pragma unroll
            for (int j = 0; j < 4; j++) c[mt][nb][j] = 0.f;

    const int ic0 = ks * 4;
    ISSUE3(ic0, 0);
    #pragma unroll 1
    for (int it = 0; it < 4; it++) {
        const int cur = it & 1;
        if (it < 3) ISSUE3(ic0 + it + 1, cur ^ 1);
        if (it < 3) asm volatile("cp.async.wait_group 1;" ::: "memory");
        else        asm volatile("cp.async.wait_group 0;" ::: "memory");
        __syncthreads();
        const uint32_t base = sb + cur * BUF3_BYTES;
        #pragma unroll
        for (int kk = 0; kk < 4; kk++) {
            const uint32_t kb = kk * 32;
            uint32_t ah[2][4], al_[2][4];
            #pragma unroll
            for (int mt = 0; mt < 2; mt++) {
                const uint32_t off =
                    SWZ128((uint32_t)((wm * 32 + mt * 16 + arow_in) * 128 + kb + acolx));
                ldsm_x4(base + off,          ah[mt]);
                ldsm_x4(base + 16384 + off,  al_[mt]);
            }
            uint32_t bh[4][4], bl[4][4];
            #pragma unroll
            for (int p = 0; p < 4; p++) {
                const uint32_t off =
                    SWZ128((uint32_t)((wn * 64 + p * 16 + brow_in) * 128 + kb + bcolx));
                ldsm_x4(base + 32768 + off, bh[p]);
                ldsm_x4(base + 49152 + off, bl[p]);
            }
            #pragma unroll
            for (int mt = 0; mt < 2; mt++) {
                #pragma unroll
                for (int p = 0; p < 4; p++) {
                    mma_f16(c[mt][2 * p],     ah[mt],  bh[p][0], bh[p][1]);
                    mma_f16(c[mt][2 * p],     ah[mt],  bl[p][0], bl[p][1]);
                    mma_f16(c[mt][2 * p],     al_[mt], bh[p][0], bh[p][1]);
                    mma_f16(c[mt][2 * p + 1], ah[mt],  bh[p][2], bh[p][3]);
                    mma_f16(c[mt][2 * p + 1], ah[mt],  bl[p][2], bl[p][3]);
                    mma_f16(c[mt][2 * p + 1], al_[mt], bh[p][2], bh[p][3]);
                }
            }
        }
        __syncthreads();
    }

    float* Pp = P + (size_t)(zi * 4 + ks) * PART_STRIDE;
    const int row_base = wm * 32 + (lane >> 2);
    const int col_base = bn * 128 + wn * 64 + 2 * (lane & 3);
    #pragma unroll
    for (int mt = 0; mt < 2; mt++) {
        #pragma unroll
        for (int hh = 0; hh < 2; hh++) {
            const int row = row_base + mt * 16 + hh * 8;
            #pragma unroll
            for (int nb = 0; nb < 8; nb++) {
                const int col = col_base + nb * 8;
                float2 o;
                o.x = c[mt][nb][hh * 2 + 0];
                o.y = c[mt][nb][hh * 2 + 1];
                *(float2*)(Pp + (size_t)row * 1024 + col) = o;
            }
        }
    }
}

// ---- reduces ----
__global__ void reduce3_fp32_kernel(const float* __restrict__ P,
                                    const float* __restrict__ b0,
                                    const float* __restrict__ b1,
                                    const float* __restrict__ b2,
                                    float* __restrict__ C)
{
    const int zi  = blockIdx.y;
    const int idx = blockIdx.x * 256 + threadIdx.x;
    const float* Pp = P + (size_t)zi * 4 * PART_STRIDE;
    const float s = Pp[idx] + Pp[idx + PART_STRIDE] + Pp[idx + 2 * PART_STRIDE] + Pp[idx + 3 * PART_STRIDE];
    const float* bias = (zi == 0) ? b0 : (zi == 1) ? b1 : b2;
    C[(size_t)zi * NBLK * D_MODEL + idx] = s + bias[idx & 1023];
}

__global__ void reduce_fp32_kernel(const float* __restrict__ P,
                                   const float* __restrict__ bias,
                                   float* __restrict__ C)
{
    const int idx = blockIdx.x * 256 + threadIdx.x;
    const float s = P[idx] + P[idx + PART_STRIDE] + P[idx + 2 * PART_STRIDE] + P[idx + 3 * PART_STRIDE];
    C[idx] = s + bias[idx & 1023];
}

__global__ void reduce_hl_kernel(const float* __restrict__ P,
                                 const float* __restrict__ bias,
                                 __half* __restrict__ H, __half* __restrict__ L)
{
    const int idx = blockIdx.x * 256 + threadIdx.x;
    const float v = P[idx] + P[idx + PART_STRIDE] + P[idx + 2 * PART_STRIDE] + P[idx + 3 * PART_STRIDE]
                  + bias[idx & 1023];
    const __half h = __float2half_rn(v);
    H[idx] = h;
    L[idx] = __float2half_rn(v - __half2float(h));
}

// =================== 1-term GEMM mainloop (big path): C ~= Ah * Bh ===================
#define BUF1_BYTES 32768
#define GEMM1_SMEM (2 * BUF1_BYTES)

#define ISSUE1(ic, buf) do {                                                  \
    const uint32_t sbase = sb + (buf) * BUF1_BYTES;                           \
    const size_t coff = (size_t)(ic) * 128 + cb;                              \
    _Pragma("unroll")                                                         \
    for (int i = 0; i < 4; i++) {                                             \
        const size_t go = (size_t)(rcp + i * 32) * 2048 + coff;               \
        cp16(sbase + dsw[i],          gAh + go);                              \
        cp16(sbase + 16384 + dsw[i],  gBh + go);                              \
    }                                                                         \
    cp_commit();                                                              \
} while (0)

#define GEMM1_BODY()                                                          \
    extern __shared__ char smem[];                                            \
    const uint32_t sb = smem_u32(smem);                                       \
    const int tid  = threadIdx.x;                                             \
    const int lane = tid & 31;                                                \
    const int wid  = tid >> 5;                                                \
    const int wm   = wid & 3;                                                 \
    const int wn   = wid >> 2;                                                \
    const int bn = blockIdx.x;                                                \
    const int bm = blockIdx.y;                                                \
    const int rcp = tid >> 3;                                                 \
    const int cb  = (tid & 7) << 4;                                           \
    uint32_t dsw[4];                                                          \
    _Pragma("unroll")                                                         \
    for (int i = 0; i < 4; i++) dsw[i] = SWZ128((uint32_t)((rcp + i * 32) * 128 + cb)); \
    FRAG_IDX();                                                               \
    float c[2][8][4];                                                         \
    _Pragma("unroll")                                                         \
    for (int mt = 0; mt < 2; mt++)                                            \
        _Pragma("unroll")                                                     \
        for (int nb = 0; nb < 8; nb++)                                        \
            _Pragma("unroll")                                                 \
            for (int j = 0; j < 4; j++) c[mt][nb][j] = 0.f;                   \
    ISSUE1(0, 0);                                                             \
    _Pragma("unroll 1")                                                       \
    for (int ic = 0; ic < 16; ic++) {                                         \
        const int cur = ic & 1;                                               \
        if (ic < 15) ISSUE1(ic + 1, cur ^ 1);                                 \
        if (ic < 15) asm volatile("cp.async.wait_group 1;" ::: "memory");     \
        else         asm volatile("cp.async.wait_group 0;" ::: "memory");     \
        __syncthreads();                                                      \
        const uint32_t base = sb + cur * BUF1_BYTES;                          \
        _Pragma("unroll")                                                     \
        for (int kk = 0; kk < 4; kk++) {                                      \
            const uint32_t kb = kk * 32;                                      \
            uint32_t ah[2][4];                                                \
            _Pragma("unroll")                                                 \
            for (int mt = 0; mt < 2; mt++) {                                  \
                const uint32_t off =                                          \
                    SWZ128((uint32_t)((wm * 32 + mt * 16 + arow_in) * 128 + kb + acolx)); \
                ldsm_x4(base + off, ah[mt]);                                  \
            }                                                                 \
            uint32_t bh[4][4];                                                \
            _Pragma("unroll")                                                 \
            for (int p = 0; p < 4; p++) {                                     \
                const uint32_t off =                                          \
                    SWZ128((uint32_t)((wn * 64 + p * 16 + brow_in) * 128 + kb + bcolx)); \
                ldsm_x4(base + 16384 + off, bh[p]);                           \
            }                                                                 \
            _Pragma("unroll")                                                 \
            for (int mt = 0; mt < 2; mt++) {                                  \
                _Pragma("unroll")                                             \
                for (int p = 0; p < 4; p++) {                                 \
                    mma_f16(c[mt][2 * p],     ah[mt], bh[p][0], bh[p][1]);    \
                    mma_f16(c[mt][2 * p + 1], ah[mt], bh[p][2], bh[p][3]);    \
                }                                                             \
            }                                                                 \
        }                                                                     \
        __syncthreads();                                                      \
    }

// ---- fused QKV: 1-term fp16; Q hi-only out, K/V split out ----
__global__ __launch_bounds__(256, 2) void gemm1_qkv_kernel(
    const __half* __restrict__ Ah, const __half* __restrict__ Bh,
    const float* __restrict__ bq, const float* __restrict__ bk, const float* __restrict__ bv,
    __half* __restrict__ QH,
    __half* __restrict__ KH, __half* __restrict__ KL,
    __half* __restrict__ VH, __half* __restrict__ VL)
{
    const char* gAh = (const char*)(Ah + (size_t)(blockIdx.y * 128) * 1024);
    const char* gBh = (const char*)(Bh + (size_t)(blockIdx.x * 128) * 1024);
    GEMM1_BODY();

    const int tensor = bn >> 3;
    const float* bias = (tensor == 0) ? bq : (tensor == 1) ? bk : bv;
    __half* OH = (tensor == 0) ? QH : (tensor == 1) ? KH : VH;
    __half* OL = (tensor == 1) ? KL : VL;   // unused for tensor==0

    const int row_base = bm * 128 + wm * 32 + (lane >> 2);
    const int col_base = (bn & 7) * 128 + wn * 64 + 2 * (lane & 3);
    #pragma unroll
    for (int mt = 0; mt < 2; mt++) {
        #pragma unroll
        for (int hh = 0; hh < 2; hh++) {
            const int row = row_base + mt * 16 + hh * 8;
            #pragma unroll
            for (int nb = 0; nb < 8; nb++) {
                const int col = col_base + nb * 8;
                const float v0 = c[mt][nb][hh * 2 + 0] + bias[col + 0];
                const float v1 = c[mt][nb][hh * 2 + 1] + bias[col + 1];
                const __half h0 = __float2half_rn(v0);
                const __half h1 = __float2half_rn(v1);
                *(__half2*)(OH + (size_t)row * 1024 + col) = __halves2half2(h0, h1);
                if (tensor != 0) {
                    *(__half2*)(OL + (size_t)row * 1024 + col) = __halves2half2(
                        __float2half_rn(v0 - __half2float(h0)),
                        __float2half_rn(v1 - __half2float(h1)));
                }
            }
        }
    }
}

// ---- o-proj: 1-term fp16, fp32 out + bias + summary add ----
__global__ __launch_bounds__(256, 2) void gemm1_oproj_kernel(
    const __half* __restrict__ Ah, const __half* __restrict__ Bh,
    const float* __restrict__ bias, const float* __restrict__ addBlk,
    float* __restrict__ C)
{
    const char* gAh = (const char*)(Ah + (size_t)(blockIdx.y * 128) * 1024);
    const char* gBh = (const char*)(Bh + (size_t)(blockIdx.x * 128) * 1024);
    GEMM1_BODY();

    const int row_base = bm * 128 + wm * 32 + (lane >> 2);
    const int col_base = bn * 128 + wn * 64 + 2 * (lane & 3);
    #pragma unroll
    for (int mt = 0; mt < 2; mt++) {
        #pragma unroll
        for (int hh = 0; hh < 2; hh++) {
            const int row = row_base + mt * 16 + hh * 8;
            const int rb = row >> 8;
            #pragma unroll
            for (int nb = 0; nb < 8; nb++) {
                const int col = col_base + nb * 8;
                float2 o;
                o.x = c[mt][nb][hh * 2 + 0] + bias[col + 0] + addBlk[(size_t)rb * 1024 + col + 0];
                o.y = c[mt][nb][hh * 2 + 1] + bias[col + 1] + addBlk[(size_t)rb * 1024 + col + 1];
                *(float2*)(C + (size_t)row * 1024 + col) = o;
            }
        }
    }
}

// =================== V transpose ===================
__global__ __launch_bounds__(256) void vtrans_kernel(
    const __half* __restrict__ VH, const __half* __restrict__ VL,
    __half* __restrict__ VTH, __half* __restrict__ VTL)
{
    __shared__ __half t[256][72];
    const int blk = blockIdx.x;
    const int dt  = blockIdx.y;
    const int tid = threadIdx.x;
    #pragma unroll 1
    for (int pass = 0; pass < 2; pass++) {
        const __half* src = pass ? VL : VH;
        __half* dst = pass ? VTL : VTH;
        #pragma unroll
        for (int it = 0; it < 8; it++) {
            const int task = it * 256 + tid;
            const int row = task >> 3;
            const int dc  = (task & 7) * 8;
            *(uint4*)&t[row][dc] =
                *(const uint4*)(src + ((size_t)(blk * 256 + row)) * 1024 + dt * 64 + dc);
        }
        __syncthreads();
        #pragma unroll
        for (int it = 0; it < 8; it++) {
            const int task = it * 256 + tid;
            const int d  = task >> 5;
            const int tc = (task & 31) * 8;
            __half tmp[8];
            #pragma unroll
            for (int j = 0; j < 8; j++) tmp[j] = t[tc + j][d];
            *(uint4*)(dst + ((size_t)(blk * 1024) + dt * 64 + d) * 256 + tc) = *(uint4*)tmp;
        }
        __syncthreads();
    }
}

// =================== HMMA local attention (2-term phases, hi-only ctx out) ===================
// Phase 1: S = Qh Kh^T + Qh Kl^T.  Phase 2: O = Ph Vh + Ph Vl.
#define ATT_SMEM (5 * 32768)

__global__ __launch_bounds__(512, 1) void attn_mma_kernel(
    const __half* __restrict__ QH,
    const __half* __restrict__ KH, const __half* __restrict__ KL,
    const __half* __restrict__ VTH, const __half* __restrict__ VTL,
    const float* __restrict__ bias,
    __half* __restrict__ CH)
{
    extern __shared__ char smem[];
    const uint32_t sb = smem_u32(smem);
    const int blk = blockIdx.x;
    const int h   = blockIdx.y;
    const int tid = threadIdx.x;
    const int lane = tid & 31;
    const int w    = tid >> 5;

    const uint32_t QHs = sb;
    const uint32_t KHs = sb + 32768;
    const uint32_t KLs = sb + 65536;
    const uint32_t VHs = sb + 98304;
    const uint32_t VLs = sb + 131072;

    {
        const char* qh0 = (const char*)(QH + ((size_t)blk * 256) * 1024 + h * 64);
        const char* kh0 = (const char*)(KH + ((size_t)blk * 256) * 1024 + h * 64);
        const char* kl0 = (const char*)(KL + ((size_t)blk * 256) * 1024 + h * 64);
        #pragma unroll
        for (int i = 0; i < 4; i++) {
            const int cidx = tid + i * 512;
            const int row = cidx >> 3;
            const int cbo = (cidx & 7) << 4;
            const uint32_t d = SWZ128((uint32_t)(row * 128 + cbo));
            const size_t go = (size_t)row * 2048 + cbo;
            cp16(QHs + d, qh0 + go);
            cp16(KHs + d, kh0 + go);
            cp16(KLs + d, kl0 + go);
        }
        const char* vh0 = (const char*)(VTH + ((size_t)blk * 1024 + h * 64) * 256);
        const char* vl0 = (const char*)(VTL + ((size_t)blk * 1024 + h * 64) * 256);
        #pragma unroll
        for (int i = 0; i < 4; i++) {
            const int cidx = tid + i * 512;
            const int row = cidx >> 5;
            const int cbo = (cidx & 31) << 4;
            const uint32_t d = SWZ512((uint32_t)(row * 512 + cbo));
            const size_t go = (size_t)row * 512 + cbo;
            cp16(VHs + d, vh0 + go);
            cp16(VLs + d, vl0 + go);
        }
        cp_commit();
        asm volatile("cp.async.wait_group 0;" ::: "memory");
        __syncthreads();
    }

    const int arow = (lane & 7) + ((lane >> 3) & 1) * 8;
    const int acol = (lane >> 4) * 16;
    const int brow = (lane & 7) + ((lane >> 4) & 1) * 8;
    const int bcol = ((lane >> 3) & 1) * 16;

    float s[32][4];
    #pragma unroll
    for (int j = 0; j < 32; j++)
        #pragma unroll
        for (int q = 0; q < 4; q++) s[j][q] = 0.f;

    #pragma unroll
    for (int kk = 0; kk < 4; kk++) {
        const uint32_t kb = kk * 32;
        uint32_t qh[4];
        const uint32_t aoff = SWZ128((uint32_t)((w * 16 + arow) * 128 + kb + acol));
        ldsm_x4(QHs + aoff, qh);
        #pragma unroll
        for (int p = 0; p < 16; p++) {
            uint32_t bh[4], bl[4];
            const uint32_t boff = SWZ128((uint32_t)((p * 16 + brow) * 128 + kb + bcol));
            ldsm_x4(KHs + boff, bh);
            ldsm_x4(KLs + boff, bl);
            mma_f16(s[2 * p],     qh, bh[0], bh[1]);
            mma_f16(s[2 * p],     qh, bl[0], bl[1]);
            mma_f16(s[2 * p + 1], qh, bh[2], bh[3]);
            mma_f16(s[2 * p + 1], qh, bl[2], bl[3]);
        }
    }

    const int r0 = w * 16 + (lane >> 2);
    const int cq = (lane & 3) * 2;
    const float* br0 = bias + ((size_t)h * 256 + r0) * 256;
    const float* br1 = br0 + 8 * 256;

    float m0 = -1e30f, m1 = -1e30f;
    #pragma unroll
    for (int j = 0; j < 32; j++) {
        const float2 b0 = *(const float2*)(br0 + j * 8 + cq);
        const float2 b1 = *(const float2*)(br1 + j * 8 + cq);
        s[j][0] = s[j][0] * 0.125f + b0.x;
        s[j][1] = s[j][1] * 0.125f + b0.y;
        s[j][2] = s[j][2] * 0.125f + b1.x;
        s[j][3] = s[j][3] * 0.125f + b1.y;
        m0 = fmaxf(m0, fmaxf(s[j][0], s[j][1]));
        m1 = fmaxf(m1, fmaxf(s[j][2], s[j][3]));
    }
    #pragma unroll
    for (int msk = 1; msk <= 2; msk <<= 1) {
        m0 = fmaxf(m0, __shfl_xor_sync(0xffffffffu, m0, msk));
        m1 = fmaxf(m1, __shfl_xor_sync(0xffffffffu, m1, msk));
    }
    float l0 = 0.f, l1 = 0.f;
    #pragma unroll
    for (int j = 0; j < 32; j++) {
        s[j][0] = __expf(s[j][0] - m0);
        s[j][1] = __expf(s[j][1] - m0);
        s[j][2] = __expf(s[j][2] - m1);
        s[j][3] = __expf(s[j][3] - m1);
        l0 += s[j][0] + s[j][1];
        l1 += s[j][2] + s[j][3];
    }
    #pragma unroll
    for (int msk = 1; msk <= 2; msk <<= 1) {
        l0 += __shfl_xor_sync(0xffffffffu, l0, msk);
        l1 += __shfl_xor_sync(0xffffffffu, l1, msk);
    }

    float o[8][4];
    #pragma unroll
    for (int j = 0; j < 8; j++)
        #pragma unroll
        for (int q = 0; q < 4; q++) o[j][q] = 0.f;

    #pragma unroll
    for (int kt = 0; kt < 16; kt++) {
        uint32_t pah[4];
        #pragma unroll
        for (int half_ = 0; half_ < 2; half_++) {
            const float* sv = s[2 * kt + half_];
            pah[2 * half_ + 0] = pack_f16x2(sv[0], sv[1]);
            pah[2 * half_ + 1] = pack_f16x2(sv[2], sv[3]);
        }
        #pragma unroll
        for (int nd = 0; nd < 4; nd++) {
            uint32_t bh[4], bl[4];
            const uint32_t boff = SWZ512((uint32_t)((nd * 16 + brow) * 512 + kt * 32 + bcol));
            ldsm_x4(VHs + boff, bh);
            ldsm_x4(VLs + boff, bl);
            mma_f16(o[2 * nd],     pah, bh[0], bh[1]);
            mma_f16(o[2 * nd],     pah, bl[0], bl[1]);
            mma_f16(o[2 * nd + 1], pah, bh[2], bh[3]);
            mma_f16(o[2 * nd + 1], pah, bl[2], bl[3]);
        }
    }

    const float inv0 = 1.f / l0;
    const float inv1 = 1.f / l1;
    const size_t row0 = (size_t)blk * 256 + r0;
    #pragma unroll
    for (int j = 0; j < 8; j++) {
        const int col = h * 64 + j * 8 + cq;
        *(__half2*)(CH + row0 * 1024 + col) = __halves2half2(
            __float2half_rn(o[j][0] * inv0), __float2half_rn(o[j][1] * inv0));
        *(__half2*)(CH + (row0 + 8) * 1024 + col) = __halves2half2(
            __float2half_rn(o[j][2] * inv1), __float2half_rn(o[j][3] * inv1));
    }
}

// =================== mean pool -> split fp16 directly ===================
__global__ void meanpool_hl_kernel(const float* __restrict__ x,
                                   __half* __restrict__ H, __half* __restrict__ L)
{
    const int blk = blockIdx.x;
    const int c   = blockIdx.y * 256 + threadIdx.x;
    const float* base = x + (size_t)blk * BSZ * D_MODEL + c;
    float s = 0.f;
    #pragma unroll 4
    for (int r = 0; r < BSZ; r++) s += base[(size_t)r * D_MODEL];
    const float v = s * (1.0f / BSZ);
    const __half h = __float2half_rn(v);
    H[blk * D_MODEL + c] = h;
    L[blk * D_MODEL + c] = __float2half_rn(v - __half2float(h));
}

// =================== summary attention (fp32 in, split fp16 out) ===================
__global__ void summ_attn_kernel(
    const float* __restrict__ QKV2,
    __half* __restrict__ SCH, __half* __restrict__ SCL)
{
    const float* Q2 = QKV2;
    const float* K2 = QKV2 + (size_t)NBLK * D_MODEL;
    const float* V2 = QKV2 + (size_t)2 * NBLK * D_MODEL;
    const int b = blockIdx.x;
    const int h = blockIdx.y;
    const int l = threadIdx.x;

    const float* qr = Q2 + (size_t)(b * 16 + l) * D_MODEL + h * DHEAD;
    float q[DHEAD];
    #pragma unroll
    for (int d = 0; d < DHEAD; d += 4) {
        const float4 v = *(const float4*)(qr + d);
        q[d] = v.x; q[d + 1] = v.y; q[d + 2] = v.z; q[d + 3] = v.w;
    }

    float s[16];
    float m = -1e30f;
    for (int j = 0; j < 16; j++) {
        const float* kr = K2 + (size_t)(b * 16 + j) * D_MODEL + h * DHEAD;
        float a = 0.f;
        #pragma unroll
        for (int d = 0; d < DHEAD; d += 4) {
            const float4 v = *(const float4*)(kr + d);
            a += q[d] * v.x + q[d + 1] * v.y + q[d + 2] * v.z + q[d + 3] * v.w;
        }
        s[j] = a * 0.125f;
        m = fmaxf(m, s[j]);
    }
    float lsum = 0.f;
    for (int j = 0; j < 16; j++) { s[j] = __expf(s[j] - m); lsum += s[j]; }
    const float inv = 1.f / lsum;

    float o[DHEAD];
    #pragma unroll
    for (int d = 0; d < DHEAD; d++) o[d] = 0.f;
    for (int j = 0; j < 16; j++) {
        const float* vr = V2 + (size_t)(b * 16 + j) * D_MODEL + h * DHEAD;
        const float p = s[j] * inv;
        #pragma unroll
        for (int d = 0; d < DHEAD; d += 4) {
            const float4 v = *(const float4*)(vr + d);
            o[d] += p * v.x; o[d + 1] += p * v.y; o[d + 2] += p * v.z; o[d + 3] += p * v.w;
        }
    }
    const size_t ob = (size_t)(b * 16 + l) * D_MODEL + h * DHEAD;
    #pragma unroll
    for (int d = 0; d < DHEAD; d += 2) {
        const __half h0 = __float2half_rn(o[d]);
        const __half h1 = __float2half_rn(o[d + 1]);
        *(__half2*)(SCH + ob + d) = __halves2half2(h0, h1);
        *(__half2*)(SCL + ob + d) = __halves2half2(
            __float2half_rn(o[d] - __half2float(h0)),
            __float2half_rn(o[d + 1] - __half2float(h1)));
    }
}

// =================== launch ===================
extern "C" void kernel_launch(void* const* d_in, const int* in_sizes, int n_in,
                              void* d_out, int out_size)
{
    const float* x     = (const float*)d_in[0];
    const float* lq_w  = (const float*)d_in[1];
    const float* lq_b  = (const float*)d_in[2];
    const float* lk_w  = (const float*)d_in[3];
    const float* lk_b  = (const float*)d_in[4];
    const float* lv_w  = (const float*)d_in[5];
    const float* lv_b  = (const float*)d_in[6];
    const float* lo_w  = (const float*)d_in[7];
    const float* lo_b  = (const float*)d_in[8];
    const float* pbias = (const float*)d_in[9];
    const float* sq_w  = (const float*)d_in[10];
    const float* sq_b  = (const float*)d_in[11];
    const float* sk_w  = (const float*)d_in[12];
    const float* sk_b  = (const float*)d_in[13];
    const float* sv_w  = (const float*)d_in[14];
    const float* sv_b  = (const float*)d_in[15];
    const float* so_w  = (const float*)d_in[16];
    const float* so_b  = (const float*)d_in[17];
    const float* sum_w = (const float*)d_in[18];
    const float* sum_b = (const float*)d_in[19];
    float* out = (float*)d_out;

    float *QKV2, *SOUT, *PART;
    cudaGetSymbolAddress((void**)&QKV2, g_QKV2);
    cudaGetSymbolAddress((void**)&SOUT, g_SOUT);
    cudaGetSymbolAddress((void**)&PART, g_PART);

    __half *XH, *QH, *KH, *KL, *VH, *VL, *VTH, *VTL, *CH, *WH, *WL;
    __half *S1H, *S1L, *S2H, *S2L, *S3H, *S3L;
    cudaGetSymbolAddress((void**)&XH, g_XH);
    cudaGetSymbolAddress((void**)&QH, g_QH);
    cudaGetSymbolAddress((void**)&KH, g_KH);
    cudaGetSymbolAddress((void**)&KL, g_KL);
    cudaGetSymbolAddress((void**)&VH, g_VH);
    cudaGetSymbolAddress((void**)&VL, g_VL);
    cudaGetSymbolAddress((void**)&VTH, g_VTH);
    cudaGetSymbolAddress((void**)&VTL, g_VTL);
    cudaGetSymbolAddress((void**)&CH, g_CH);
    cudaGetSymbolAddress((void**)&WH, g_WH);
    cudaGetSymbolAddress((void**)&WL, g_WL);
    cudaGetSymbolAddress((void**)&S1H, g_S1H);
    cudaGetSymbolAddress((void**)&S1L, g_S1L);
    cudaGetSymbolAddress((void**)&S2H, g_S2H);
    cudaGetSymbolAddress((void**)&S2L, g_S2L);
    cudaGetSymbolAddress((void**)&S3H, g_S3H);
    cudaGetSymbolAddress((void**)&S3L, g_S3L);

    WP9 wp;
    const float* ws[9] = {lq_w, lk_w, lv_w, lo_w, sum_w, sq_w, sk_w, sv_w, so_w};
    for (int i = 0; i < 9; i++) {
        wp.w[i] = ws[i];
        wp.h[i] = WH + (size_t)i * WSTRIDE;
        wp.l[i] = WL + (size_t)i * WSTRIDE;
    }

    cudaFuncSetAttribute(gemm_smallk_kernel,
                         cudaFuncAttributeMaxDynamicSharedMemorySize, GEMM3_SMEM);
    cudaFuncSetAttribute(gemm1_qkv_kernel,
                         cudaFuncAttributeMaxDynamicSharedMemorySize, GEMM1_SMEM);
    cudaFuncSetAttribute(gemm1_oproj_kernel,
                         cudaFuncAttributeMaxDynamicSharedMemorySize, GEMM1_SMEM);
    cudaFuncSetAttribute(attn_mma_kernel,
                         cudaFuncAttributeMaxDynamicSharedMemorySize, ATT_SMEM);

    static cudaStream_t s2 = nullptr;
    static cudaEvent_t evFork = nullptr, evJoin = nullptr;
    if (s2 == nullptr) {
        cudaStreamCreateWithFlags(&s2, cudaStreamNonBlocking);
        cudaEventCreateWithFlags(&evFork, cudaEventDisableTiming);
        cudaEventCreateWithFlags(&evJoin, cudaEventDisableTiming);
    }

    // fork first: side stream preps its own weights (4..8) and runs the whole
    // small summary path concurrently with the big path.
    cudaEventRecord(evFork, 0);
    cudaStreamWaitEvent(s2, evFork, 0);

    // ---- side stream: weight prep (z=4..8, hi+lo) + small summary path ----
    prep_w_kernel<<<dim3(32, 32, 5), dim3(32, 8), 0, s2>>>(wp, 4);
    meanpool_hl_kernel<<<dim3(NBLK, 4), 256, 0, s2>>>(x, S1H, S1L);
    gemm_smallk_kernel<<<dim3(8, 1, 4), 256, GEMM3_SMEM, s2>>>(S1H, S1L, WH, WL, 4, PART);
    reduce_hl_kernel<<<512, 256, 0, s2>>>(PART, sum_b, S2H, S2L);
    gemm_smallk_kernel<<<dim3(8, 3, 4), 256, GEMM3_SMEM, s2>>>(S2H, S2L, WH, WL, 5, PART);
    reduce3_fp32_kernel<<<dim3(256, 3), 256, 0, s2>>>(PART, sq_b, sk_b, sv_b, QKV2);
    summ_attn_kernel<<<dim3(4, NHEAD), 16, 0, s2>>>(QKV2, S3H, S3L);
    gemm_smallk_kernel<<<dim3(8, 1, 4), 256, GEMM3_SMEM, s2>>>(S3H, S3L, WH, WL, 8, PART);
    reduce_fp32_kernel<<<256, 256, 0, s2>>>(PART, so_b, SOUT);
    cudaEventRecord(evJoin, s2);

    // ---- main stream: big local path (only needs weights 0..3, hi) ----
    prep_w_kernel<<<dim3(32, 32, 4), dim3(32, 8)>>>(wp, 0);
    prep_act_h_kernel<<<16384, 256>>>((const float4*)x, XH, 4194304);
    gemm1_qkv_kernel<<<dim3(24, NTOK / 128), 256, GEMM1_SMEM>>>(
        XH, wp.h[0], lq_b, lk_b, lv_b,
        QH, KH, KL, VH, VL);
    vtrans_kernel<<<dim3(NBLK, 16), 256>>>(VH, VL, VTH, VTL);
    attn_mma_kernel<<<dim3(NBLK, NHEAD), 512, ATT_SMEM>>>(
        QH, KH, KL, VTH, VTL, pbias, CH);

    cudaStreamWaitEvent(0, evJoin, 0);
    gemm1_oproj_kernel<<<dim3(8, NTOK / 128), 256, GEMM1_SMEM>>>(
        CH, wp.h[3], lo_b, SOUT, out);
}

// round 14
// speedup vs baseline: 2.8128x; 1.1573x over previous
#include <cuda_runtime.h>
#include <cuda_fp16.h>
#include <cstdint>

#define D_MODEL 1024
#define NHEAD   16
#define DHEAD   64
#define BSZ     256
#define NTOK    16384
#define NBLK    64
#define NELEM   ((size_t)NTOK * D_MODEL)
#define WSTRIDE (1024 * 1024)
#define PART_STRIDE (128 * 1024)

// ---------------- fp32 scratch (small path) ----------------
__device__ __align__(16) float g_QKV2[3 * NBLK * D_MODEL];   // Q2|K2|V2
__device__ __align__(16) float g_SOUT[NBLK * D_MODEL];
__device__ __align__(16) float g_PART[12 * PART_STRIDE];     // split-K partials

// ---------------- fp16 scratch ----------------
__device__ __align__(16) __half g_XH[NELEM];
__device__ __align__(16) __half g_QH[NELEM];
__device__ __align__(16) __half g_KH[NELEM];
__device__ __align__(16) __half g_VH[NELEM];
__device__ __align__(16) __half g_VTH[NELEM];   // [blk][dim][tok]
__device__ __align__(16) __half g_CH[NELEM];
__device__ __align__(16) __half g_WH[9][WSTRIDE];  // transposed [N][K] hi
__device__ __align__(16) __half g_WL[9][WSTRIDE];  // transposed [N][K] lo (3-term small path only)
// per-stage small activations (distinct buffers -> replay-deterministic)
__device__ __align__(16) __half g_S1H[128 * 1024];
__device__ __align__(16) __half g_S1L[128 * 1024];
__device__ __align__(16) __half g_S2H[128 * 1024];
__device__ __align__(16) __half g_S2L[128 * 1024];
__device__ __align__(16) __half g_S3H[128 * 1024];
__device__ __align__(16) __half g_S3L[128 * 1024];

// =================== helpers ===================
__device__ __forceinline__ uint32_t smem_u32(const void* p) {
    uint32_t a;
    asm("{ .reg .u64 t; cvta.to.shared.u64 t, %1; cvt.u32.u64 %0, t; }" : "=r"(a) : "l"(p));
    return a;
}
#define SWZ128(off) ((off) ^ (((off) >> 3) & 0x70))
#define SWZ512(off) ((off) ^ (((off) >> 5) & 0x70))

__device__ __forceinline__ void cp16(uint32_t dst, const void* src) {
    asm volatile("cp.async.cg.shared.global [%0], [%1], 16;" :: "r"(dst), "l"(src));
}
__device__ __forceinline__ void cp_commit() {
    asm volatile("cp.async.commit_group;" ::: "memory");
}
__device__ __forceinline__ void ldsm_x4(uint32_t addr, uint32_t r[4]) {
    asm volatile("ldmatrix.sync.aligned.m8n8.x4.shared.b16 {%0,%1,%2,%3}, [%4];"
        : "=r"(r[0]), "=r"(r[1]), "=r"(r[2]), "=r"(r[3]) : "r"(addr));
}
__device__ __forceinline__ void mma_f16(float c[4], const uint32_t a[4],
                                        uint32_t b0, uint32_t b1) {
    asm volatile(
        "mma.sync.aligned.m16n8k16.row.col.f32.f16.f16.f32 "
        "{%0,%1,%2,%3}, {%4,%5,%6,%7}, {%8,%9}, {%0,%1,%2,%3};"
        : "+f"(c[0]), "+f"(c[1]), "+f"(c[2]), "+f"(c[3])
        : "r"(a[0]), "r"(a[1]), "r"(a[2]), "r"(a[3]), "r"(b0), "r"(b1));
}
__device__ __forceinline__ uint32_t pack_f16x2(float lo, float hi) {
    uint32_t r;
    asm("cvt.rn.f16x2.f32 %0, %1, %2;" : "=r"(r) : "f"(hi), "f"(lo));
    return r;
}

// =================== prep kernels ===================
__global__ void prep_act_h_kernel(const float4* __restrict__ A,
                                  __half* __restrict__ H, int nquads)
{
    const int i = blockIdx.x * blockDim.x + threadIdx.x;
    if (i >= nquads) return;
    const float4 v = A[i];
    *(__half2*)(H + (size_t)i * 4)     = __halves2half2(__float2half_rn(v.x), __float2half_rn(v.y));
    *(__half2*)(H + (size_t)i * 4 + 2) = __halves2half2(__float2half_rn(v.z), __float2half_rn(v.w));
}

struct WP9 {
    const float* w[9];
    __half* h[9];
    __half* l[9];
};
// zoff splits the 9 weights across streams: main does [0,4) (hi only), side does [4,9) (hi+lo)
__global__ void prep_w_kernel(WP9 wp, int zoff)
{
    __shared__ float t[32][33];
    const int z  = blockIdx.z + zoff;
    const float* W = wp.w[z];
    __half* H = wp.h[z];
    __half* L = wp.l[z];
    const int bx = blockIdx.x;
    const int by = blockIdx.y;
    const int tx = threadIdx.x;
    const int ty = threadIdx.y;
    #pragma unroll
    for (int r = 0; r < 32; r += 8)
        t[ty + r][tx] = W[(size_t)(by * 32 + ty + r) * 1024 + bx * 32 + tx];
    __syncthreads();
    #pragma unroll
    for (int r = 0; r < 32; r += 8) {
        const float v = t[tx][ty + r];
        const __half h = __float2half_rn(v);
        const size_t o = (size_t)(bx * 32 + ty + r) * 1024 + by * 32 + tx;
        H[o] = h;
        if (z >= 4) L[o] = __float2half_rn(v - __half2float(h));
    }
}

// =================== fragment index helpers ===================
#define FRAG_IDX()                                                            \
    const int arow_in = (lane & 7) + ((lane >> 3) & 1) * 8;                   \
    const int acolx   = (lane >> 4) * 16;                                     \
    const int brow_in = (lane & 7) + ((lane >> 4) & 1) * 8;                   \
    const int bcolx   = ((lane >> 3) & 1) * 16;

#define BUF3_BYTES 65536
#define GEMM3_SMEM (2 * BUF3_BYTES)

#define ISSUE3(ic, buf) do {                                                  \
    const uint32_t sbase = sb + (buf) * BUF3_BYTES;                           \
    const size_t coff = (size_t)(ic) * 128 + cb;                              \
    _Pragma("unroll")                                                         \
    for (int i = 0; i < 4; i++) {                                             \
        const size_t go = (size_t)(rcp + i * 32) * 2048 + coff;               \
        cp16(sbase + dsw[i],          gAh + go);                              \
        cp16(sbase + 16384 + dsw[i],  gAl + go);                              \
        cp16(sbase + 32768 + dsw[i],  gBh + go);                              \
        cp16(sbase + 49152 + dsw[i],  gBl + go);                              \
    }                                                                         \
    cp_commit();                                                              \
} while (0)

// =================== split-K 3-term small GEMM -> fp32 partials ===================
__global__ __launch_bounds__(256, 1) void gemm_smallk_kernel(
    const __half* __restrict__ Ah, const __half* __restrict__ Al,
    const __half* __restrict__ WHb, const __half* __restrict__ WLb,
    int zbase, float* __restrict__ P)
{
    extern __shared__ char smem[];
    const uint32_t sb = smem_u32(smem);
    const int tid  = threadIdx.x;
    const int lane = tid & 31;
    const int wid  = tid >> 5;
    const int wm   = wid & 3;
    const int wn   = wid >> 2;
    const int bn = blockIdx.x;
    const int zi = blockIdx.y;
    const int ks = blockIdx.z;
    const int rcp = tid >> 3;
    const int cb  = (tid & 7) << 4;
    uint32_t dsw[4];
    #pragma unroll
    for (int i = 0; i < 4; i++) dsw[i] = SWZ128((uint32_t)((rcp + i * 32) * 128 + cb));
    FRAG_IDX();

    const char* gAh = (const char*)Ah;
    const char* gAl = (const char*)Al;
    const char* gBh = (const char*)(WHb + (size_t)(zbase + zi) * WSTRIDE + (size_t)bn * 128 * 1024);
    const char* gBl = (const char*)(WLb + (size_t)(zbase + zi) * WSTRIDE + (size_t)bn * 128 * 1024);

    float c[2][8][4];
    #pragma unroll
    for (int mt = 0; mt < 2; mt++)
        #pragma unroll
        for (int nb = 0; nb < 8; nb++)
            #pragma unroll
            for (int j = 0; j < 4; j++) c[mt][nb][j] = 0.f;

    const int ic0 = ks * 4;
    ISSUE3(ic0, 0);
    #pragma unroll 1
    for (int it = 0; it < 4; it++) {
        const int cur = it & 1;
        if (it < 3) ISSUE3(ic0 + it + 1, cur ^ 1);
        if (it < 3) asm volatile("cp.async.wait_group 1;" ::: "memory");
        else        asm volatile("cp.async.wait_group 0;" ::: "memory");
        __syncthreads();
        const uint32_t base = sb + cur * BUF3_BYTES;
        #pragma unroll
        for (int kk = 0; kk < 4; kk++) {
            const uint32_t kb = kk * 32;
            uint32_t ah[2][4], al_[2][4];
            #pragma unroll
            for (int mt = 0; mt < 2; mt++) {
                const uint32_t off =
                    SWZ128((uint32_t)((wm * 32 + mt * 16 + arow_in) * 128 + kb + acolx));
                ldsm_x4(base + off,          ah[mt]);
                ldsm_x4(base + 16384 + off,  al_[mt]);
            }
            uint32_t bh[4][4], bl[4][4];
            #pragma unroll
            for (int p = 0; p < 4; p++) {
                const uint32_t off =
                    SWZ128((uint32_t)((wn * 64 + p * 16 + brow_in) * 128 + kb + bcolx));
                ldsm_x4(base + 32768 + off, bh[p]);
                ldsm_x4(base + 49152 + off, bl[p]);
            }
            #pragma unroll
            for (int mt = 0; mt < 2; mt++) {
                #pragma unroll
                for (int p = 0; p < 4; p++) {
                    mma_f16(c[mt][2 * p],     ah[mt],  bh[p][0], bh[p][1]);
                    mma_f16(c[mt][2 * p],     ah[mt],  bl[p][0], bl[p][1]);
                    mma_f16(c[mt][2 * p],     al_[mt], bh[p][0], bh[p][1]);
                    mma_f16(c[mt][2 * p + 1], ah[mt],  bh[p][2], bh[p][3]);
                    mma_f16(c[mt][2 * p + 1], ah[mt],  bl[p][2], bl[p][3]);
                    mma_f16(c[mt][2 * p + 1], al_[mt], bh[p][2], bh[p][3]);
                }
            }
        }
        __syncthreads();
    }

    float* Pp = P + (size_t)(zi * 4 + ks) * PART_STRIDE;
    const int row_base = wm * 32 + (lane >> 2);
    const int col_base = bn * 128 + wn * 64 + 2 * (lane & 3);
    #pragma unroll
    for (int mt = 0; mt < 2; mt++) {
        #pragma unroll
        for (int hh = 0; hh < 2; hh++) {
            const int row = row_base + mt * 16 + hh * 8;
            #pragma unroll
            for (int nb = 0; nb < 8; nb++) {
                const int col = col_base + nb * 8;
                float2 o;
                o.x = c[mt][nb][hh * 2 + 0];
                o.y = c[mt][nb][hh * 2 + 1];
                *(float2*)(Pp + (size_t)row * 1024 + col) = o;
            }
        }
    }
}

// ---- reduces ----
__global__ void reduce3_fp32_kernel(const float* __restrict__ P,
                                    const float* __restrict__ b0,
                                    const float* __restrict__ b1,
                                    const float* __restrict__ b2,
                                    float* __restrict__ C)
{
    const int zi  = blockIdx.y;
    const int idx = blockIdx.x * 256 + threadIdx.x;
    const float* Pp = P + (size_t)zi * 4 * PART_STRIDE;
    const float s = Pp[idx] + Pp[idx + PART_STRIDE] + Pp[idx + 2 * PART_STRIDE] + Pp[idx + 3 * PART_STRIDE];
    const float* bias = (zi == 0) ? b0 : (zi == 1) ? b1 : b2;
    C[(size_t)zi * NBLK * D_MODEL + idx] = s + bias[idx & 1023];
}

__global__ void reduce_fp32_kernel(const float* __restrict__ P,
                                   const float* __restrict__ bias,
                                   float* __restrict__ C)
{
    const int idx = blockIdx.x * 256 + threadIdx.x;
    const float s = P[idx] + P[idx + PART_STRIDE] + P[idx + 2 * PART_STRIDE] + P[idx + 3 * PART_STRIDE];
    C[idx] = s + bias[idx & 1023];
}

__global__ void reduce_hl_kernel(const float* __restrict__ P,
                                 const float* __restrict__ bias,
                                 __half* __restrict__ H, __half* __restrict__ L)
{
    const int idx = blockIdx.x * 256 + threadIdx.x;
    const float v = P[idx] + P[idx + PART_STRIDE] + P[idx + 2 * PART_STRIDE] + P[idx + 3 * PART_STRIDE]
                  + bias[idx & 1023];
    const __half h = __float2half_rn(v);
    H[idx] = h;
    L[idx] = __float2half_rn(v - __half2float(h));
}

// =================== 1-term GEMM mainloop (big path): C ~= Ah * Bh ===================
#define BUF1_BYTES 32768
#define GEMM1_SMEM (2 * BUF1_BYTES)

#define ISSUE1(ic, buf) do {                                                  \
    const uint32_t sbase = sb + (buf) * BUF1_BYTES;                           \
    const size_t coff = (size_t)(ic) * 128 + cb;                              \
    _Pragma("unroll")                                                         \
    for (int i = 0; i < 4; i++) {                                             \
        const size_t go = (size_t)(rcp + i * 32) * 2048 + coff;               \
        cp16(sbase + dsw[i],          gAh + go);                              \
        cp16(sbase + 16384 + dsw[i],  gBh + go);                              \
    }                                                                         \
    cp_commit();                                                              \
} while (0)

#define GEMM1_BODY()                                                          \
    extern __shared__ char smem[];                                            \
    const uint32_t sb = smem_u32(smem);                                       \
    const int tid  = threadIdx.x;                                             \
    const int lane = tid & 31;                                                \
    const int wid  = tid >> 5;                                                \
    const int wm   = wid & 3;                                                 \
    const int wn   = wid >> 2;                                                \
    const int bn = blockIdx.x;                                                \
    const int bm = blockIdx.y;                                                \
    const int rcp = tid >> 3;                                                 \
    const int cb  = (tid & 7) << 4;                                           \
    uint32_t dsw[4];                                                          \
    _Pragma("unroll")                                                         \
    for (int i = 0; i < 4; i++) dsw[i] = SWZ128((uint32_t)((rcp + i * 32) * 128 + cb)); \
    FRAG_IDX();                                                               \
    float c[2][8][4];                                                         \
    _Pragma("unroll")                                                         \
    for (int mt = 0; mt < 2; mt++)                                            \
        _Pragma("unroll")                                                     \
        for (int nb = 0; nb < 8; nb++)                                        \
            _Pragma("unroll")                                                 \
            for (int j = 0; j < 4; j++) c[mt][nb][j] = 0.f;                   \
    ISSUE1(0, 0);                                                             \
    _Pragma("unroll 1")                                                       \
    for (int ic = 0; ic < 16; ic++) {                                         \
        const int cur = ic & 1;                                               \
        if (ic < 15) ISSUE1(ic + 1, cur ^ 1);                                 \
        if (ic < 15) asm volatile("cp.async.wait_group 1;" ::: "memory");     \
        else         asm volatile("cp.async.wait_group 0;" ::: "memory");     \
        __syncthreads();                                                      \
        const uint32_t base = sb + cur * BUF1_BYTES;                          \
        _Pragma("unroll")                                                     \
        for (int kk = 0; kk < 4; kk++) {                                      \
            const uint32_t kb = kk * 32;                                      \
            uint32_t ah[2][4];                                                \
            _Pragma("unroll")                                                 \
            for (int mt = 0; mt < 2; mt++) {                                  \
                const uint32_t off =                                          \
                    SWZ128((uint32_t)((wm * 32 + mt * 16 + arow_in) * 128 + kb + acolx)); \
                ldsm_x4(base + off, ah[mt]);                                  \
            }                                                                 \
            uint32_t bh[4][4];                                                \
            _Pragma("unroll")                                                 \
            for (int p = 0; p < 4; p++) {                                     \
                const uint32_t off =                                          \
                    SWZ128((uint32_t)((wn * 64 + p * 16 + brow_in) * 128 + kb + bcolx)); \
                ldsm_x4(base + 16384 + off, bh[p]);                           \
            }                                                                 \
            _Pragma("unroll")                                                 \
            for (int mt = 0; mt < 2; mt++) {                                  \
                _Pragma("unroll")                                             \
                for (int p = 0; p < 4; p++) {                                 \
                    mma_f16(c[mt][2 * p],     ah[mt], bh[p][0], bh[p][1]);    \
                    mma_f16(c[mt][2 * p + 1], ah[mt], bh[p][2], bh[p][3]);    \
                }                                                             \
            }                                                                 \
        }                                                                     \
        __syncthreads();                                                      \
    }

// ---- fused QKV: 1-term fp16, hi-only outputs ----
__global__ __launch_bounds__(256, 2) void gemm1_qkv_kernel(
    const __half* __restrict__ Ah, const __half* __restrict__ Bh,
    const float* __restrict__ bq, const float* __restrict__ bk, const float* __restrict__ bv,
    __half* __restrict__ QH, __half* __restrict__ KH, __half* __restrict__ VH)
{
    const char* gAh = (const char*)(Ah + (size_t)(blockIdx.y * 128) * 1024);
    const char* gBh = (const char*)(Bh + (size_t)(blockIdx.x * 128) * 1024);
    GEMM1_BODY();

    const int tensor = bn >> 3;
    const float* bias = (tensor == 0) ? bq : (tensor == 1) ? bk : bv;
    __half* OH = (tensor == 0) ? QH : (tensor == 1) ? KH : VH;

    const int row_base = bm * 128 + wm * 32 + (lane >> 2);
    const int col_base = (bn & 7) * 128 + wn * 64 + 2 * (lane & 3);
    #pragma unroll
    for (int mt = 0; mt < 2; mt++) {
        #pragma unroll
        for (int hh = 0; hh < 2; hh++) {
            const int row = row_base + mt * 16 + hh * 8;
            #pragma unroll
            for (int nb = 0; nb < 8; nb++) {
                const int col = col_base + nb * 8;
                const float v0 = c[mt][nb][hh * 2 + 0] + bias[col + 0];
                const float v1 = c[mt][nb][hh * 2 + 1] + bias[col + 1];
                *(__half2*)(OH + (size_t)row * 1024 + col) = __halves2half2(
                    __float2half_rn(v0), __float2half_rn(v1));
            }
        }
    }
}

// ---- o-proj: 1-term fp16, fp32 out + bias + summary add ----
__global__ __launch_bounds__(256, 2) void gemm1_oproj_kernel(
    const __half* __restrict__ Ah, const __half* __restrict__ Bh,
    const float* __restrict__ bias, const float* __restrict__ addBlk,
    float* __restrict__ C)
{
    const char* gAh = (const char*)(Ah + (size_t)(blockIdx.y * 128) * 1024);
    const char* gBh = (const char*)(Bh + (size_t)(blockIdx.x * 128) * 1024);
    GEMM1_BODY();

    const int row_base = bm * 128 + wm * 32 + (lane >> 2);
    const int col_base = bn * 128 + wn * 64 + 2 * (lane & 3);
    #pragma unroll
    for (int mt = 0; mt < 2; mt++) {
        #pragma unroll
        for (int hh = 0; hh < 2; hh++) {
            const int row = row_base + mt * 16 + hh * 8;
            const int rb = row >> 8;
            #pragma unroll
            for (int nb = 0; nb < 8; nb++) {
                const int col = col_base + nb * 8;
                float2 o;
                o.x = c[mt][nb][hh * 2 + 0] + bias[col + 0] + addBlk[(size_t)rb * 1024 + col + 0];
                o.y = c[mt][nb][hh * 2 + 1] + bias[col + 1] + addBlk[(size_t)rb * 1024 + col + 1];
                *(float2*)(C + (size_t)row * 1024 + col) = o;
            }
        }
    }
}

// =================== V transpose (hi only) ===================
__global__ __launch_bounds__(256) void vtrans_kernel(
    const __half* __restrict__ VH, __half* __restrict__ VTH)
{
    __shared__ __half t[256][72];
    const int blk = blockIdx.x;
    const int dt  = blockIdx.y;
    const int tid = threadIdx.x;
    #pragma unroll
    for (int it = 0; it < 8; it++) {
        const int task = it * 256 + tid;
        const int row = task >> 3;
        const int dc  = (task & 7) * 8;
        *(uint4*)&t[row][dc] =
            *(const uint4*)(VH + ((size_t)(blk * 256 + row)) * 1024 + dt * 64 + dc);
    }
    __syncthreads();
    #pragma unroll
    for (int it = 0; it < 8; it++) {
        const int task = it * 256 + tid;
        const int d  = task >> 5;
        const int tc = (task & 31) * 8;
        __half tmp[8];
        #pragma unroll
        for (int j = 0; j < 8; j++) tmp[j] = t[tc + j][d];
        *(uint4*)(VTH + ((size_t)(blk * 1024) + dt * 64 + d) * 256 + tc) = *(uint4*)tmp;
    }
}

// =================== HMMA local attention (plain fp16, fp32 accum) ===================
// Phase 1: S = Qh Kh^T.  Phase 2: O = P Vh.
#define ATT_SMEM (3 * 32768)

__global__ __launch_bounds__(512, 1) void attn_mma_kernel(
    const __half* __restrict__ QH, const __half* __restrict__ KH,
    const __half* __restrict__ VTH,
    const float* __restrict__ bias,
    __half* __restrict__ CH)
{
    extern __shared__ char smem[];
    const uint32_t sb = smem_u32(smem);
    const int blk = blockIdx.x;
    const int h   = blockIdx.y;
    const int tid = threadIdx.x;
    const int lane = tid & 31;
    const int w    = tid >> 5;

    const uint32_t QHs = sb;
    const uint32_t KHs = sb + 32768;
    const uint32_t VHs = sb + 65536;

    {
        const char* qh0 = (const char*)(QH + ((size_t)blk * 256) * 1024 + h * 64);
        const char* kh0 = (const char*)(KH + ((size_t)blk * 256) * 1024 + h * 64);
        #pragma unroll
        for (int i = 0; i < 4; i++) {
            const int cidx = tid + i * 512;
            const int row = cidx >> 3;
            const int cbo = (cidx & 7) << 4;
            const uint32_t d = SWZ128((uint32_t)(row * 128 + cbo));
            const size_t go = (size_t)row * 2048 + cbo;
            cp16(QHs + d, qh0 + go);
            cp16(KHs + d, kh0 + go);
        }
        const char* vh0 = (const char*)(VTH + ((size_t)blk * 1024 + h * 64) * 256);
        #pragma unroll
        for (int i = 0; i < 4; i++) {
            const int cidx = tid + i * 512;
            const int row = cidx >> 5;
            const int cbo = (cidx & 31) << 4;
            const uint32_t d = SWZ512((uint32_t)(row * 512 + cbo));
            const size_t go = (size_t)row * 512 + cbo;
            cp16(VHs + d, vh0 + go);
        }
        cp_commit();
        asm volatile("cp.async.wait_group 0;" ::: "memory");
        __syncthreads();
    }

    const int arow = (lane & 7) + ((lane >> 3) & 1) * 8;
    const int acol = (lane >> 4) * 16;
    const int brow = (lane & 7) + ((lane >> 4) & 1) * 8;
    const int bcol = ((lane >> 3) & 1) * 16;

    float s[32][4];
    #pragma unroll
    for (int j = 0; j < 32; j++)
        #pragma unroll
        for (int q = 0; q < 4; q++) s[j][q] = 0.f;

    #pragma unroll
    for (int kk = 0; kk < 4; kk++) {
        const uint32_t kb = kk * 32;
        uint32_t qh[4];
        const uint32_t aoff = SWZ128((uint32_t)((w * 16 + arow) * 128 + kb + acol));
        ldsm_x4(QHs + aoff, qh);
        #pragma unroll
        for (int p = 0; p < 16; p++) {
            uint32_t bh[4];
            const uint32_t boff = SWZ128((uint32_t)((p * 16 + brow) * 128 + kb + bcol));
            ldsm_x4(KHs + boff, bh);
            mma_f16(s[2 * p],     qh, bh[0], bh[1]);
            mma_f16(s[2 * p + 1], qh, bh[2], bh[3]);
        }
    }

    const int r0 = w * 16 + (lane >> 2);
    const int cq = (lane & 3) * 2;
    const float* br0 = bias + ((size_t)h * 256 + r0) * 256;
    const float* br1 = br0 + 8 * 256;

    float m0 = -1e30f, m1 = -1e30f;
    #pragma unroll
    for (int j = 0; j < 32; j++) {
        const float2 b0 = *(const float2*)(br0 + j * 8 + cq);
        const float2 b1 = *(const float2*)(br1 + j * 8 + cq);
        s[j][0] = s[j][0] * 0.125f + b0.x;
        s[j][1] = s[j][1] * 0.125f + b0.y;
        s[j][2] = s[j][2] * 0.125f + b1.x;
        s[j][3] = s[j][3] * 0.125f + b1.y;
        m0 = fmaxf(m0, fmaxf(s[j][0], s[j][1]));
        m1 = fmaxf(m1, fmaxf(s[j][2], s[j][3]));
    }
    #pragma unroll
    for (int msk = 1; msk <= 2; msk <<= 1) {
        m0 = fmaxf(m0, __shfl_xor_sync(0xffffffffu, m0, msk));
        m1 = fmaxf(m1, __shfl_xor_sync(0xffffffffu, m1, msk));
    }
    float l0 = 0.f, l1 = 0.f;
    #pragma unroll
    for (int j = 0; j < 32; j++) {
        s[j][0] = __expf(s[j][0] - m0);
        s[j][1] = __expf(s[j][1] - m0);
        s[j][2] = __expf(s[j][2] - m1);
        s[j][3] = __expf(s[j][3] - m1);
        l0 += s[j][0] + s[j][1];
        l1 += s[j][2] + s[j][3];
    }
    #pragma unroll
    for (int msk = 1; msk <= 2; msk <<= 1) {
        l0 += __shfl_xor_sync(0xffffffffu, l0, msk);
        l1 += __shfl_xor_sync(0xffffffffu, l1, msk);
    }

    float o[8][4];
    #pragma unroll
    for (int j = 0; j < 8; j++)
        #pragma unroll
        for (int q = 0; q < 4; q++) o[j][q] = 0.f;

    #pragma unroll
    for (int kt = 0; kt < 16; kt++) {
        uint32_t pah[4];
        #pragma unroll
        for (int half_ = 0; half_ < 2; half_++) {
            const float* sv = s[2 * kt + half_];
            pah[2 * half_ + 0] = pack_f16x2(sv[0], sv[1]);
            pah[2 * half_ + 1] = pack_f16x2(sv[2], sv[3]);
        }
        #pragma unroll
        for (int nd = 0; nd < 4; nd++) {
            uint32_t bh[4];
            const uint32_t boff = SWZ512((uint32_t)((nd * 16 + brow) * 512 + kt * 32 + bcol));
            ldsm_x4(VHs + boff, bh);
            mma_f16(o[2 * nd],     pah, bh[0], bh[1]);
            mma_f16(o[2 * nd + 1], pah, bh[2], bh[3]);
        }
    }

    const float inv0 = 1.f / l0;
    const float inv1 = 1.f / l1;
    const size_t row0 = (size_t)blk * 256 + r0;
    #pragma unroll
    for (int j = 0; j < 8; j++) {
        const int col = h * 64 + j * 8 + cq;
        *(__half2*)(CH + row0 * 1024 + col) = __halves2half2(
            __float2half_rn(o[j][0] * inv0), __float2half_rn(o[j][1] * inv0));
        *(__half2*)(CH + (row0 + 8) * 1024 + col) = __halves2half2(
            __float2half_rn(o[j][2] * inv1), __float2half_rn(o[j][3] * inv1));
    }
}

// =================== mean pool -> split fp16 directly ===================
__global__ void meanpool_hl_kernel(const float* __restrict__ x,
                                   __half* __restrict__ H, __half* __restrict__ L)
{
    const int blk = blockIdx.x;
    const int c   = blockIdx.y * 256 + threadIdx.x;
    const float* base = x + (size_t)blk * BSZ * D_MODEL + c;
    float s = 0.f;
    #pragma unroll 4
    for (int r = 0; r < BSZ; r++) s += base[(size_t)r * D_MODEL];
    const float v = s * (1.0f / BSZ);
    const __half h = __float2half_rn(v);
    H[blk * D_MODEL + c] = h;
    L[blk * D_MODEL + c] = __float2half_rn(v - __half2float(h));
}

// =================== summary attention (fp32 in, split fp16 out) ===================
__global__ void summ_attn_kernel(
    const float* __restrict__ QKV2,
    __half* __restrict__ SCH, __half* __restrict__ SCL)
{
    const float* Q2 = QKV2;
    const float* K2 = QKV2 + (size_t)NBLK * D_MODEL;
    const float* V2 = QKV2 + (size_t)2 * NBLK * D_MODEL;
    const int b = blockIdx.x;
    const int h = blockIdx.y;
    const int l = threadIdx.x;

    const float* qr = Q2 + (size_t)(b * 16 + l) * D_MODEL + h * DHEAD;
    float q[DHEAD];
    #pragma unroll
    for (int d = 0; d < DHEAD; d += 4) {
        const float4 v = *(const float4*)(qr + d);
        q[d] = v.x; q[d + 1] = v.y; q[d + 2] = v.z; q[d + 3] = v.w;
    }

    float s[16];
    float m = -1e30f;
    for (int j = 0; j < 16; j++) {
        const float* kr = K2 + (size_t)(b * 16 + j) * D_MODEL + h * DHEAD;
        float a = 0.f;
        #pragma unroll
        for (int d = 0; d < DHEAD; d += 4) {
            const float4 v = *(const float4*)(kr + d);
            a += q[d] * v.x + q[d + 1] * v.y + q[d + 2] * v.z + q[d + 3] * v.w;
        }
        s[j] = a * 0.125f;
        m = fmaxf(m, s[j]);
    }
    float lsum = 0.f;
    for (int j = 0; j < 16; j++) { s[j] = __expf(s[j] - m); lsum += s[j]; }
    const float inv = 1.f / lsum;

    float o[DHEAD];
    #pragma unroll
    for (int d = 0; d < DHEAD; d++) o[d] = 0.f;
    for (int j = 0; j < 16; j++) {
        const float* vr = V2 + (size_t)(b * 16 + j) * D_MODEL + h * DHEAD;
        const float p = s[j] * inv;
        #pragma unroll
        for (int d = 0; d < DHEAD; d += 4) {
            const float4 v = *(const float4*)(vr + d);
            o[d] += p * v.x; o[d + 1] += p * v.y; o[d + 2] += p * v.z; o[d + 3] += p * v.w;
        }
    }
    const size_t ob = (size_t)(b * 16 + l) * D_MODEL + h * DHEAD;
    #pragma unroll
    for (int d = 0; d < DHEAD; d += 2) {
        const __half h0 = __float2half_rn(o[d]);
        const __half h1 = __float2half_rn(o[d + 1]);
        *(__half2*)(SCH + ob + d) = __halves2half2(h0, h1);
        *(__half2*)(SCL + ob + d) = __halves2half2(
            __float2half_rn(o[d] - __half2float(h0)),
            __float2half_rn(o[d + 1] - __half2float(h1)));
    }
}

// =================== launch ===================
extern "C" void kernel_launch(void* const* d_in, const int* in_sizes, int n_in,
                              void* d_out, int out_size)
{
    const float* x     = (const float*)d_in[0];
    const float* lq_w  = (const float*)d_in[1];
    const float* lq_b  = (const float*)d_in[2];
    const float* lk_w  = (const float*)d_in[3];
    const float* lk_b  = (const float*)d_in[4];
    const float* lv_w  = (const float*)d_in[5];
    const float* lv_b  = (const float*)d_in[6];
    const float* lo_w  = (const float*)d_in[7];
    const float* lo_b  = (const float*)d_in[8];
    const float* pbias = (const float*)d_in[9];
    const float* sq_w  = (const float*)d_in[10];
    const float* sq_b  = (const float*)d_in[11];
    const float* sk_w  = (const float*)d_in[12];
    const float* sk_b  = (const float*)d_in[13];
    const float* sv_w  = (const float*)d_in[14];
    const float* sv_b  = (const float*)d_in[15];
    const float* so_w  = (const float*)d_in[16];
    const float* so_b  = (const float*)d_in[17];
    const float* sum_w = (const float*)d_in[18];
    const float* sum_b = (const float*)d_in[19];
    float* out = (float*)d_out;

    float *QKV2, *SOUT, *PART;
    cudaGetSymbolAddress((void**)&QKV2, g_QKV2);
    cudaGetSymbolAddress((void**)&SOUT, g_SOUT);
    cudaGetSymbolAddress((void**)&PART, g_PART);

    __half *XH, *QH, *KH, *VH, *VTH, *CH, *WH, *WL;
    __half *S1H, *S1L, *S2H, *S2L, *S3H, *S3L;
    cudaGetSymbolAddress((void**)&XH, g_XH);
    cudaGetSymbolAddress((void**)&QH, g_QH);
    cudaGetSymbolAddress((void**)&KH, g_KH);
    cudaGetSymbolAddress((void**)&VH, g_VH);
    cudaGetSymbolAddress((void**)&VTH, g_VTH);
    cudaGetSymbolAddress((void**)&CH, g_CH);
    cudaGetSymbolAddress((void**)&WH, g_WH);
    cudaGetSymbolAddress((void**)&WL, g_WL);
    cudaGetSymbolAddress((void**)&S1H, g_S1H);
    cudaGetSymbolAddress((void**)&S1L, g_S1L);
    cudaGetSymbolAddress((void**)&S2H, g_S2H);
    cudaGetSymbolAddress((void**)&S2L, g_S2L);
    cudaGetSymbolAddress((void**)&S3H, g_S3H);
    cudaGetSymbolAddress((void**)&S3L, g_S3L);

    WP9 wp;
    const float* ws[9] = {lq_w, lk_w, lv_w, lo_w, sum_w, sq_w, sk_w, sv_w, so_w};
    for (int i = 0; i < 9; i++) {
        wp.w[i] = ws[i];
        wp.h[i] = WH + (size_t)i * WSTRIDE;
        wp.l[i] = WL + (size_t)i * WSTRIDE;
    }

    cudaFuncSetAttribute(gemm_smallk_kernel,
                         cudaFuncAttributeMaxDynamicSharedMemorySize, GEMM3_SMEM);
    cudaFuncSetAttribute(gemm1_qkv_kernel,
                         cudaFuncAttributeMaxDynamicSharedMemorySize, GEMM1_SMEM);
    cudaFuncSetAttribute(gemm1_oproj_kernel,
                         cudaFuncAttributeMaxDynamicSharedMemorySize, GEMM1_SMEM);
    cudaFuncSetAttribute(attn_mma_kernel,
                         cudaFuncAttributeMaxDynamicSharedMemorySize, ATT_SMEM);

    static cudaStream_t s2 = nullptr;
    static cudaEvent_t evFork = nullptr, evJoin = nullptr;
    if (s2 == nullptr) {
        cudaStreamCreateWithFlags(&s2, cudaStreamNonBlocking);
        cudaEventCreateWithFlags(&evFork, cudaEventDisableTiming);
        cudaEventCreateWithFlags(&evJoin, cudaEventDisableTiming);
    }

    // fork: side stream preps its weights (4..8) and runs the small path.
    cudaEventRecord(evFork, 0);
    cudaStreamWaitEvent(s2, evFork, 0);

    // ---- side stream: weight prep (z=4..8, hi+lo) + small summary path ----
    prep_w_kernel<<<dim3(32, 32, 5), dim3(32, 8), 0, s2>>>(wp, 4);
    meanpool_hl_kernel<<<dim3(NBLK, 4), 256, 0, s2>>>(x, S1H, S1L);
    gemm_smallk_kernel<<<dim3(8, 1, 4), 256, GEMM3_SMEM, s2>>>(S1H, S1L, WH, WL, 4, PART);
    reduce_hl_kernel<<<512, 256, 0, s2>>>(PART, sum_b, S2H, S2L);
    gemm_smallk_kernel<<<dim3(8, 3, 4), 256, GEMM3_SMEM, s2>>>(S2H, S2L, WH, WL, 5, PART);
    reduce3_fp32_kernel<<<dim3(256, 3), 256, 0, s2>>>(PART, sq_b, sk_b, sv_b, QKV2);
    summ_attn_kernel<<<dim3(4, NHEAD), 16, 0, s2>>>(QKV2, S3H, S3L);
    gemm_smallk_kernel<<<dim3(8, 1, 4), 256, GEMM3_SMEM, s2>>>(S3H, S3L, WH, WL, 8, PART);
    reduce_fp32_kernel<<<256, 256, 0, s2>>>(PART, so_b, SOUT);
    cudaEventRecord(evJoin, s2);

    // ---- main stream: big local path (weights 0..3, hi only) ----
    prep_w_kernel<<<dim3(32, 32, 4), dim3(32, 8)>>>(wp, 0);
    prep_act_h_kernel<<<16384, 256>>>((const float4*)x, XH, 4194304);
    gemm1_qkv_kernel<<<dim3(24, NTOK / 128), 256, GEMM1_SMEM>>>(
        XH, wp.h[0], lq_b, lk_b, lv_b, QH, KH, VH);
    vtrans_kernel<<<dim3(NBLK, 16), 256>>>(VH, VTH);
    attn_mma_kernel<<<dim3(NBLK, NHEAD), 512, ATT_SMEM>>>(
        QH, KH, VTH, pbias, CH);

    cudaStreamWaitEvent(0, evJoin, 0);
    gemm1_oproj_kernel<<<dim3(8, NTOK / 128), 256, GEMM1_SMEM>>>(
        CH, wp.h[3], lo_b, SOUT, out);
}

// round 15
// speedup vs baseline: 2.8751x; 1.0221x over previous
#include <cuda_runtime.h>
#include <cuda_fp16.h>
#include <cstdint>

#define D_MODEL 1024
#define NHEAD   16
#define DHEAD   64
#define BSZ     256
#define NTOK    16384
#define NBLK    64
#define NELEM   ((size_t)NTOK * D_MODEL)
#define WSTRIDE (1024 * 1024)
#define PART_STRIDE (128 * 1024)

// ---------------- fp32 scratch (small path) ----------------
__device__ __align__(16) float g_QKV2[3 * NBLK * D_MODEL];   // Q2|K2|V2
__device__ __align__(16) float g_SOUT[NBLK * D_MODEL];
__device__ __align__(16) float g_PART[12 * PART_STRIDE];     // split-K partials

// ---------------- fp16 scratch ----------------
__device__ __align__(16) __half g_XH[NELEM];
__device__ __align__(16) __half g_QH[NELEM];
__device__ __align__(16) __half g_KH[NELEM];
__device__ __align__(16) __half g_VH[NELEM];
__device__ __align__(16) __half g_CH[NELEM];
__device__ __align__(16) __half g_WH[9][WSTRIDE];  // transposed [N][K] hi
__device__ __align__(16) __half g_WL[9][WSTRIDE];  // transposed [N][K] lo (3-term small path only)
// per-stage small activations (distinct buffers -> replay-deterministic)
__device__ __align__(16) __half g_S1H[128 * 1024];
__device__ __align__(16) __half g_S1L[128 * 1024];
__device__ __align__(16) __half g_S2H[128 * 1024];
__device__ __align__(16) __half g_S2L[128 * 1024];
__device__ __align__(16) __half g_S3H[128 * 1024];
__device__ __align__(16) __half g_S3L[128 * 1024];

// =================== helpers ===================
__device__ __forceinline__ uint32_t smem_u32(const void* p) {
    uint32_t a;
    asm("{ .reg .u64 t; cvta.to.shared.u64 t, %1; cvt.u32.u64 %0, t; }" : "=r"(a) : "l"(p));
    return a;
}
#define SWZ128(off) ((off) ^ (((off) >> 3) & 0x70))

__device__ __forceinline__ void cp16(uint32_t dst, const void* src) {
    asm volatile("cp.async.cg.shared.global [%0], [%1], 16;" :: "r"(dst), "l"(src));
}
__device__ __forceinline__ void cp_commit() {
    asm volatile("cp.async.commit_group;" ::: "memory");
}
__device__ __forceinline__ void ldsm_x4(uint32_t addr, uint32_t r[4]) {
    asm volatile("ldmatrix.sync.aligned.m8n8.x4.shared.b16 {%0,%1,%2,%3}, [%4];"
        : "=r"(r[0]), "=r"(r[1]), "=r"(r[2]), "=r"(r[3]) : "r"(addr));
}
__device__ __forceinline__ void ldsm_x4_t(uint32_t addr, uint32_t r[4]) {
    asm volatile("ldmatrix.sync.aligned.m8n8.x4.trans.shared.b16 {%0,%1,%2,%3}, [%4];"
        : "=r"(r[0]), "=r"(r[1]), "=r"(r[2]), "=r"(r[3]) : "r"(addr));
}
__device__ __forceinline__ void mma_f16(float c[4], const uint32_t a[4],
                                        uint32_t b0, uint32_t b1) {
    asm volatile(
        "mma.sync.aligned.m16n8k16.row.col.f32.f16.f16.f32 "
        "{%0,%1,%2,%3}, {%4,%5,%6,%7}, {%8,%9}, {%0,%1,%2,%3};"
        : "+f"(c[0]), "+f"(c[1]), "+f"(c[2]), "+f"(c[3])
        : "r"(a[0]), "r"(a[1]), "r"(a[2]), "r"(a[3]), "r"(b0), "r"(b1));
}
__device__ __forceinline__ uint32_t pack_f16x2(float lo, float hi) {
    uint32_t r;
    asm("cvt.rn.f16x2.f32 %0, %1, %2;" : "=r"(r) : "f"(hi), "f"(lo));
    return r;
}

// =================== prep kernels ===================
__global__ void prep_act_h_kernel(const float4* __restrict__ A,
                                  __half* __restrict__ H, int nquads)
{
    const int i = blockIdx.x * blockDim.x + threadIdx.x;
    if (i >= nquads) return;
    const float4 v = A[i];
    *(__half2*)(H + (size_t)i * 4)     = __halves2half2(__float2half_rn(v.x), __float2half_rn(v.y));
    *(__half2*)(H + (size_t)i * 4 + 2) = __halves2half2(__float2half_rn(v.z), __float2half_rn(v.w));
}

struct WP9 {
    const float* w[9];
    __half* h[9];
    __half* l[9];
};
// zoff splits the 9 weights across streams: main does [0,4) (hi only), side does [4,9) (hi+lo)
__global__ void prep_w_kernel(WP9 wp, int zoff)
{
    __shared__ float t[32][33];
    const int z  = blockIdx.z + zoff;
    const float* W = wp.w[z];
    __half* H = wp.h[z];
    __half* L = wp.l[z];
    const int bx = blockIdx.x;
    const int by = blockIdx.y;
    const int tx = threadIdx.x;
    const int ty = threadIdx.y;
    #pragma unroll
    for (int r = 0; r < 32; r += 8)
        t[ty + r][tx] = W[(size_t)(by * 32 + ty + r) * 1024 + bx * 32 + tx];
    __syncthreads();
    #pragma unroll
    for (int r = 0; r < 32; r += 8) {
        const float v = t[tx][ty + r];
        const __half h = __float2half_rn(v);
        const size_t o = (size_t)(bx * 32 + ty + r) * 1024 + by * 32 + tx;
        H[o] = h;
        if (z >= 4) L[o] = __float2half_rn(v - __half2float(h));
    }
}

// =================== fragment index helpers ===================
#define FRAG_IDX()                                                            \
    const int arow_in = (lane & 7) + ((lane >> 3) & 1) * 8;                   \
    const int acolx   = (lane >> 4) * 16;                                     \
    const int brow_in = (lane & 7) + ((lane >> 4) & 1) * 8;                   \
    const int bcolx   = ((lane >> 3) & 1) * 16;

#define BUF3_BYTES 65536
#define GEMM3_SMEM (2 * BUF3_BYTES)

#define ISSUE3(ic, buf) do {                                                  \
    const uint32_t sbase = sb + (buf) * BUF3_BYTES;                           \
    const size_t coff = (size_t)(ic) * 128 + cb;                              \
    _Pragma("unroll")                                                         \
    for (int i = 0; i < 4; i++) {                                             \
        const size_t go = (size_t)(rcp + i * 32) * 2048 + coff;               \
        cp16(sbase + dsw[i],          gAh + go);                              \
        cp16(sbase + 16384 + dsw[i],  gAl + go);                              \
        cp16(sbase + 32768 + dsw[i],  gBh + go);                              \
        cp16(sbase + 49152 + dsw[i],  gBl + go);                              \
    }                                                                         \
    cp_commit();                                                              \
} while (0)

// =================== split-K 3-term small GEMM -> fp32 partials ===================
__global__ __launch_bounds__(256, 1) void gemm_smallk_kernel(
    const __half* __restrict__ Ah, const __half* __restrict__ Al,
    const __half* __restrict__ WHb, const __half* __restrict__ WLb,
    int zbase, float* __restrict__ P)
{
    extern __shared__ char smem[];
    const uint32_t sb = smem_u32(smem);
    const int tid  = threadIdx.x;
    const int lane = tid & 31;
    const int wid  = tid >> 5;
    const int wm   = wid & 3;
    const int wn   = wid >> 2;
    const int bn = blockIdx.x;
    const int zi = blockIdx.y;
    const int ks = blockIdx.z;
    const int rcp = tid >> 3;
    const int cb  = (tid & 7) << 4;
    uint32_t dsw[4];
    #pragma unroll
    for (int i = 0; i < 4; i++) dsw[i] = SWZ128((uint32_t)((rcp + i * 32) * 128 + cb));
    FRAG_IDX();

    const char* gAh = (const char*)Ah;
    const char* gAl = (const char*)Al;
    const char* gBh = (const char*)(WHb + (size_t)(zbase + zi) * WSTRIDE + (size_t)bn * 128 * 1024);
    const char* gBl = (const char*)(WLb + (size_t)(zbase + zi) * WSTRIDE + (size_t)bn * 128 * 1024);

    float c[2][8][4];
    #pragma unroll
    for (int mt = 0; mt < 2; mt++)
        #pragma unroll
        for (int nb = 0; nb < 8; nb++)
            #pragma unroll
            for (int j = 0; j < 4; j++) c[mt][nb][j] = 0.f;

    const int ic0 = ks * 4;
    ISSUE3(ic0, 0);
    #pragma unroll 1
    for (int it = 0; it < 4; it++) {
        const int cur = it & 1;
        if (it < 3) ISSUE3(ic0 + it + 1, cur ^ 1);
        if (it < 3) asm volatile("cp.async.wait_group 1;" ::: "memory");
        else        asm volatile("cp.async.wait_group 0;" ::: "memory");
        __syncthreads();
        const uint32_t base = sb + cur * BUF3_BYTES;
        #pragma unroll
        for (int kk = 0; kk < 4; kk++) {
            const uint32_t kb = kk * 32;
            uint32_t ah[2][4], al_[2][4];
            #pragma unroll
            for (int mt = 0; mt < 2; mt++) {
                const uint32_t off =
                    SWZ128((uint32_t)((wm * 32 + mt * 16 + arow_in) * 128 + kb + acolx));
                ldsm_x4(base + off,          ah[mt]);
                ldsm_x4(base + 16384 + off,  al_[mt]);
            }
            uint32_t bh[4][4], bl[4][4];
            #pragma unroll
            for (int p = 0; p < 4; p++) {
                const uint32_t off =
                    SWZ128((uint32_t)((wn * 64 + p * 16 + brow_in) * 128 + kb + bcolx));
                ldsm_x4(base + 32768 + off, bh[p]);
                ldsm_x4(base + 49152 + off, bl[p]);
            }
            #pragma unroll
            for (int mt = 0; mt < 2; mt++) {
                #pragma unroll
                for (int p = 0; p < 4; p++) {
                    mma_f16(c[mt][2 * p],     ah[mt],  bh[p][0], bh[p][1]);
                    mma_f16(c[mt][2 * p],     ah[mt],  bl[p][0], bl[p][1]);
                    mma_f16(c[mt][2 * p],     al_[mt], bh[p][0], bh[p][1]);
                    mma_f16(c[mt][2 * p + 1], ah[mt],  bh[p][2], bh[p][3]);
                    mma_f16(c[mt][2 * p + 1], ah[mt],  bl[p][2], bl[p][3]);
                    mma_f16(c[mt][2 * p + 1], al_[mt], bh[p][2], bh[p][3]);
                }
            }
        }
        __syncthreads();
    }

    float* Pp = P + (size_t)(zi * 4 + ks) * PART_STRIDE;
    const int row_base = wm * 32 + (lane >> 2);
    const int col_base = bn * 128 + wn * 64 + 2 * (lane & 3);
    #pragma unroll
    for (int mt = 0; mt < 2; mt++) {
        #pragma unroll
        for (int hh = 0; hh < 2; hh++) {
            const int row = row_base + mt * 16 + hh * 8;
            #pragma unroll
            for (int nb = 0; nb < 8; nb++) {
                const int col = col_base + nb * 8;
                float2 o;
                o.x = c[mt][nb][hh * 2 + 0];
                o.y = c[mt][nb][hh * 2 + 1];
                *(float2*)(Pp + (size_t)row * 1024 + col) = o;
            }
        }
    }
}

// ---- reduces ----
__global__ void reduce3_fp32_kernel(const float* __restrict__ P,
                                    const float* __restrict__ b0,
                                    const float* __restrict__ b1,
                                    const float* __restrict__ b2,
                                    float* __restrict__ C)
{
    const int zi  = blockIdx.y;
    const int idx = blockIdx.x * 256 + threadIdx.x;
    const float* Pp = P + (size_t)zi * 4 * PART_STRIDE;
    const float s = Pp[idx] + Pp[idx + PART_STRIDE] + Pp[idx + 2 * PART_STRIDE] + Pp[idx + 3 * PART_STRIDE];
    const float* bias = (zi == 0) ? b0 : (zi == 1) ? b1 : b2;
    C[(size_t)zi * NBLK * D_MODEL + idx] = s + bias[idx & 1023];
}

__global__ void reduce_fp32_kernel(const float* __restrict__ P,
                                   const float* __restrict__ bias,
                                   float* __restrict__ C)
{
    const int idx = blockIdx.x * 256 + threadIdx.x;
    const float s = P[idx] + P[idx + PART_STRIDE] + P[idx + 2 * PART_STRIDE] + P[idx + 3 * PART_STRIDE];
    C[idx] = s + bias[idx & 1023];
}

__global__ void reduce_hl_kernel(const float* __restrict__ P,
                                 const float* __restrict__ bias,
                                 __half* __restrict__ H, __half* __restrict__ L)
{
    const int idx = blockIdx.x * 256 + threadIdx.x;
    const float v = P[idx] + P[idx + PART_STRIDE] + P[idx + 2 * PART_STRIDE] + P[idx + 3 * PART_STRIDE]
                  + bias[idx & 1023];
    const __half h = __float2half_rn(v);
    H[idx] = h;
    L[idx] = __float2half_rn(v - __half2float(h));
}

// =================== 1-term GEMM mainloop (big path): C ~= Ah * Bh ===================
#define BUF1_BYTES 32768
#define GEMM1_SMEM (2 * BUF1_BYTES)

#define ISSUE1(ic, buf) do {                                                  \
    const uint32_t sbase = sb + (buf) * BUF1_BYTES;                           \
    const size_t coff = (size_t)(ic) * 128 + cb;                              \
    _Pragma("unroll")                                                         \
    for (int i = 0; i < 4; i++) {                                             \
        const size_t go = (size_t)(rcp + i * 32) * 2048 + coff;               \
        cp16(sbase + dsw[i],          gAh + go);                              \
        cp16(sbase + 16384 + dsw[i],  gBh + go);                              \
    }                                                                         \
    cp_commit();                                                              \
} while (0)

#define GEMM1_BODY()                                                          \
    extern __shared__ char smem[];                                            \
    const uint32_t sb = smem_u32(smem);                                       \
    const int tid  = threadIdx.x;                                             \
    const int lane = tid & 31;                                                \
    const int wid  = tid >> 5;                                                \
    const int wm   = wid & 3;                                                 \
    const int wn   = wid >> 2;                                                \
    const int bn = blockIdx.x;                                                \
    const int bm = blockIdx.y;                                                \
    const int rcp = tid >> 3;                                                 \
    const int cb  = (tid & 7) << 4;                                           \
    uint32_t dsw[4];                                                          \
    _Pragma("unroll")                                                         \
    for (int i = 0; i < 4; i++) dsw[i] = SWZ128((uint32_t)((rcp + i * 32) * 128 + cb)); \
    FRAG_IDX();                                                               \
    float c[2][8][4];                                                         \
    _Pragma("unroll")                                                         \
    for (int mt = 0; mt < 2; mt++)                                            \
        _Pragma("unroll")                                                     \
        for (int nb = 0; nb < 8; nb++)                                        \
            _Pragma("unroll")                                                 \
            for (int j = 0; j < 4; j++) c[mt][nb][j] = 0.f;                   \
    ISSUE1(0, 0);                                                             \
    _Pragma("unroll 1")                                                       \
    for (int ic = 0; ic < 16; ic++) {                                         \
        const int cur = ic & 1;                                               \
        if (ic < 15) ISSUE1(ic + 1, cur ^ 1);                                 \
        if (ic < 15) asm volatile("cp.async.wait_group 1;" ::: "memory");     \
        else         asm volatile("cp.async.wait_group 0;" ::: "memory");     \
        __syncthreads();                                                      \
        const uint32_t base = sb + cur * BUF1_BYTES;                          \
        _Pragma("unroll")                                                     \
        for (int kk = 0; kk < 4; kk++) {                                      \
            const uint32_t kb = kk * 32;                                      \
            uint32_t ah[2][4];                                                \
            _Pragma("unroll")                                                 \
            for (int mt = 0; mt < 2; mt++) {                                  \
                const uint32_t off =                                          \
                    SWZ128((uint32_t)((wm * 32 + mt * 16 + arow_in) * 128 + kb + acolx)); \
                ldsm_x4(base + off, ah[mt]);                                  \
            }                                                                 \
            uint32_t bh[4][4];                                                \
            _Pragma("unroll")                                                 \
            for (int p = 0; p < 4; p++) {                                     \
                const uint32_t off =                                          \
                    SWZ128((uint32_t)((wn * 64 + p * 16 + brow_in) * 128 + kb + bcolx)); \
                ldsm_x4(base + 16384 + off, bh[p]);                           \
            }                                                                 \
            _Pragma("unroll")                                                 \
            for (int mt = 0; mt < 2; mt++) {                                  \
                _Pragma("unroll")                                             \
                for (int p = 0; p < 4; p++) {                                 \
                    mma_f16(c[mt][2 * p],     ah[mt], bh[p][0], bh[p][1]);    \
                    mma_f16(c[mt][2 * p + 1], ah[mt], bh[p][2], bh[p][3]);    \
                }                                                             \
            }                                                                 \
        }                                                                     \
        __syncthreads();                                                      \
    }

// ---- fused QKV: 1-term fp16, hi-only outputs ----
__global__ __launch_bounds__(256, 2) void gemm1_qkv_kernel(
    const __half* __restrict__ Ah, const __half* __restrict__ Bh,
    const float* __restrict__ bq, const float* __restrict__ bk, const float* __restrict__ bv,
    __half* __restrict__ QH, __half* __restrict__ KH, __half* __restrict__ VH)
{
    const char* gAh = (const char*)(Ah + (size_t)(blockIdx.y * 128) * 1024);
    const char* gBh = (const char*)(Bh + (size_t)(blockIdx.x * 128) * 1024);
    GEMM1_BODY();

    const int tensor = bn >> 3;
    const float* bias = (tensor == 0) ? bq : (tensor == 1) ? bk : bv;
    __half* OH = (tensor == 0) ? QH : (tensor == 1) ? KH : VH;

    const int row_base = bm * 128 + wm * 32 + (lane >> 2);
    const int col_base = (bn & 7) * 128 + wn * 64 + 2 * (lane & 3);
    #pragma unroll
    for (int mt = 0; mt < 2; mt++) {
        #pragma unroll
        for (int hh = 0; hh < 2; hh++) {
            const int row = row_base + mt * 16 + hh * 8;
            #pragma unroll
            for (int nb = 0; nb < 8; nb++) {
                const int col = col_base + nb * 8;
                const float v0 = c[mt][nb][hh * 2 + 0] + bias[col + 0];
                const float v1 = c[mt][nb][hh * 2 + 1] + bias[col + 1];
                *(__half2*)(OH + (size_t)row * 1024 + col) = __halves2half2(
                    __float2half_rn(v0), __float2half_rn(v1));
            }
        }
    }
}

// ---- o-proj: 1-term fp16, fp32 out + bias + summary add ----
__global__ __launch_bounds__(256, 2) void gemm1_oproj_kernel(
    const __half* __restrict__ Ah, const __half* __restrict__ Bh,
    const float* __restrict__ bias, const float* __restrict__ addBlk,
    float* __restrict__ C)
{
    const char* gAh = (const char*)(Ah + (size_t)(blockIdx.y * 128) * 1024);
    const char* gBh = (const char*)(Bh + (size_t)(blockIdx.x * 128) * 1024);
    GEMM1_BODY();

    const int row_base = bm * 128 + wm * 32 + (lane >> 2);
    const int col_base = bn * 128 + wn * 64 + 2 * (lane & 3);
    #pragma unroll
    for (int mt = 0; mt < 2; mt++) {
        #pragma unroll
        for (int hh = 0; hh < 2; hh++) {
            const int row = row_base + mt * 16 + hh * 8;
            const int rb = row >> 8;
            #pragma unroll
            for (int nb = 0; nb < 8; nb++) {
                const int col = col_base + nb * 8;
                float2 o;
                o.x = c[mt][nb][hh * 2 + 0] + bias[col + 0] + addBlk[(size_t)rb * 1024 + col + 0];
                o.y = c[mt][nb][hh * 2 + 1] + bias[col + 1] + addBlk[(size_t)rb * 1024 + col + 1];
                *(float2*)(C + (size_t)row * 1024 + col) = o;
            }
        }
    }
}

// =================== HMMA local attention (plain fp16, fp32 accum) ===================
// Phase 1: S = Qh Kh^T.  Phase 2: O = P V, V read via ldmatrix.trans from [tok][dim].
#define ATT_SMEM (3 * 32768)

__global__ __launch_bounds__(512, 1) void attn_mma_kernel(
    const __half* __restrict__ QH, const __half* __restrict__ KH,
    const __half* __restrict__ VH,
    const float* __restrict__ bias,
    __half* __restrict__ CH)
{
    extern __shared__ char smem[];
    const uint32_t sb = smem_u32(smem);
    const int blk = blockIdx.x;
    const int h   = blockIdx.y;
    const int tid = threadIdx.x;
    const int lane = tid & 31;
    const int w    = tid >> 5;

    const uint32_t QHs = sb;
    const uint32_t KHs = sb + 32768;
    const uint32_t VHs = sb + 65536;   // [256 tok][64 dim], SWZ128 rows of 128B

    {
        const char* qh0 = (const char*)(QH + ((size_t)blk * 256) * 1024 + h * 64);
        const char* kh0 = (const char*)(KH + ((size_t)blk * 256) * 1024 + h * 64);
        const char* vh0 = (const char*)(VH + ((size_t)blk * 256) * 1024 + h * 64);
        #pragma unroll
        for (int i = 0; i < 4; i++) {
            const int cidx = tid + i * 512;
            const int row = cidx >> 3;
            const int cbo = (cidx & 7) << 4;
            const uint32_t d = SWZ128((uint32_t)(row * 128 + cbo));
            const size_t go = (size_t)row * 2048 + cbo;
            cp16(QHs + d, qh0 + go);
            cp16(KHs + d, kh0 + go);
            cp16(VHs + d, vh0 + go);
        }
        cp_commit();
        asm volatile("cp.async.wait_group 0;" ::: "memory");
        __syncthreads();
    }

    const int arow = (lane & 7) + ((lane >> 3) & 1) * 8;
    const int acol = (lane >> 4) * 16;
    const int brow = (lane & 7) + ((lane >> 4) & 1) * 8;
    const int bcol = ((lane >> 3) & 1) * 16;

    float s[32][4];
    #pragma unroll
    for (int j = 0; j < 32; j++)
        #pragma unroll
        for (int q = 0; q < 4; q++) s[j][q] = 0.f;

    #pragma unroll
    for (int kk = 0; kk < 4; kk++) {
        const uint32_t kb = kk * 32;
        uint32_t qh[4];
        const uint32_t aoff = SWZ128((uint32_t)((w * 16 + arow) * 128 + kb + acol));
        ldsm_x4(QHs + aoff, qh);
        #pragma unroll
        for (int p = 0; p < 16; p++) {
            uint32_t bh[4];
            const uint32_t boff = SWZ128((uint32_t)((p * 16 + brow) * 128 + kb + bcol));
            ldsm_x4(KHs + boff, bh);
            mma_f16(s[2 * p],     qh, bh[0], bh[1]);
            mma_f16(s[2 * p + 1], qh, bh[2], bh[3]);
        }
    }

    const int r0 = w * 16 + (lane >> 2);
    const int cq = (lane & 3) * 2;
    const float* br0 = bias + ((size_t)h * 256 + r0) * 256;
    const float* br1 = br0 + 8 * 256;

    float m0 = -1e30f, m1 = -1e30f;
    #pragma unroll
    for (int j = 0; j < 32; j++) {
        const float2 b0 = *(const float2*)(br0 + j * 8 + cq);
        const float2 b1 = *(const float2*)(br1 + j * 8 + cq);
        s[j][0] = s[j][0] * 0.125f + b0.x;
        s[j][1] = s[j][1] * 0.125f + b0.y;
        s[j][2] = s[j][2] * 0.125f + b1.x;
        s[j][3] = s[j][3] * 0.125f + b1.y;
        m0 = fmaxf(m0, fmaxf(s[j][0], s[j][1]));
        m1 = fmaxf(m1, fmaxf(s[j][2], s[j][3]));
    }
    #pragma unroll
    for (int msk = 1; msk <= 2; msk <<= 1) {
        m0 = fmaxf(m0, __shfl_xor_sync(0xffffffffu, m0, msk));
        m1 = fmaxf(m1, __shfl_xor_sync(0xffffffffu, m1, msk));
    }
    float l0 = 0.f, l1 = 0.f;
    #pragma unroll
    for (int j = 0; j < 32; j++) {
        s[j][0] = __expf(s[j][0] - m0);
        s[j][1] = __expf(s[j][1] - m0);
        s[j][2] = __expf(s[j][2] - m1);
        s[j][3] = __expf(s[j][3] - m1);
        l0 += s[j][0] + s[j][1];
        l1 += s[j][2] + s[j][3];
    }
    #pragma unroll
    for (int msk = 1; msk <= 2; msk <<= 1) {
        l0 += __shfl_xor_sync(0xffffffffu, l0, msk);
        l1 += __shfl_xor_sync(0xffffffffu, l1, msk);
    }

    float o[8][4];
    #pragma unroll
    for (int j = 0; j < 8; j++)
        #pragma unroll
        for (int q = 0; q < 4; q++) o[j][q] = 0.f;

    // Phase 2: B-frag via ldmatrix.trans from V[tok][dim].
    // Lane map mirrors the A-frag map: k-row = arow, n-col byte = acol.
    #pragma unroll
    for (int kt = 0; kt < 16; kt++) {
        uint32_t pah[4];
        #pragma unroll
        for (int half_ = 0; half_ < 2; half_++) {
            const float* sv = s[2 * kt + half_];
            pah[2 * half_ + 0] = pack_f16x2(sv[0], sv[1]);
            pah[2 * half_ + 1] = pack_f16x2(sv[2], sv[3]);
        }
        #pragma unroll
        for (int nd = 0; nd < 4; nd++) {
            uint32_t bh[4];
            const uint32_t boff =
                SWZ128((uint32_t)((kt * 16 + arow) * 128 + nd * 32 + acol));
            ldsm_x4_t(VHs + boff, bh);
            mma_f16(o[2 * nd],     pah, bh[0], bh[1]);
            mma_f16(o[2 * nd + 1], pah, bh[2], bh[3]);
        }
    }

    const float inv0 = 1.f / l0;
    const float inv1 = 1.f / l1;
    const size_t row0 = (size_t)blk * 256 + r0;
    #pragma unroll
    for (int j = 0; j < 8; j++) {
        const int col = h * 64 + j * 8 + cq;
        *(__half2*)(CH + row0 * 1024 + col) = __halves2half2(
            __float2half_rn(o[j][0] * inv0), __float2half_rn(o[j][1] * inv0));
        *(__half2*)(CH + (row0 + 8) * 1024 + col) = __halves2half2(
            __float2half_rn(o[j][2] * inv1), __float2half_rn(o[j][3] * inv1));
    }
}

// =================== mean pool -> split fp16 directly ===================
__global__ void meanpool_hl_kernel(const float* __restrict__ x,
                                   __half* __restrict__ H, __half* __restrict__ L)
{
    const int blk = blockIdx.x;
    const int c   = blockIdx.y * 256 + threadIdx.x;
    const float* base = x + (size_t)blk * BSZ * D_MODEL + c;
    float s = 0.f;
    #pragma unroll 4
    for (int r = 0; r < BSZ; r++) s += base[(size_t)r * D_MODEL];
    const float v = s * (1.0f / BSZ);
    const __half h = __float2half_rn(v);
    H[blk * D_MODEL + c] = h;
    L[blk * D_MODEL + c] = __float2half_rn(v - __half2float(h));
}

// =================== summary attention (fp32 in, split fp16 out) ===================
__global__ void summ_attn_kernel(
    const float* __restrict__ QKV2,
    __half* __restrict__ SCH, __half* __restrict__ SCL)
{
    const float* Q2 = QKV2;
    const float* K2 = QKV2 + (size_t)NBLK * D_MODEL;
    const float* V2 = QKV2 + (size_t)2 * NBLK * D_MODEL;
    const int b = blockIdx.x;
    const int h = blockIdx.y;
    const int l = threadIdx.x;

    const float* qr = Q2 + (size_t)(b * 16 + l) * D_MODEL + h * DHEAD;
    float q[DHEAD];
    #pragma unroll
    for (int d = 0; d < DHEAD; d += 4) {
        const float4 v = *(const float4*)(qr + d);
        q[d] = v.x; q[d + 1] = v.y; q[d + 2] = v.z; q[d + 3] = v.w;
    }

    float s[16];
    float m = -1e30f;
    for (int j = 0; j < 16; j++) {
        const float* kr = K2 + (size_t)(b * 16 + j) * D_MODEL + h * DHEAD;
        float a = 0.f;
        #pragma unroll
        for (int d = 0; d < DHEAD; d += 4) {
            const float4 v = *(const float4*)(kr + d);
            a += q[d] * v.x + q[d + 1] * v.y + q[d + 2] * v.z + q[d + 3] * v.w;
        }
        s[j] = a * 0.125f;
        m = fmaxf(m, s[j]);
    }
    float lsum = 0.f;
    for (int j = 0; j < 16; j++) { s[j] = __expf(s[j] - m); lsum += s[j]; }
    const float inv = 1.f / lsum;

    float o[DHEAD];
    #pragma unroll
    for (int d = 0; d < DHEAD; d++) o[d] = 0.f;
    for (int j = 0; j < 16; j++) {
        const float* vr = V2 + (size_t)(b * 16 + j) * D_MODEL + h * DHEAD;
        const float p = s[j] * inv;
        #pragma unroll
        for (int d = 0; d < DHEAD; d += 4) {
            const float4 v = *(const float4*)(vr + d);
            o[d] += p * v.x; o[d + 1] += p * v.y; o[d + 2] += p * v.z; o[d + 3] += p * v.w;
        }
    }
    const size_t ob = (size_t)(b * 16 + l) * D_MODEL + h * DHEAD;
    #pragma unroll
    for (int d = 0; d < DHEAD; d += 2) {
        const __half h0 = __float2half_rn(o[d]);
        const __half h1 = __float2half_rn(o[d + 1]);
        *(__half2*)(SCH + ob + d) = __halves2half2(h0, h1);
        *(__half2*)(SCL + ob + d) = __halves2half2(
            __float2half_rn(o[d] - __half2float(h0)),
            __float2half_rn(o[d + 1] - __half2float(h1)));
    }
}

// =================== launch ===================
extern "C" void kernel_launch(void* const* d_in, const int* in_sizes, int n_in,
                              void* d_out, int out_size)
{
    const float* x     = (const float*)d_in[0];
    const float* lq_w  = (const float*)d_in[1];
    const float* lq_b  = (const float*)d_in[2];
    const float* lk_w  = (const float*)d_in[3];
    const float* lk_b  = (const float*)d_in[4];
    const float* lv_w  = (const float*)d_in[5];
    const float* lv_b  = (const float*)d_in[6];
    const float* lo_w  = (const float*)d_in[7];
    const float* lo_b  = (const float*)d_in[8];
    const float* pbias = (const float*)d_in[9];
    const float* sq_w  = (const float*)d_in[10];
    const float* sq_b  = (const float*)d_in[11];
    const float* sk_w  = (const float*)d_in[12];
    const float* sk_b  = (const float*)d_in[13];
    const float* sv_w  = (const float*)d_in[14];
    const float* sv_b  = (const float*)d_in[15];
    const float* so_w  = (const float*)d_in[16];
    const float* so_b  = (const float*)d_in[17];
    const float* sum_w = (const float*)d_in[18];
    const float* sum_b = (const float*)d_in[19];
    float* out = (float*)d_out;

    float *QKV2, *SOUT, *PART;
    cudaGetSymbolAddress((void**)&QKV2, g_QKV2);
    cudaGetSymbolAddress((void**)&SOUT, g_SOUT);
    cudaGetSymbolAddress((void**)&PART, g_PART);

    __half *XH, *QH, *KH, *VH, *CH, *WH, *WL;
    __half *S1H, *S1L, *S2H, *S2L, *S3H, *S3L;
    cudaGetSymbolAddress((void**)&XH, g_XH);
    cudaGetSymbolAddress((void**)&QH, g_QH);
    cudaGetSymbolAddress((void**)&KH, g_KH);
    cudaGetSymbolAddress((void**)&VH, g_VH);
    cudaGetSymbolAddress((void**)&CH, g_CH);
    cudaGetSymbolAddress((void**)&WH, g_WH);
    cudaGetSymbolAddress((void**)&WL, g_WL);
    cudaGetSymbolAddress((void**)&S1H, g_S1H);
    cudaGetSymbolAddress((void**)&S1L, g_S1L);
    cudaGetSymbolAddress((void**)&S2H, g_S2H);
    cudaGetSymbolAddress((void**)&S2L, g_S2L);
    cudaGetSymbolAddress((void**)&S3H, g_S3H);
    cudaGetSymbolAddress((void**)&S3L, g_S3L);

    WP9 wp;
    const float* ws[9] = {lq_w, lk_w, lv_w, lo_w, sum_w, sq_w, sk_w, sv_w, so_w};
    for (int i = 0; i < 9; i++) {
        wp.w[i] = ws[i];
        wp.h[i] = WH + (size_t)i * WSTRIDE;
        wp.l[i] = WL + (size_t)i * WSTRIDE;
    }

    cudaFuncSetAttribute(gemm_smallk_kernel,
                         cudaFuncAttributeMaxDynamicSharedMemorySize, GEMM3_SMEM);
    cudaFuncSetAttribute(gemm1_qkv_kernel,
                         cudaFuncAttributeMaxDynamicSharedMemorySize, GEMM1_SMEM);
    cudaFuncSetAttribute(gemm1_oproj_kernel,
                         cudaFuncAttributeMaxDynamicSharedMemorySize, GEMM1_SMEM);
    cudaFuncSetAttribute(attn_mma_kernel,
                         cudaFuncAttributeMaxDynamicSharedMemorySize, ATT_SMEM);

    static cudaStream_t s2 = nullptr, s3 = nullptr;
    static cudaEvent_t evFork = nullptr, evJoin = nullptr, evAct = nullptr;
    if (s2 == nullptr) {
        cudaStreamCreateWithFlags(&s2, cudaStreamNonBlocking);
        cudaStreamCreateWithFlags(&s3, cudaStreamNonBlocking);
        cudaEventCreateWithFlags(&evFork, cudaEventDisableTiming);
        cudaEventCreateWithFlags(&evJoin, cudaEventDisableTiming);
        cudaEventCreateWithFlags(&evAct,  cudaEventDisableTiming);
    }

    // fork: s2 = small summary path (+ its weights), s3 = activation conversion
    cudaEventRecord(evFork, 0);
    cudaStreamWaitEvent(s2, evFork, 0);
    cudaStreamWaitEvent(s3, evFork, 0);

    // ---- s3: activation fp32 -> fp16 (overlaps with prep_w on main) ----
    prep_act_h_kernel<<<16384, 256, 0, s3>>>((const float4*)x, XH, 4194304);
    cudaEventRecord(evAct, s3);

    // ---- s2: weight prep (z=4..8, hi+lo) + small summary path ----
    prep_w_kernel<<<dim3(32, 32, 5), dim3(32, 8), 0, s2>>>(wp, 4);
    meanpool_hl_kernel<<<dim3(NBLK, 4), 256, 0, s2>>>(x, S1H, S1L);
    gemm_smallk_kernel<<<dim3(8, 1, 4), 256, GEMM3_SMEM, s2>>>(S1H, S1L, WH, WL, 4, PART);
    reduce_hl_kernel<<<512, 256, 0, s2>>>(PART, sum_b, S2H, S2L);
    gemm_smallk_kernel<<<dim3(8, 3, 4), 256, GEMM3_SMEM, s2>>>(S2H, S2L, WH, WL, 5, PART);
    reduce3_fp32_kernel<<<dim3(256, 3), 256, 0, s2>>>(PART, sq_b, sk_b, sv_b, QKV2);
    summ_attn_kernel<<<dim3(4, NHEAD), 16, 0, s2>>>(QKV2, S3H, S3L);
    gemm_smallk_kernel<<<dim3(8, 1, 4), 256, GEMM3_SMEM, s2>>>(S3H, S3L, WH, WL, 8, PART);
    reduce_fp32_kernel<<<256, 256, 0, s2>>>(PART, so_b, SOUT);
    cudaEventRecord(evJoin, s2);

    // ---- main stream: big local path (weights 0..3, hi only) ----
    prep_w_kernel<<<dim3(32, 32, 4), dim3(32, 8)>>>(wp, 0);
    cudaStreamWaitEvent(0, evAct, 0);
    gemm1_qkv_kernel<<<dim3(24, NTOK / 128), 256, GEMM1_SMEM>>>(
        XH, wp.h[0], lq_b, lk_b, lv_b, QH, KH, VH);
    attn_mma_kernel<<<dim3(NBLK, NHEAD), 512, ATT_SMEM>>>(
        QH, KH, VH, pbias, CH);

    cudaStreamWaitEvent(0, evJoin, 0);
    gemm1_oproj_kernel<<<dim3(8, NTOK / 128), 256, GEMM1_SMEM>>>(
        CH, wp.h[3], lo_b, SOUT, out);
}

// round 16
// speedup vs baseline: 3.0541x; 1.0623x over previous
#include <cuda_runtime.h>
#include <cuda_fp16.h>
#include <cstdint>

#define D_MODEL 1024
#define NHEAD   16
#define DHEAD   64
#define BSZ     256
#define NTOK    16384
#define NBLK    64
#define NELEM   ((size_t)NTOK * D_MODEL)
#define WSTRIDE (1024 * 1024)
#define PART_STRIDE (128 * 1024)

// ---------------- fp32 scratch (small path) ----------------
__device__ __align__(16) float g_QKV2[3 * NBLK * D_MODEL];   // Q2|K2|V2
__device__ __align__(16) float g_SOUT[NBLK * D_MODEL];
__device__ __align__(16) float g_PART[12 * PART_STRIDE];     // split-K partials

// ---------------- fp16 scratch ----------------
__device__ __align__(16) __half g_XH[NELEM];
__device__ __align__(16) __half g_QH[NELEM];
__device__ __align__(16) __half g_KH[NELEM];
__device__ __align__(16) __half g_VH[NELEM];
__device__ __align__(16) __half g_CH[NELEM];
__device__ __align__(16) __half g_WH[9][WSTRIDE];  // transposed [N][K] hi
__device__ __align__(16) __half g_WL[9][WSTRIDE];  // transposed [N][K] lo (3-term small path only)
// per-stage small activations (distinct buffers -> replay-deterministic)
__device__ __align__(16) __half g_S1H[128 * 1024];
__device__ __align__(16) __half g_S1L[128 * 1024];
__device__ __align__(16) __half g_S2H[128 * 1024];
__device__ __align__(16) __half g_S2L[128 * 1024];
__device__ __align__(16) __half g_S3H[128 * 1024];
__device__ __align__(16) __half g_S3L[128 * 1024];

// =================== helpers ===================
__device__ __forceinline__ uint32_t smem_u32(const void* p) {
    uint32_t a;
    asm("{ .reg .u64 t; cvta.to.shared.u64 t, %1; cvt.u32.u64 %0, t; }" : "=r"(a) : "l"(p));
    return a;
}
#define SWZ128(off) ((off) ^ (((off) >> 3) & 0x70))

__device__ __forceinline__ void cp16(uint32_t dst, const void* src) {
    asm volatile("cp.async.cg.shared.global [%0], [%1], 16;" :: "r"(dst), "l"(src));
}
__device__ __forceinline__ void cp_commit() {
    asm volatile("cp.async.commit_group;" ::: "memory");
}
__device__ __forceinline__ void ldsm_x4(uint32_t addr, uint32_t r[4]) {
    asm volatile("ldmatrix.sync.aligned.m8n8.x4.shared.b16 {%0,%1,%2,%3}, [%4];"
        : "=r"(r[0]), "=r"(r[1]), "=r"(r[2]), "=r"(r[3]) : "r"(addr));
}
__device__ __forceinline__ void ldsm_x4_t(uint32_t addr, uint32_t r[4]) {
    asm volatile("ldmatrix.sync.aligned.m8n8.x4.trans.shared.b16 {%0,%1,%2,%3}, [%4];"
        : "=r"(r[0]), "=r"(r[1]), "=r"(r[2]), "=r"(r[3]) : "r"(addr));
}
__device__ __forceinline__ void mma_f16(float c[4], const uint32_t a[4],
                                        uint32_t b0, uint32_t b1) {
    asm volatile(
        "mma.sync.aligned.m16n8k16.row.col.f32.f16.f16.f32 "
        "{%0,%1,%2,%3}, {%4,%5,%6,%7}, {%8,%9}, {%0,%1,%2,%3};"
        : "+f"(c[0]), "+f"(c[1]), "+f"(c[2]), "+f"(c[3])
        : "r"(a[0]), "r"(a[1]), "r"(a[2]), "r"(a[3]), "r"(b0), "r"(b1));
}
__device__ __forceinline__ uint32_t pack_f16x2(float lo, float hi) {
    uint32_t r;
    asm("cvt.rn.f16x2.f32 %0, %1, %2;" : "=r"(r) : "f"(hi), "f"(lo));
    return r;
}

// =================== prep kernels ===================
__global__ void prep_act_h_kernel(const float4* __restrict__ A,
                                  __half* __restrict__ H, int nquads)
{
    const int i = blockIdx.x * blockDim.x + threadIdx.x;
    if (i >= nquads) return;
    const float4 v = A[i];
    *(__half2*)(H + (size_t)i * 4)     = __halves2half2(__float2half_rn(v.x), __float2half_rn(v.y));
    *(__half2*)(H + (size_t)i * 4 + 2) = __halves2half2(__float2half_rn(v.z), __float2half_rn(v.w));
}

struct WP9 {
    const float* w[9];
    __half* h[9];
    __half* l[9];
};
// zoff selects the weight range: main does [0,3), s3 does [3,4), side does [4,9)
__global__ void prep_w_kernel(WP9 wp, int zoff)
{
    __shared__ float t[32][33];
    const int z  = blockIdx.z + zoff;
    const float* W = wp.w[z];
    __half* H = wp.h[z];
    __half* L = wp.l[z];
    const int bx = blockIdx.x;
    const int by = blockIdx.y;
    const int tx = threadIdx.x;
    const int ty = threadIdx.y;
    #pragma unroll
    for (int r = 0; r < 32; r += 8)
        t[ty + r][tx] = W[(size_t)(by * 32 + ty + r) * 1024 + bx * 32 + tx];
    __syncthreads();
    #pragma unroll
    for (int r = 0; r < 32; r += 8) {
        const float v = t[tx][ty + r];
        const __half h = __float2half_rn(v);
        const size_t o = (size_t)(bx * 32 + ty + r) * 1024 + by * 32 + tx;
        H[o] = h;
        if (z >= 4) L[o] = __float2half_rn(v - __half2float(h));
    }
}

// =================== fragment index helpers ===================
#define FRAG_IDX()                                                            \
    const int arow_in = (lane & 7) + ((lane >> 3) & 1) * 8;                   \
    const int acolx   = (lane >> 4) * 16;                                     \
    const int brow_in = (lane & 7) + ((lane >> 4) & 1) * 8;                   \
    const int bcolx   = ((lane >> 3) & 1) * 16;

#define BUF3_BYTES 65536
#define GEMM3_SMEM (2 * BUF3_BYTES)

#define ISSUE3(ic, buf) do {                                                  \
    const uint32_t sbase = sb + (buf) * BUF3_BYTES;                           \
    const size_t coff = (size_t)(ic) * 128 + cb;                              \
    _Pragma("unroll")                                                         \
    for (int i = 0; i < 4; i++) {                                             \
        const size_t go = (size_t)(rcp + i * 32) * 2048 + coff;               \
        cp16(sbase + dsw[i],          gAh + go);                              \
        cp16(sbase + 16384 + dsw[i],  gAl + go);                              \
        cp16(sbase + 32768 + dsw[i],  gBh + go);                              \
        cp16(sbase + 49152 + dsw[i],  gBl + go);                              \
    }                                                                         \
    cp_commit();                                                              \
} while (0)

// =================== split-K 3-term small GEMM -> fp32 partials ===================
__global__ __launch_bounds__(256, 1) void gemm_smallk_kernel(
    const __half* __restrict__ Ah, const __half* __restrict__ Al,
    const __half* __restrict__ WHb, const __half* __restrict__ WLb,
    int zbase, float* __restrict__ P)
{
    extern __shared__ char smem[];
    const uint32_t sb = smem_u32(smem);
    const int tid  = threadIdx.x;
    const int lane = tid & 31;
    const int wid  = tid >> 5;
    const int wm   = wid & 3;
    const int wn   = wid >> 2;
    const int bn = blockIdx.x;
    const int zi = blockIdx.y;
    const int ks = blockIdx.z;
    const int rcp = tid >> 3;
    const int cb  = (tid & 7) << 4;
    uint32_t dsw[4];
    #pragma unroll
    for (int i = 0; i < 4; i++) dsw[i] = SWZ128((uint32_t)((rcp + i * 32) * 128 + cb));
    FRAG_IDX();

    const char* gAh = (const char*)Ah;
    const char* gAl = (const char*)Al;
    const char* gBh = (const char*)(WHb + (size_t)(zbase + zi) * WSTRIDE + (size_t)bn * 128 * 1024);
    const char* gBl = (const char*)(WLb + (size_t)(zbase + zi) * WSTRIDE + (size_t)bn * 128 * 1024);

    float c[2][8][4];
    #pragma unroll
    for (int mt = 0; mt < 2; mt++)
        #pragma unroll
        for (int nb = 0; nb < 8; nb++)
            #pragma unroll
            for (int j = 0; j < 4; j++) c[mt][nb][j] = 0.f;

    const int ic0 = ks * 4;
    ISSUE3(ic0, 0);
    #pragma unroll 1
    for (int it = 0; it < 4; it++) {
        const int cur = it & 1;
        if (it < 3) ISSUE3(ic0 + it + 1, cur ^ 1);
        if (it < 3) asm volatile("cp.async.wait_group 1;" ::: "memory");
        else        asm volatile("cp.async.wait_group 0;" ::: "memory");
        __syncthreads();
        const uint32_t base = sb + cur * BUF3_BYTES;
        #pragma unroll
        for (int kk = 0; kk < 4; kk++) {
            const uint32_t kb = kk * 32;
            uint32_t ah[2][4], al_[2][4];
            #pragma unroll
            for (int mt = 0; mt < 2; mt++) {
                const uint32_t off =
                    SWZ128((uint32_t)((wm * 32 + mt * 16 + arow_in) * 128 + kb + acolx));
                ldsm_x4(base + off,          ah[mt]);
                ldsm_x4(base + 16384 + off,  al_[mt]);
            }
            uint32_t bh[4][4], bl[4][4];
            #pragma unroll
            for (int p = 0; p < 4; p++) {
                const uint32_t off =
                    SWZ128((uint32_t)((wn * 64 + p * 16 + brow_in) * 128 + kb + bcolx));
                ldsm_x4(base + 32768 + off, bh[p]);
                ldsm_x4(base + 49152 + off, bl[p]);
            }
            #pragma unroll
            for (int mt = 0; mt < 2; mt++) {
                #pragma unroll
                for (int p = 0; p < 4; p++) {
                    mma_f16(c[mt][2 * p],     ah[mt],  bh[p][0], bh[p][1]);
                    mma_f16(c[mt][2 * p],     ah[mt],  bl[p][0], bl[p][1]);
                    mma_f16(c[mt][2 * p],     al_[mt], bh[p][0], bh[p][1]);
                    mma_f16(c[mt][2 * p + 1], ah[mt],  bh[p][2], bh[p][3]);
                    mma_f16(c[mt][2 * p + 1], ah[mt],  bl[p][2], bl[p][3]);
                    mma_f16(c[mt][2 * p + 1], al_[mt], bh[p][2], bh[p][3]);
                }
            }
        }
        __syncthreads();
    }

    float* Pp = P + (size_t)(zi * 4 + ks) * PART_STRIDE;
    const int row_base = wm * 32 + (lane >> 2);
    const int col_base = bn * 128 + wn * 64 + 2 * (lane & 3);
    #pragma unroll
    for (int mt = 0; mt < 2; mt++) {
        #pragma unroll
        for (int hh = 0; hh < 2; hh++) {
            const int row = row_base + mt * 16 + hh * 8;
            #pragma unroll
            for (int nb = 0; nb < 8; nb++) {
                const int col = col_base + nb * 8;
                float2 o;
                o.x = c[mt][nb][hh * 2 + 0];
                o.y = c[mt][nb][hh * 2 + 1];
                *(float2*)(Pp + (size_t)row * 1024 + col) = o;
            }
        }
    }
}

// ---- reduces ----
__global__ void reduce3_fp32_kernel(const float* __restrict__ P,
                                    const float* __restrict__ b0,
                                    const float* __restrict__ b1,
                                    const float* __restrict__ b2,
                                    float* __restrict__ C)
{
    const int zi  = blockIdx.y;
    const int idx = blockIdx.x * 256 + threadIdx.x;
    const float* Pp = P + (size_t)zi * 4 * PART_STRIDE;
    const float s = Pp[idx] + Pp[idx + PART_STRIDE] + Pp[idx + 2 * PART_STRIDE] + Pp[idx + 3 * PART_STRIDE];
    const float* bias = (zi == 0) ? b0 : (zi == 1) ? b1 : b2;
    C[(size_t)zi * NBLK * D_MODEL + idx] = s + bias[idx & 1023];
}

__global__ void reduce_fp32_kernel(const float* __restrict__ P,
                                   const float* __restrict__ bias,
                                   float* __restrict__ C)
{
    const int idx = blockIdx.x * 256 + threadIdx.x;
    const float s = P[idx] + P[idx + PART_STRIDE] + P[idx + 2 * PART_STRIDE] + P[idx + 3 * PART_STRIDE];
    C[idx] = s + bias[idx & 1023];
}

__global__ void reduce_hl_kernel(const float* __restrict__ P,
                                 const float* __restrict__ bias,
                                 __half* __restrict__ H, __half* __restrict__ L)
{
    const int idx = blockIdx.x * 256 + threadIdx.x;
    const float v = P[idx] + P[idx + PART_STRIDE] + P[idx + 2 * PART_STRIDE] + P[idx + 3 * PART_STRIDE]
                  + bias[idx & 1023];
    const __half h = __float2half_rn(v);
    H[idx] = h;
    L[idx] = __float2half_rn(v - __half2float(h));
}

// =================== 1-term GEMM mainloop (big path): C ~= Ah * Bh ===================
#define BUF1_BYTES 32768
#define GEMM1_SMEM (2 * BUF1_BYTES)

#define ISSUE1(ic, buf) do {                                                  \
    const uint32_t sbase = sb + (buf) * BUF1_BYTES;                           \
    const size_t coff = (size_t)(ic) * 128 + cb;                              \
    _Pragma("unroll")                                                         \
    for (int i = 0; i < 4; i++) {                                             \
        const size_t go = (size_t)(rcp + i * 32) * 2048 + coff;               \
        cp16(sbase + dsw[i],          gAh + go);                              \
        cp16(sbase + 16384 + dsw[i],  gBh + go);                              \
    }                                                                         \
    cp_commit();                                                              \
} while (0)

#define GEMM1_BODY()                                                          \
    extern __shared__ char smem[];                                            \
    const uint32_t sb = smem_u32(smem);                                       \
    const int tid  = threadIdx.x;                                             \
    const int lane = tid & 31;                                                \
    const int wid  = tid >> 5;                                                \
    const int wm   = wid & 3;                                                 \
    const int wn   = wid >> 2;                                                \
    const int bn = blockIdx.x;                                                \
    const int bm = blockIdx.y;                                                \
    const int rcp = tid >> 3;                                                 \
    const int cb  = (tid & 7) << 4;                                           \
    uint32_t dsw[4];                                                          \
    _Pragma("unroll")                                                         \
    for (int i = 0; i < 4; i++) dsw[i] = SWZ128((uint32_t)((rcp + i * 32) * 128 + cb)); \
    FRAG_IDX();                                                               \
    float c[2][8][4];                                                         \
    _Pragma("unroll")                                                         \
    for (int mt = 0; mt < 2; mt++)                                            \
        _Pragma("unroll")                                                     \
        for (int nb = 0; nb < 8; nb++)                                        \
            _Pragma("unroll")                                                 \
            for (int j = 0; j < 4; j++) c[mt][nb][j] = 0.f;                   \
    ISSUE1(0, 0);                                                             \
    _Pragma("unroll 1")                                                       \
    for (int ic = 0; ic < 16; ic++) {                                         \
        const int cur = ic & 1;                                               \
        if (ic < 15) ISSUE1(ic + 1, cur ^ 1);                                 \
        if (ic < 15) asm volatile("cp.async.wait_group 1;" ::: "memory");     \
        else         asm volatile("cp.async.wait_group 0;" ::: "memory");     \
        __syncthreads();                                                      \
        const uint32_t base = sb + cur * BUF1_BYTES;                          \
        _Pragma("unroll")                                                     \
        for (int kk = 0; kk < 4; kk++) {                                      \
            const uint32_t kb = kk * 32;                                      \
            uint32_t ah[2][4];                                                \
            _Pragma("unroll")                                                 \
            for (int mt = 0; mt < 2; mt++) {                                  \
                const uint32_t off =                                          \
                    SWZ128((uint32_t)((wm * 32 + mt * 16 + arow_in) * 128 + kb + acolx)); \
                ldsm_x4(base + off, ah[mt]);                                  \
            }                                                                 \
            uint32_t bh[4][4];                                                \
            _Pragma("unroll")                                                 \
            for (int p = 0; p < 4; p++) {                                     \
                const uint32_t off =                                          \
                    SWZ128((uint32_t)((wn * 64 + p * 16 + brow_in) * 128 + kb + bcolx)); \
                ldsm_x4(base + 16384 + off, bh[p]);                           \
            }                                                                 \
            _Pragma("unroll")                                                 \
            for (int mt = 0; mt < 2; mt++) {                                  \
                _Pragma("unroll")                                             \
                for (int p = 0; p < 4; p++) {                                 \
                    mma_f16(c[mt][2 * p],     ah[mt], bh[p][0], bh[p][1]);    \
                    mma_f16(c[mt][2 * p + 1], ah[mt], bh[p][2], bh[p][3]);    \
                }                                                             \
            }                                                                 \
        }                                                                     \
        __syncthreads();                                                      \
    }

// ---- fused QKV: 1-term fp16, hi-only outputs ----
__global__ __launch_bounds__(256, 2) void gemm1_qkv_kernel(
    const __half* __restrict__ Ah, const __half* __restrict__ Bh,
    const float* __restrict__ bq, const float* __restrict__ bk, const float* __restrict__ bv,
    __half* __restrict__ QH, __half* __restrict__ KH, __half* __restrict__ VH)
{
    const char* gAh = (const char*)(Ah + (size_t)(blockIdx.y * 128) * 1024);
    const char* gBh = (const char*)(Bh + (size_t)(blockIdx.x * 128) * 1024);
    GEMM1_BODY();

    const int tensor = bn >> 3;
    const float* bias = (tensor == 0) ? bq : (tensor == 1) ? bk : bv;
    __half* OH = (tensor == 0) ? QH : (tensor == 1) ? KH : VH;

    const int row_base = bm * 128 + wm * 32 + (lane >> 2);
    const int col_base = (bn & 7) * 128 + wn * 64 + 2 * (lane & 3);
    #pragma unroll
    for (int mt = 0; mt < 2; mt++) {
        #pragma unroll
        for (int hh = 0; hh < 2; hh++) {
            const int row = row_base + mt * 16 + hh * 8;
            #pragma unroll
            for (int nb = 0; nb < 8; nb++) {
                const int col = col_base + nb * 8;
                const float v0 = c[mt][nb][hh * 2 + 0] + bias[col + 0];
                const float v1 = c[mt][nb][hh * 2 + 1] + bias[col + 1];
                *(__half2*)(OH + (size_t)row * 1024 + col) = __halves2half2(
                    __float2half_rn(v0), __float2half_rn(v1));
            }
        }
    }
}

// ---- o-proj: 1-term fp16, fp32 out + bias + summary add ----
__global__ __launch_bounds__(256, 2) void gemm1_oproj_kernel(
    const __half* __restrict__ Ah, const __half* __restrict__ Bh,
    const float* __restrict__ bias, const float* __restrict__ addBlk,
    float* __restrict__ C)
{
    const char* gAh = (const char*)(Ah + (size_t)(blockIdx.y * 128) * 1024);
    const char* gBh = (const char*)(Bh + (size_t)(blockIdx.x * 128) * 1024);
    GEMM1_BODY();

    const int row_base = bm * 128 + wm * 32 + (lane >> 2);
    const int col_base = bn * 128 + wn * 64 + 2 * (lane & 3);
    #pragma unroll
    for (int mt = 0; mt < 2; mt++) {
        #pragma unroll
        for (int hh = 0; hh < 2; hh++) {
            const int row = row_base + mt * 16 + hh * 8;
            const int rb = row >> 8;
            #pragma unroll
            for (int nb = 0; nb < 8; nb++) {
                const int col = col_base + nb * 8;
                float2 o;
                o.x = c[mt][nb][hh * 2 + 0] + bias[col + 0] + addBlk[(size_t)rb * 1024 + col + 0];
                o.y = c[mt][nb][hh * 2 + 1] + bias[col + 1] + addBlk[(size_t)rb * 1024 + col + 1];
                *(float2*)(C + (size_t)row * 1024 + col) = o;
            }
        }
    }
}

// =================== HMMA local attention (plain fp16, fp32 accum) ===================
// 256 threads, 8 warps x 16 query rows = 128 queries per CTA; grid.z = query half.
// No register spills: per-thread live state (~185 regs) fits the 255-reg budget.
#define ATT_SMEM (80 * 1024)

__global__ __launch_bounds__(256, 1) void attn_mma_kernel(
    const __half* __restrict__ QH, const __half* __restrict__ KH,
    const __half* __restrict__ VH,
    const float* __restrict__ bias,
    __half* __restrict__ CH)
{
    extern __shared__ char smem[];
    const uint32_t sb = smem_u32(smem);
    const int blk = blockIdx.x;
    const int h   = blockIdx.y;
    const int qh2 = blockIdx.z;          // query half 0/1
    const int tid = threadIdx.x;
    const int lane = tid & 31;
    const int w    = tid >> 5;           // 0..7

    const uint32_t QHs = sb;             // 128 rows x 128B = 16 KB
    const uint32_t KHs = sb + 16384;     // 256 rows x 128B = 32 KB
    const uint32_t VHs = sb + 49152;     // 256 rows x 128B = 32 KB

    {
        const char* qh0 = (const char*)(QH + ((size_t)(blk * 256 + qh2 * 128)) * 1024 + h * 64);
        const char* kh0 = (const char*)(KH + ((size_t)blk * 256) * 1024 + h * 64);
        const char* vh0 = (const char*)(VH + ((size_t)blk * 256) * 1024 + h * 64);
        #pragma unroll
        for (int i = 0; i < 4; i++) {            // Q: 1024 16B-chunks
            const int cidx = tid + i * 256;
            const int row = cidx >> 3;
            const int cbo = (cidx & 7) << 4;
            const uint32_t d = SWZ128((uint32_t)(row * 128 + cbo));
            cp16(QHs + d, qh0 + (size_t)row * 2048 + cbo);
        }
        #pragma unroll
        for (int i = 0; i < 8; i++) {            // K,V: 2048 chunks each
            const int cidx = tid + i * 256;
            const int row = cidx >> 3;
            const int cbo = (cidx & 7) << 4;
            const uint32_t d = SWZ128((uint32_t)(row * 128 + cbo));
            const size_t go = (size_t)row * 2048 + cbo;
            cp16(KHs + d, kh0 + go);
            cp16(VHs + d, vh0 + go);
        }
        cp_commit();
        asm volatile("cp.async.wait_group 0;" ::: "memory");
        __syncthreads();
    }

    const int arow = (lane & 7) + ((lane >> 3) & 1) * 8;
    const int acol = (lane >> 4) * 16;
    const int brow = (lane & 7) + ((lane >> 4) & 1) * 8;
    const int bcol = ((lane >> 3) & 1) * 16;

    float s[32][4];
    #pragma unroll
    for (int j = 0; j < 32; j++)
        #pragma unroll
        for (int q = 0; q < 4; q++) s[j][q] = 0.f;

    #pragma unroll
    for (int kk = 0; kk < 4; kk++) {
        const uint32_t kb = kk * 32;
        uint32_t qh[4];
        const uint32_t aoff = SWZ128((uint32_t)((w * 16 + arow) * 128 + kb + acol));
        ldsm_x4(QHs + aoff, qh);
        #pragma unroll
        for (int p = 0; p < 16; p++) {
            uint32_t bh[4];
            const uint32_t boff = SWZ128((uint32_t)((p * 16 + brow) * 128 + kb + bcol));
            ldsm_x4(KHs + boff, bh);
            mma_f16(s[2 * p],     qh, bh[0], bh[1]);
            mma_f16(s[2 * p + 1], qh, bh[2], bh[3]);
        }
    }

    const int r0 = w * 16 + (lane >> 2);                // row within half
    const int cq = (lane & 3) * 2;
    const float* br0 = bias + ((size_t)h * 256 + qh2 * 128 + r0) * 256;
    const float* br1 = br0 + 8 * 256;

    float m0 = -1e30f, m1 = -1e30f;
    #pragma unroll
    for (int j = 0; j < 32; j++) {
        const float2 b0 = *(const float2*)(br0 + j * 8 + cq);
        const float2 b1 = *(const float2*)(br1 + j * 8 + cq);
        s[j][0] = s[j][0] * 0.125f + b0.x;
        s[j][1] = s[j][1] * 0.125f + b0.y;
        s[j][2] = s[j][2] * 0.125f + b1.x;
        s[j][3] = s[j][3] * 0.125f + b1.y;
        m0 = fmaxf(m0, fmaxf(s[j][0], s[j][1]));
        m1 = fmaxf(m1, fmaxf(s[j][2], s[j][3]));
    }
    #pragma unroll
    for (int msk = 1; msk <= 2; msk <<= 1) {
        m0 = fmaxf(m0, __shfl_xor_sync(0xffffffffu, m0, msk));
        m1 = fmaxf(m1, __shfl_xor_sync(0xffffffffu, m1, msk));
    }
    float l0 = 0.f, l1 = 0.f;
    #pragma unroll
    for (int j = 0; j < 32; j++) {
        s[j][0] = __expf(s[j][0] - m0);
        s[j][1] = __expf(s[j][1] - m0);
        s[j][2] = __expf(s[j][2] - m1);
        s[j][3] = __expf(s[j][3] - m1);
        l0 += s[j][0] + s[j][1];
        l1 += s[j][2] + s[j][3];
    }
    #pragma unroll
    for (int msk = 1; msk <= 2; msk <<= 1) {
        l0 += __shfl_xor_sync(0xffffffffu, l0, msk);
        l1 += __shfl_xor_sync(0xffffffffu, l1, msk);
    }

    float o[8][4];
    #pragma unroll
    for (int j = 0; j < 8; j++)
        #pragma unroll
        for (int q = 0; q < 4; q++) o[j][q] = 0.f;

    // Phase 2: B-frag via ldmatrix.trans from V[tok][dim].
    #pragma unroll
    for (int kt = 0; kt < 16; kt++) {
        uint32_t pah[4];
        #pragma unroll
        for (int half_ = 0; half_ < 2; half_++) {
            const float* sv = s[2 * kt + half_];
            pah[2 * half_ + 0] = pack_f16x2(sv[0], sv[1]);
            pah[2 * half_ + 1] = pack_f16x2(sv[2], sv[3]);
        }
        #pragma unroll
        for (int nd = 0; nd < 4; nd++) {
            uint32_t bh[4];
            const uint32_t boff =
                SWZ128((uint32_t)((kt * 16 + arow) * 128 + nd * 32 + acol));
            ldsm_x4_t(VHs + boff, bh);
            mma_f16(o[2 * nd],     pah, bh[0], bh[1]);
            mma_f16(o[2 * nd + 1], pah, bh[2], bh[3]);
        }
    }

    const float inv0 = 1.f / l0;
    const float inv1 = 1.f / l1;
    const size_t row0 = (size_t)blk * 256 + qh2 * 128 + r0;
    #pragma unroll
    for (int j = 0; j < 8; j++) {
        const int col = h * 64 + j * 8 + cq;
        *(__half2*)(CH + row0 * 1024 + col) = __halves2half2(
            __float2half_rn(o[j][0] * inv0), __float2half_rn(o[j][1] * inv0));
        *(__half2*)(CH + (row0 + 8) * 1024 + col) = __halves2half2(
            __float2half_rn(o[j][2] * inv1), __float2half_rn(o[j][3] * inv1));
    }
}

// =================== mean pool -> split fp16 directly ===================
__global__ void meanpool_hl_kernel(const float* __restrict__ x,
                                   __half* __restrict__ H, __half* __restrict__ L)
{
    const int blk = blockIdx.x;
    const int c   = blockIdx.y * 256 + threadIdx.x;
    const float* base = x + (size_t)blk * BSZ * D_MODEL + c;
    float s = 0.f;
    #pragma unroll 4
    for (int r = 0; r < BSZ; r++) s += base[(size_t)r * D_MODEL];
    const float v = s * (1.0f / BSZ);
    const __half h = __float2half_rn(v);
    H[blk * D_MODEL + c] = h;
    L[blk * D_MODEL + c] = __float2half_rn(v - __half2float(h));
}

// =================== summary attention (fp32 in, split fp16 out) ===================
__global__ void summ_attn_kernel(
    const float* __restrict__ QKV2,
    __half* __restrict__ SCH, __half* __restrict__ SCL)
{
    const float* Q2 = QKV2;
    const float* K2 = QKV2 + (size_t)NBLK * D_MODEL;
    const float* V2 = QKV2 + (size_t)2 * NBLK * D_MODEL;
    const int b = blockIdx.x;
    const int h = blockIdx.y;
    const int l = threadIdx.x;

    const float* qr = Q2 + (size_t)(b * 16 + l) * D_MODEL + h * DHEAD;
    float q[DHEAD];
    #pragma unroll
    for (int d = 0; d < DHEAD; d += 4) {
        const float4 v = *(const float4*)(qr + d);
        q[d] = v.x; q[d + 1] = v.y; q[d + 2] = v.z; q[d + 3] = v.w;
    }

    float s[16];
    float m = -1e30f;
    for (int j = 0; j < 16; j++) {
        const float* kr = K2 + (size_t)(b * 16 + j) * D_MODEL + h * DHEAD;
        float a = 0.f;
        #pragma unroll
        for (int d = 0; d < DHEAD; d += 4) {
            const float4 v = *(const float4*)(kr + d);
            a += q[d] * v.x + q[d + 1] * v.y + q[d + 2] * v.z + q[d + 3] * v.w;
        }
        s[j] = a * 0.125f;
        m = fmaxf(m, s[j]);
    }
    float lsum = 0.f;
    for (int j = 0; j < 16; j++) { s[j] = __expf(s[j] - m); lsum += s[j]; }
    const float inv = 1.f / lsum;

    float o[DHEAD];
    #pragma unroll
    for (int d = 0; d < DHEAD; d++) o[d] = 0.f;
    for (int j = 0; j < 16; j++) {
        const float* vr = V2 + (size_t)(b * 16 + j) * D_MODEL + h * DHEAD;
        const float p = s[j] * inv;
        #pragma unroll
        for (int d = 0; d < DHEAD; d += 4) {
            const float4 v = *(const float4*)(vr + d);
            o[d] += p * v.x; o[d + 1] += p * v.y; o[d + 2] += p * v.z; o[d + 3] += p * v.w;
        }
    }
    const size_t ob = (size_t)(b * 16 + l) * D_MODEL + h * DHEAD;
    #pragma unroll
    for (int d = 0; d < DHEAD; d += 2) {
        const __half h0 = __float2half_rn(o[d]);
        const __half h1 = __float2half_rn(o[d + 1]);
        *(__half2*)(SCH + ob + d) = __halves2half2(h0, h1);
        *(__half2*)(SCL + ob + d) = __halves2half2(
            __float2half_rn(o[d] - __half2float(h0)),
            __float2half_rn(o[d + 1] - __half2float(h1)));
    }
}

// =================== launch ===================
extern "C" void kernel_launch(void* const* d_in, const int* in_sizes, int n_in,
                              void* d_out, int out_size)
{
    const float* x     = (const float*)d_in[0];
    const float* lq_w  = (const float*)d_in[1];
    const float* lq_b  = (const float*)d_in[2];
    const float* lk_w  = (const float*)d_in[3];
    const float* lk_b  = (const float*)d_in[4];
    const float* lv_w  = (const float*)d_in[5];
    const float* lv_b  = (const float*)d_in[6];
    const float* lo_w  = (const float*)d_in[7];
    const float* lo_b  = (const float*)d_in[8];
    const float* pbias = (const float*)d_in[9];
    const float* sq_w  = (const float*)d_in[10];
    const float* sq_b  = (const float*)d_in[11];
    const float* sk_w  = (const float*)d_in[12];
    const float* sk_b  = (const float*)d_in[13];
    const float* sv_w  = (const float*)d_in[14];
    const float* sv_b  = (const float*)d_in[15];
    const float* so_w  = (const float*)d_in[16];
    const float* so_b  = (const float*)d_in[17];
    const float* sum_w = (const float*)d_in[18];
    const float* sum_b = (const float*)d_in[19];
    float* out = (float*)d_out;

    float *QKV2, *SOUT, *PART;
    cudaGetSymbolAddress((void**)&QKV2, g_QKV2);
    cudaGetSymbolAddress((void**)&SOUT, g_SOUT);
    cudaGetSymbolAddress((void**)&PART, g_PART);

    __half *XH, *QH, *KH, *VH, *CH, *WH, *WL;
    __half *S1H, *S1L, *S2H, *S2L, *S3H, *S3L;
    cudaGetSymbolAddress((void**)&XH, g_XH);
    cudaGetSymbolAddress((void**)&QH, g_QH);
    cudaGetSymbolAddress((void**)&KH, g_KH);
    cudaGetSymbolAddress((void**)&VH, g_VH);
    cudaGetSymbolAddress((void**)&CH, g_CH);
    cudaGetSymbolAddress((void**)&WH, g_WH);
    cudaGetSymbolAddress((void**)&WL, g_WL);
    cudaGetSymbolAddress((void**)&S1H, g_S1H);
    cudaGetSymbolAddress((void**)&S1L, g_S1L);
    cudaGetSymbolAddress((void**)&S2H, g_S2H);
    cudaGetSymbolAddress((void**)&S2L, g_S2L);
    cudaGetSymbolAddress((void**)&S3H, g_S3H);
    cudaGetSymbolAddress((void**)&S3L, g_S3L);

    WP9 wp;
    const float* ws[9] = {lq_w, lk_w, lv_w, lo_w, sum_w, sq_w, sk_w, sv_w, so_w};
    for (int i = 0; i < 9; i++) {
        wp.w[i] = ws[i];
        wp.h[i] = WH + (size_t)i * WSTRIDE;
        wp.l[i] = WL + (size_t)i * WSTRIDE;
    }

    cudaFuncSetAttribute(gemm_smallk_kernel,
                         cudaFuncAttributeMaxDynamicSharedMemorySize, GEMM3_SMEM);
    cudaFuncSetAttribute(gemm1_qkv_kernel,
                         cudaFuncAttributeMaxDynamicSharedMemorySize, GEMM1_SMEM);
    cudaFuncSetAttribute(gemm1_oproj_kernel,
                         cudaFuncAttributeMaxDynamicSharedMemorySize, GEMM1_SMEM);
    cudaFuncSetAttribute(attn_mma_kernel,
                         cudaFuncAttributeMaxDynamicSharedMemorySize, ATT_SMEM);

    static cudaStream_t s2 = nullptr, s3 = nullptr;
    static cudaEvent_t evFork = nullptr, evJoin = nullptr, evAct = nullptr, evW3 = nullptr;
    if (s2 == nullptr) {
        cudaStreamCreateWithFlags(&s2, cudaStreamNonBlocking);
        cudaStreamCreateWithFlags(&s3, cudaStreamNonBlocking);
        cudaEventCreateWithFlags(&evFork, cudaEventDisableTiming);
        cudaEventCreateWithFlags(&evJoin, cudaEventDisableTiming);
        cudaEventCreateWithFlags(&evAct,  cudaEventDisableTiming);
        cudaEventCreateWithFlags(&evW3,   cudaEventDisableTiming);
    }

    // fork: s2 = small summary path (+ its weights), s3 = act conversion + weight 3
    cudaEventRecord(evFork, 0);
    cudaStreamWaitEvent(s2, evFork, 0);
    cudaStreamWaitEvent(s3, evFork, 0);

    // ---- s3: activation fp32->fp16, then o-proj weight (z=3) ----
    prep_act_h_kernel<<<16384, 256, 0, s3>>>((const float4*)x, XH, 4194304);
    cudaEventRecord(evAct, s3);
    prep_w_kernel<<<dim3(32, 32, 1), dim3(32, 8), 0, s3>>>(wp, 3);
    cudaEventRecord(evW3, s3);

    // ---- s2: weight prep (z=4..8, hi+lo) + small summary path ----
    prep_w_kernel<<<dim3(32, 32, 5), dim3(32, 8), 0, s2>>>(wp, 4);
    meanpool_hl_kernel<<<dim3(NBLK, 4), 256, 0, s2>>>(x, S1H, S1L);
    gemm_smallk_kernel<<<dim3(8, 1, 4), 256, GEMM3_SMEM, s2>>>(S1H, S1L, WH, WL, 4, PART);
    reduce_hl_kernel<<<512, 256, 0, s2>>>(PART, sum_b, S2H, S2L);
    gemm_smallk_kernel<<<dim3(8, 3, 4), 256, GEMM3_SMEM, s2>>>(S2H, S2L, WH, WL, 5, PART);
    reduce3_fp32_kernel<<<dim3(256, 3), 256, 0, s2>>>(PART, sq_b, sk_b, sv_b, QKV2);
    summ_attn_kernel<<<dim3(4, NHEAD), 16, 0, s2>>>(QKV2, S3H, S3L);
    gemm_smallk_kernel<<<dim3(8, 1, 4), 256, GEMM3_SMEM, s2>>>(S3H, S3L, WH, WL, 8, PART);
    reduce_fp32_kernel<<<256, 256, 0, s2>>>(PART, so_b, SOUT);
    cudaEventRecord(evJoin, s2);

    // ---- main stream: big local path (weights 0..2 hi; QKV waits on XH) ----
    prep_w_kernel<<<dim3(32, 32, 3), dim3(32, 8)>>>(wp, 0);
    cudaStreamWaitEvent(0, evAct, 0);
    gemm1_qkv_kernel<<<dim3(24, NTOK / 128), 256, GEMM1_SMEM>>>(
        XH, wp.h[0], lq_b, lk_b, lv_b, QH, KH, VH);
    attn_mma_kernel<<<dim3(NBLK, NHEAD, 2), 256, ATT_SMEM>>>(
        QH, KH, VH, pbias, CH);

    cudaStreamWaitEvent(0, evJoin, 0);
    cudaStreamWaitEvent(0, evW3, 0);
    gemm1_oproj_kernel<<<dim3(8, NTOK / 128), 256, GEMM1_SMEM>>>(
        CH, wp.h[3], lo_b, SOUT, out);
}